// round 1
// baseline (speedup 1.0000x reference)
#include <cuda_runtime.h>
#include <cuda_bf16.h>
#include <math.h>

// ---------------- problem constants ----------------
#define BB 4
#define HI 56
#define WI 56
#define DD 256
#define HO 28
#define WO 28
#define NPOS 784           // HO*WO
#define NTOK (BB*NPOS)     // 3136
#define NTOKIN (BB*HI*WI)  // 12544
#define HEADS 8
#define HDIM 32
#define KG 3
#define KB 7
#define LN_EPS 1e-5f

// ---------------- scratch (device globals; no allocations allowed) ----------------
__device__ float g_lnx   [NTOKIN*DD];      // LN_in(x)
__device__ float g_tmp0  [NTOKIN*DD];      // gemm staging
__device__ float g_kg    [BB*4*NPOS*DD];   // grouped k
__device__ float g_vg    [BB*4*NPOS*DD];   // grouped v
__device__ float g_colim [NTOK*2304];      // im2col for seed conv
__device__ float g_wseed [DD*2304];        // transposed seed weight
__device__ float g_xout  [NTOK*DD];
__device__ float g_buf1  [NTOK*768];
__device__ float g_buf2  [NTOK*768];
__device__ float g_attn  [BB*4*NPOS*9];
__device__ float g_colsum[BB*NPOS];
__device__ float g_cos   [NPOS*16];
__device__ float g_sin   [NPOS*16];

// ---------------- LN over 256 (optionally + residual) ----------------
__global__ void ln256(const float* __restrict__ in, const float* __restrict__ gamma,
                      const float* __restrict__ beta, const float* __restrict__ res,
                      float* __restrict__ out) {
    int row = blockIdx.x, t = threadIdx.x;
    float x = in[row*DD + t];
    __shared__ float sm[8];
    float v = x;
    #pragma unroll
    for (int o=16;o;o>>=1) v += __shfl_xor_sync(0xffffffffu, v, o);
    if ((t&31)==0) sm[t>>5] = v;
    __syncthreads();
    float tot = 0.f;
    #pragma unroll
    for (int u=0;u<8;u++) tot += sm[u];
    float mean = tot * (1.f/256.f);
    __syncthreads();
    float d = x - mean;
    v = d*d;
    #pragma unroll
    for (int o=16;o;o>>=1) v += __shfl_xor_sync(0xffffffffu, v, o);
    if ((t&31)==0) sm[t>>5] = v;
    __syncthreads();
    tot = 0.f;
    #pragma unroll
    for (int u=0;u<8;u++) tot += sm[u];
    float var = tot * (1.f/256.f);
    float y = d * rsqrtf(var + LN_EPS) * gamma[t] + beta[t];
    if (res) y += res[row*DD + t];
    out[row*DD + t] = y;
}

// ---------------- generic SGEMM: C[M,N] = A[M,K] @ W[N,K]^T (+bias)(gelu)(+res) ----------------
// Requires M%64==0, N%64==0, K%16==0 (true for all calls here).
__device__ __forceinline__ float gelu_exact(float x) {
    return 0.5f * x * (1.f + erff(x * 0.70710678118654752f));
}

__global__ __launch_bounds__(256)
void gemm_nt(const float* __restrict__ A, const float* __restrict__ W,
             const float* __restrict__ bias, const float* __restrict__ res,
             float* __restrict__ C, int M, int N, int K, int act) {
    __shared__ float As[64][17];
    __shared__ float Ws[64][17];
    int tid = threadIdx.x;
    int tx = tid & 15, ty = tid >> 4;
    int bm = blockIdx.y * 64, bn = blockIdx.x * 64;
    float acc[4][4] = {};
    int lr = tid >> 2;
    int lc = (tid & 3) * 4;
    const float* Aptr = A + (size_t)(bm + lr) * K + lc;
    const float* Wptr = W + (size_t)(bn + lr) * K + lc;
    for (int k0 = 0; k0 < K; k0 += 16) {
        float4 a4 = *(const float4*)(Aptr + k0);
        float4 w4 = *(const float4*)(Wptr + k0);
        As[lr][lc+0]=a4.x; As[lr][lc+1]=a4.y; As[lr][lc+2]=a4.z; As[lr][lc+3]=a4.w;
        Ws[lr][lc+0]=w4.x; Ws[lr][lc+1]=w4.y; Ws[lr][lc+2]=w4.z; Ws[lr][lc+3]=w4.w;
        __syncthreads();
        #pragma unroll
        for (int kk=0;kk<16;kk++) {
            float ar[4], wr[4];
            #pragma unroll
            for (int i=0;i<4;i++) ar[i] = As[ty*4+i][kk];
            #pragma unroll
            for (int j=0;j<4;j++) wr[j] = Ws[tx*4+j][kk];
            #pragma unroll
            for (int i=0;i<4;i++)
                #pragma unroll
                for (int j=0;j<4;j++)
                    acc[i][j] = fmaf(ar[i], wr[j], acc[i][j]);
        }
        __syncthreads();
    }
    #pragma unroll
    for (int i=0;i<4;i++) {
        int r = bm + ty*4 + i;
        #pragma unroll
        for (int j=0;j<4;j++) {
            int c = bn + tx*4 + j;
            float v = acc[i][j];
            if (bias) v += bias[c];
            if (act)  v = gelu_exact(v);
            if (res)  v += res[(size_t)r*N + c];
            C[(size_t)r*N + c] = v;
        }
    }
}

// ---------------- permute (B,56,56,D) -> (B,4,28,28,D), group = dh*2+dw ----------------
__global__ void to_groups_k(const float* __restrict__ in, float* __restrict__ out) {
    int idx = blockIdx.x*blockDim.x + threadIdx.x;
    if (idx >= BB*4*NPOS*DD) return;
    int d = idx & 255; int r = idx >> 8;
    int p = r % NPOS; int bg = r / NPOS; int g = bg & 3; int b = bg >> 2;
    int i = p / WO, j = p % WO;
    int dh = g >> 1, dw = g & 1;
    int srow = b*(HI*WI) + (2*i+dh)*WI + (2*j+dw);
    out[idx] = in[(size_t)srow*DD + d];
}

// ---------------- im2col for seed conv (3x3 stride2 pad1) ----------------
__global__ void im2col_k(const float* __restrict__ x, float* __restrict__ out) {
    int idx = blockIdx.x*blockDim.x + threadIdx.x;
    const int total = NTOK*2304;
    if (idx >= total) return;
    int col = idx % 2304; int row = idx / 2304;
    int b = row / NPOS; int p = row % NPOS;
    int i = p / WO, j = p % WO;
    int kk = col >> 8; int ic = col & 255;
    int kh = kk / 3, kw = kk % 3;
    int hi = 2*i - 1 + kh, wi = 2*j - 1 + kw;
    float v = 0.f;
    if (hi >= 0 && hi < HI && wi >= 0 && wi < WI)
        v = x[((size_t)(b*(HI*WI) + hi*WI + wi))*DD + ic];
    out[idx] = v;
}

// w (oc,ic,kh,kw) -> w2[oc][kk*256+ic]
__global__ void wseed_tr(const float* __restrict__ w, float* __restrict__ w2) {
    int idx = blockIdx.x*blockDim.x + threadIdx.x;
    if (idx >= DD*2304) return;
    int oc = idx / 2304; int c = idx % 2304;
    int kk = c >> 8; int ic = c & 255;
    w2[idx] = w[(size_t)oc*2304 + ic*9 + kk];
}

// ---------------- group NA (K=3) logits + softmax ----------------
__global__ void na3_attn(const float* __restrict__ kg, const float* __restrict__ q,
                         const float* __restrict__ rpb, const float* __restrict__ tau,
                         float* __restrict__ attn) {
    int blk = blockIdx.x;                   // (b*4+n)*784 + p
    int p = blk % NPOS; int bn = blk / NPOS; int n = bn & 3; int b = bn >> 2;
    int i = p / WO, j = p % WO;
    int t = threadIdx.x; int w = t >> 5; int lane = t & 31;   // 9 warps
    __shared__ float logit[9];
    __shared__ float ev[9];
    int a = w / 3, c = w % 3;
    int si = min(max(i-1,0),25), sj = min(max(j-1,0),25);
    int np = (si+a)*WO + (sj+c);
    const float* kv = kg + (size_t)blk*DD;
    const float* qv = q + (size_t)(b*NPOS + np)*DD;
    float s = 0.f;
    #pragma unroll
    for (int u=0;u<8;u++) s = fmaf(kv[lane + 32*u], qv[lane + 32*u], s);
    #pragma unroll
    for (int o=16;o;o>>=1) s += __shfl_xor_sync(0xffffffffu, s, o);
    if (lane==0) logit[w] = s + rpb[n*9 + w];
    __syncthreads();
    if (t < 9) {
        float scale = expf(tau[0]);
        float m = -1e30f;
        #pragma unroll
        for (int u=0;u<9;u++) m = fmaxf(m, logit[u]*scale);
        ev[t] = expf(logit[t]*scale - m);
    }
    __syncthreads();
    if (t < 9) {
        float sum = 0.f;
        #pragma unroll
        for (int u=0;u<9;u++) sum += ev[u];
        attn[(size_t)blk*9 + t] = ev[t]/sum + 1e-6f;
    }
}

// ---------------- deterministic column scatter-sum ----------------
__device__ __forceinline__ int inv_list(int s, int* lst) {
    if (s == 0)       { lst[0]=0;  lst[1]=1;  return 2; }
    else if (s == 25) { lst[0]=26; lst[1]=27; return 2; }
    else              { lst[0]=s+1;           return 1; }
}

__global__ void col_sum_k(const float* __restrict__ attn, float* __restrict__ col) {
    int idx = blockIdx.x*blockDim.x + threadIdx.x;
    if (idx >= BB*NPOS) return;
    int t = idx % NPOS, b = idx / NPOS;
    int ti = t / WO, tj = t % WO;
    float acc = 0.f;
    for (int a=0;a<3;a++) {
        int sr = ti - a; if (sr < 0 || sr > 25) continue;
        int il[2]; int ic = inv_list(sr, il);
        for (int c=0;c<3;c++) {
            int sc = tj - c; if (sc < 0 || sc > 25) continue;
            int jl[2]; int jc = inv_list(sc, jl);
            for (int ii=0; ii<ic; ii++)
                for (int jj=0; jj<jc; jj++) {
                    int pp = il[ii]*WO + jl[jj];
                    #pragma unroll
                    for (int n=0;n<4;n++)
                        acc += attn[((size_t)(b*4+n)*NPOS + pp)*9 + a*3 + c];
                }
        }
    }
    col[idx] = acc;
}

// ---------------- group NA AV + in-place residual ----------------
__global__ void na3_av(const float* __restrict__ attn, const float* __restrict__ col,
                       const float* __restrict__ vg, float* __restrict__ xout) {
    int blk = blockIdx.x;                 // b*784 + p
    int p = blk % NPOS, b = blk / NPOS;
    int i = p / WO, j = p % WO;
    int t = threadIdx.x;
    __shared__ float wgt[4][9];
    __shared__ int npos[9];
    if (t < 9) {
        int a = t/3, c = t%3;
        int ni = min(max(i-1,0),25)+a, nj = min(max(j-1,0),25)+c;
        npos[t] = ni*WO + nj;
    }
    __syncthreads();
    if (t < 36) {
        int n = t/9, ac = t%9;
        float av = attn[((size_t)(b*4+n)*NPOS + p)*9 + ac];
        wgt[n][ac] = av / (col[b*NPOS + npos[ac]] + 1e-8f);
    }
    __syncthreads();
    float acc = xout[(size_t)blk*DD + t];
    #pragma unroll
    for (int n=0;n<4;n++) {
        const float* vb = vg + (size_t)(b*4+n)*NPOS*DD;
        #pragma unroll
        for (int ac=0;ac<9;ac++)
            acc = fmaf(wgt[n][ac], vb[(size_t)npos[ac]*DD + t], acc);
    }
    xout[(size_t)blk*DD + t] = acc;
}

// ---------------- RoPE table + apply ----------------
__global__ void rope_tab(float* __restrict__ cs, float* __restrict__ sn) {
    int idx = blockIdx.x*blockDim.x + threadIdx.x;
    if (idx >= NPOS*16) return;
    int pos = idx / 16, r = idx % 16;
    float f = expf(-((float)(2*r) / 32.f) * 9.210340371976184f); // ln(10000)
    float ang = (float)pos * f;
    cs[idx] = cosf(ang);
    sn[idx] = sinf(ang);
}

__global__ void rope_apply(float* __restrict__ qkv, const float* __restrict__ cs,
                           const float* __restrict__ sn) {
    int idx = blockIdx.x*blockDim.x + threadIdx.x;
    const int total = BB*NPOS*2*HEADS*16;
    if (idx >= total) return;
    int r = idx % 16; int rest = idx / 16;
    int h = rest % HEADS; rest /= HEADS;
    int part = rest % 2; rest /= 2;
    int pos = rest % NPOS; int b = rest / NPOS;
    size_t base = ((size_t)(b*NPOS + pos))*768 + part*256 + h*32 + 2*r;
    float c = cs[pos*16 + r], s = sn[pos*16 + r];
    float x0 = qkv[base], x1 = qkv[base+1];
    qkv[base]   = x0*c - x1*s;
    qkv[base+1] = x1*c + x0*s;
}

// ---------------- block NA (K=7, HD=32) full attention ----------------
__global__ void na7_k(const float* __restrict__ qkv, float* __restrict__ obuf) {
    int blk = blockIdx.x;                 // (b*8+h)*784 + p
    int p = blk % NPOS; int bh = blk / NPOS; int h = bh & 7; int b = bh >> 3;
    int i = p / WO, j = p % WO;
    int t = threadIdx.x; int w = t >> 5; int lane = t & 31;   // 8 warps
    __shared__ float qs[32];
    __shared__ float logit[49];
    __shared__ float prob[49];
    __shared__ int   kpos[49];
    __shared__ float part[8][32];
    __shared__ float red[2];
    size_t rowbase = (size_t)(b*NPOS + p)*768;
    if (t < 32) qs[t] = qkv[rowbase + h*32 + t];
    int si = min(max(i-3,0),21), sj = min(max(j-3,0),21);
    __syncthreads();
    for (int nb = w; nb < 49; nb += 8) {
        int a = nb / 7, c = nb % 7;
        int kp = (si+a)*WO + (sj+c);
        const float* kptr = qkv + (size_t)(b*NPOS + kp)*768 + 256 + h*32;
        float s = qs[lane] * kptr[lane];
        #pragma unroll
        for (int o=16;o;o>>=1) s += __shfl_xor_sync(0xffffffffu, s, o);
        if (lane==0) { logit[nb] = s * 0.17677669529663687f; kpos[nb] = kp; }
    }
    __syncthreads();
    if (t == 0) {
        float m = -1e30f;
        #pragma unroll
        for (int u=0;u<49;u++) m = fmaxf(m, logit[u]);
        red[0] = m;
    }
    __syncthreads();
    if (t < 49) prob[t] = expf(logit[t] - red[0]);
    __syncthreads();
    if (t == 0) {
        float s = 0.f;
        #pragma unroll
        for (int u=0;u<49;u++) s += prob[u];
        red[1] = s;
    }
    __syncthreads();
    float inv = 1.f / red[1];
    float acc = 0.f;
    for (int nb = w; nb < 49; nb += 8) {
        const float* vptr = qkv + (size_t)(b*NPOS + kpos[nb])*768 + 512 + h*32;
        acc = fmaf(prob[nb]*inv, vptr[lane], acc);
    }
    part[w][lane] = acc;
    __syncthreads();
    if (w == 0) {
        float s = 0.f;
        #pragma unroll
        for (int u=0;u<8;u++) s += part[u][lane];
        obuf[(size_t)(b*NPOS + p)*DD + h*32 + lane] = s;
    }
}

// ---------------- launch helpers ----------------
static inline void run_gemm(const float* A, const float* W, const float* bias,
                            const float* res, float* C, int M, int N, int K, int act) {
    dim3 grid(N/64, M/64);
    gemm_nt<<<grid, 256>>>(A, W, bias, res, C, M, N, K, act);
}

extern "C" void kernel_launch(void* const* d_in, const int* in_sizes, int n_in,
                              void* d_out, int out_size) {
    const float* x          = (const float*)d_in[0];
    const float* g_seed_w   = (const float*)d_in[1];
    const float* g_q_w      = (const float*)d_in[2];
    const float* g_k_w      = (const float*)d_in[3];
    const float* g_v_w      = (const float*)d_in[4];
    const float* g_mlp_w1   = (const float*)d_in[5];
    const float* g_mlp_b1   = (const float*)d_in[6];
    const float* g_mlp_w2   = (const float*)d_in[7];
    const float* g_mlp_b2   = (const float*)d_in[8];
    const float* g_ln_in_g  = (const float*)d_in[9];
    const float* g_ln_in_b  = (const float*)d_in[10];
    const float* g_ln_out_g = (const float*)d_in[11];
    const float* g_ln_out_b = (const float*)d_in[12];
    const float* g_tau      = (const float*)d_in[13];
    const float* g_rpb      = (const float*)d_in[14];
    const float* blk_ln1_g  = (const float*)d_in[15];
    const float* blk_ln1_b  = (const float*)d_in[16];
    const float* blk_qkv_w  = (const float*)d_in[17];
    const float* blk_proj_w = (const float*)d_in[18];
    const float* blk_proj_b = (const float*)d_in[19];
    const float* blk_ln2_g  = (const float*)d_in[20];
    const float* blk_ln2_b  = (const float*)d_in[21];
    const float* blk_mlp_w1 = (const float*)d_in[22];
    const float* blk_mlp_b1 = (const float*)d_in[23];
    const float* blk_mlp_w2 = (const float*)d_in[24];
    const float* blk_mlp_b2 = (const float*)d_in[25];
    float* out = (float*)d_out;

    float *lnx, *tmp0, *kg, *vg, *colim, *wseed, *xout, *buf1, *buf2, *attn, *colsum, *csb, *snb;
    cudaGetSymbolAddress((void**)&lnx,   g_lnx);
    cudaGetSymbolAddress((void**)&tmp0,  g_tmp0);
    cudaGetSymbolAddress((void**)&kg,    g_kg);
    cudaGetSymbolAddress((void**)&vg,    g_vg);
    cudaGetSymbolAddress((void**)&colim, g_colim);
    cudaGetSymbolAddress((void**)&wseed, g_wseed);
    cudaGetSymbolAddress((void**)&xout,  g_xout);
    cudaGetSymbolAddress((void**)&buf1,  g_buf1);
    cudaGetSymbolAddress((void**)&buf2,  g_buf2);
    cudaGetSymbolAddress((void**)&attn,  g_attn);
    cudaGetSymbolAddress((void**)&colsum,g_colsum);
    cudaGetSymbolAddress((void**)&csb,   g_cos);
    cudaGetSymbolAddress((void**)&snb,   g_sin);

    // ---- k, v group projections ----
    ln256<<<NTOKIN, 256>>>(x, g_ln_in_g, g_ln_in_b, nullptr, lnx);
    run_gemm(lnx, g_k_w, nullptr, nullptr, tmp0, NTOKIN, DD, DD, 0);
    to_groups_k<<<(BB*4*NPOS*DD + 255)/256, 256>>>(tmp0, kg);
    run_gemm(x, g_v_w, nullptr, nullptr, tmp0, NTOKIN, DD, DD, 0);
    to_groups_k<<<(BB*4*NPOS*DD + 255)/256, 256>>>(tmp0, vg);

    // ---- seed conv via im2col + GEMM ----
    wseed_tr<<<(DD*2304 + 255)/256, 256>>>(g_seed_w, wseed);
    im2col_k<<<(NTOK*2304 + 255)/256, 256>>>(x, colim);
    run_gemm(colim, wseed, nullptr, nullptr, tmp0, NTOK, DD, 2304, 0);
    ln256<<<NTOK, 256>>>(tmp0, g_ln_out_g, g_ln_out_b, nullptr, xout);

    // ---- RoPE tables (needed later) ----
    rope_tab<<<(NPOS*16 + 255)/256, 256>>>(csb, snb);

    // ---- 3 grouped-NA seeding iterations ----
    for (int it = 0; it < 3; it++) {
        ln256<<<NTOK, 256>>>(xout, g_ln_out_g, g_ln_out_b, nullptr, buf1);
        run_gemm(buf1, g_q_w, nullptr, nullptr, buf2, NTOK, DD, DD, 0);
        na3_attn<<<BB*4*NPOS, 288>>>(kg, buf2, g_rpb, g_tau, attn);
        col_sum_k<<<(BB*NPOS + 255)/256, 256>>>(attn, colsum);
        na3_av<<<NTOK, 256>>>(attn, colsum, vg, xout);
        run_gemm(xout, g_mlp_w1, g_mlp_b1, nullptr, buf1, NTOK, 512, DD, 1);
        run_gemm(buf1, g_mlp_w2, g_mlp_b2, nullptr, buf2, NTOK, DD, 512, 0);
        ln256<<<NTOK, 256>>>(buf2, g_ln_out_g, g_ln_out_b, xout, xout);
    }

    // ---- 2 transformer blocks with 7x7 NA ----
    for (int l = 0; l < 2; l++) {
        const float* ln1g = blk_ln1_g + l*DD;
        const float* ln1b = blk_ln1_b + l*DD;
        const float* qkvw = blk_qkv_w + (size_t)l*768*DD;
        const float* pjw  = blk_proj_w + (size_t)l*DD*DD;
        const float* pjb  = blk_proj_b + l*DD;
        const float* ln2g = blk_ln2_g + l*DD;
        const float* ln2b = blk_ln2_b + l*DD;
        const float* mw1  = blk_mlp_w1 + (size_t)l*768*DD;
        const float* mb1  = blk_mlp_b1 + l*768;
        const float* mw2  = blk_mlp_w2 + (size_t)l*DD*768;
        const float* mb2  = blk_mlp_b2 + l*DD;

        ln256<<<NTOK, 256>>>(xout, ln1g, ln1b, nullptr, buf1);
        run_gemm(buf1, qkvw, nullptr, nullptr, buf2, NTOK, 768, DD, 0);
        rope_apply<<<(BB*NPOS*2*HEADS*16 + 255)/256, 256>>>(buf2, csb, snb);
        na7_k<<<BB*HEADS*NPOS, 256>>>(buf2, buf1);
        run_gemm(buf1, pjw, pjb, xout, xout, NTOK, DD, DD, 0);
        ln256<<<NTOK, 256>>>(xout, ln2g, ln2b, nullptr, buf1);
        run_gemm(buf1, mw1, mb1, nullptr, buf2, NTOK, 768, DD, 1);
        run_gemm(buf2, mw2, mb2, xout, (l == 1) ? out : xout, NTOK, DD, 768, 0);
    }
}

// round 2
// speedup vs baseline: 1.1587x; 1.1587x over previous
#include <cuda_runtime.h>
#include <cuda_bf16.h>
#include <math.h>

// ---------------- problem constants ----------------
#define BB 4
#define HI 56
#define WI 56
#define DD 256
#define HO 28
#define WO 28
#define NPOS 784           // HO*WO
#define NTOK (BB*NPOS)     // 3136
#define NTOKIN (BB*HI*WI)  // 12544
#define HEADS 8
#define HDIM 32
#define KG 3
#define KB 7
#define LN_EPS 1e-5f

// ---------------- scratch (device globals; no allocations allowed) ----------------
__device__ float g_lnx   [NTOKIN*DD];
__device__ float g_tmp0  [NTOKIN*DD];
__device__ float g_kg    [BB*4*NPOS*DD];
__device__ float g_vg    [BB*4*NPOS*DD];
__device__ float g_colim [NTOK*2304];
__device__ float g_wseed [DD*2304];
__device__ float g_xout  [NTOK*DD];
__device__ float g_buf1  [NTOK*768];
__device__ float g_buf2  [NTOK*768];
__device__ float g_attn  [BB*4*NPOS*9];
__device__ float g_colsum[BB*NPOS];
__device__ float g_cos   [NPOS*16];
__device__ float g_sin   [NPOS*16];

// ---------------- LN over 256 (optionally + residual) ----------------
__global__ void ln256(const float* __restrict__ in, const float* __restrict__ gamma,
                      const float* __restrict__ beta, const float* __restrict__ res,
                      float* __restrict__ out) {
    int row = blockIdx.x, t = threadIdx.x;
    float x = in[row*DD + t];
    __shared__ float sm[8];
    float v = x;
    #pragma unroll
    for (int o=16;o;o>>=1) v += __shfl_xor_sync(0xffffffffu, v, o);
    if ((t&31)==0) sm[t>>5] = v;
    __syncthreads();
    float tot = 0.f;
    #pragma unroll
    for (int u=0;u<8;u++) tot += sm[u];
    float mean = tot * (1.f/256.f);
    __syncthreads();
    float d = x - mean;
    v = d*d;
    #pragma unroll
    for (int o=16;o;o>>=1) v += __shfl_xor_sync(0xffffffffu, v, o);
    if ((t&31)==0) sm[t>>5] = v;
    __syncthreads();
    tot = 0.f;
    #pragma unroll
    for (int u=0;u<8;u++) tot += sm[u];
    float var = tot * (1.f/256.f);
    float y = d * rsqrtf(var + LN_EPS) * gamma[t] + beta[t];
    if (res) y += res[row*DD + t];
    out[row*DD + t] = y;
}

// ---------------- SGEMM: C[M,N] = A[M,K] @ W[N,K]^T (+bias)(gelu)(+res) ----------------
// 64x64 tile, 128 threads, 8x4 microtile, double-buffered smem, vector LDS.
// Requires M%64==0, N%64==0, K%16==0.
__device__ __forceinline__ float gelu_exact(float x) {
    return 0.5f * x * (1.f + erff(x * 0.70710678118654752f));
}

#define BMT 64
#define BNT 64
#define BKT 16
#define SPAD 4

__global__ __launch_bounds__(128)
void gemm_nt(const float* __restrict__ A, const float* __restrict__ W,
             const float* __restrict__ bias, const float* __restrict__ res,
             float* __restrict__ C, int M, int N, int K, int act) {
    __shared__ float As[2][BKT][BMT+SPAD];
    __shared__ float Bs[2][BKT][BNT+SPAD];
    int tid = threadIdx.x;
    int tm = tid >> 4, tn = tid & 15;            // 8 x 16 thread grid
    int bm = blockIdx.y * BMT, bn = blockIdx.x * BNT;
    float acc[8][4] = {};

    const float* Abase = A + (size_t)bm * K;
    const float* Wbase = W + (size_t)bn * K;

    // per-thread global-load coords: 2 float4 each for A and B per k-tile
    int idx0 = tid * 2;
    int row0 = idx0 >> 2, c40 = (idx0 & 3) * 4;
    int idx1 = idx0 + 1;
    int row1 = idx1 >> 2, c41 = (idx1 & 3) * 4;

    float4 ra0, ra1, rb0, rb1;
    ra0 = *(const float4*)(Abase + (size_t)row0*K + c40);
    ra1 = *(const float4*)(Abase + (size_t)row1*K + c41);
    rb0 = *(const float4*)(Wbase + (size_t)row0*K + c40);
    rb1 = *(const float4*)(Wbase + (size_t)row1*K + c41);

    #define STORE_SMEM(BUF)                                                   \
        As[BUF][c40+0][row0]=ra0.x; As[BUF][c40+1][row0]=ra0.y;               \
        As[BUF][c40+2][row0]=ra0.z; As[BUF][c40+3][row0]=ra0.w;               \
        As[BUF][c41+0][row1]=ra1.x; As[BUF][c41+1][row1]=ra1.y;               \
        As[BUF][c41+2][row1]=ra1.z; As[BUF][c41+3][row1]=ra1.w;               \
        Bs[BUF][c40+0][row0]=rb0.x; Bs[BUF][c40+1][row0]=rb0.y;               \
        Bs[BUF][c40+2][row0]=rb0.z; Bs[BUF][c40+3][row0]=rb0.w;               \
        Bs[BUF][c41+0][row1]=rb1.x; Bs[BUF][c41+1][row1]=rb1.y;               \
        Bs[BUF][c41+2][row1]=rb1.z; Bs[BUF][c41+3][row1]=rb1.w;

    STORE_SMEM(0)
    __syncthreads();

    int buf = 0;
    for (int k0 = 0; k0 < K; k0 += BKT) {
        bool more = (k0 + BKT) < K;
        if (more) {
            int kn = k0 + BKT;
            ra0 = *(const float4*)(Abase + (size_t)row0*K + kn + c40);
            ra1 = *(const float4*)(Abase + (size_t)row1*K + kn + c41);
            rb0 = *(const float4*)(Wbase + (size_t)row0*K + kn + c40);
            rb1 = *(const float4*)(Wbase + (size_t)row1*K + kn + c41);
        }
        #pragma unroll
        for (int kk = 0; kk < BKT; kk++) {
            float a[8], b[4];
            *(float4*)&a[0] = *(const float4*)&As[buf][kk][tm*8];
            *(float4*)&a[4] = *(const float4*)&As[buf][kk][tm*8+4];
            *(float4*)&b[0] = *(const float4*)&Bs[buf][kk][tn*4];
            #pragma unroll
            for (int i=0;i<8;i++)
                #pragma unroll
                for (int j=0;j<4;j++)
                    acc[i][j] = fmaf(a[i], b[j], acc[i][j]);
        }
        if (!more) break;
        int nb = buf ^ 1;
        STORE_SMEM(nb)
        __syncthreads();
        buf = nb;
    }
    #undef STORE_SMEM

    float bv[4] = {0.f,0.f,0.f,0.f};
    if (bias) *(float4*)bv = *(const float4*)(bias + bn + tn*4);
    #pragma unroll
    for (int i=0;i<8;i++) {
        int r = bm + tm*8 + i;
        float o[4];
        #pragma unroll
        for (int j=0;j<4;j++) {
            float v = acc[i][j] + bv[j];
            if (act) v = gelu_exact(v);
            o[j] = v;
        }
        if (res) {
            float4 rr = *(const float4*)(res + (size_t)r*N + bn + tn*4);
            o[0]+=rr.x; o[1]+=rr.y; o[2]+=rr.z; o[3]+=rr.w;
        }
        *(float4*)(C + (size_t)r*N + bn + tn*4) = *(float4*)o;
    }
}

// ---------------- permute (B,56,56,D) -> (B,4,28,28,D), group = dh*2+dw ----------------
__global__ void to_groups_k(const float* __restrict__ in, float* __restrict__ out) {
    int idx = blockIdx.x*blockDim.x + threadIdx.x;
    if (idx >= BB*4*NPOS*DD) return;
    int d = idx & 255; int r = idx >> 8;
    int p = r % NPOS; int bg = r / NPOS; int g = bg & 3; int b = bg >> 2;
    int i = p / WO, j = p % WO;
    int dh = g >> 1, dw = g & 1;
    int srow = b*(HI*WI) + (2*i+dh)*WI + (2*j+dw);
    out[idx] = in[(size_t)srow*DD + d];
}

// ---------------- im2col for seed conv (3x3 stride2 pad1) ----------------
__global__ void im2col_k(const float* __restrict__ x, float* __restrict__ out) {
    int idx = blockIdx.x*blockDim.x + threadIdx.x;
    const int total = NTOK*2304;
    if (idx >= total) return;
    int col = idx % 2304; int row = idx / 2304;
    int b = row / NPOS; int p = row % NPOS;
    int i = p / WO, j = p % WO;
    int kk = col >> 8; int ic = col & 255;
    int kh = kk / 3, kw = kk % 3;
    int hi = 2*i - 1 + kh, wi = 2*j - 1 + kw;
    float v = 0.f;
    if (hi >= 0 && hi < HI && wi >= 0 && wi < WI)
        v = x[((size_t)(b*(HI*WI) + hi*WI + wi))*DD + ic];
    out[idx] = v;
}

// w (oc,ic,kh,kw) -> w2[oc][kk*256+ic]
__global__ void wseed_tr(const float* __restrict__ w, float* __restrict__ w2) {
    int idx = blockIdx.x*blockDim.x + threadIdx.x;
    if (idx >= DD*2304) return;
    int oc = idx / 2304; int c = idx % 2304;
    int kk = c >> 8; int ic = c & 255;
    w2[idx] = w[(size_t)oc*2304 + ic*9 + kk];
}

// ---------------- group NA (K=3) logits + softmax ----------------
__global__ void na3_attn(const float* __restrict__ kg, const float* __restrict__ q,
                         const float* __restrict__ rpb, const float* __restrict__ tau,
                         float* __restrict__ attn) {
    int blk = blockIdx.x;                   // (b*4+n)*784 + p
    int p = blk % NPOS; int bn = blk / NPOS; int n = bn & 3; int b = bn >> 2;
    int i = p / WO, j = p % WO;
    int t = threadIdx.x; int w = t >> 5; int lane = t & 31;   // 9 warps
    __shared__ float logit[9];
    __shared__ float ev[9];
    int a = w / 3, c = w % 3;
    int si = min(max(i-1,0),25), sj = min(max(j-1,0),25);
    int np = (si+a)*WO + (sj+c);
    const float* kv = kg + (size_t)blk*DD;
    const float* qv = q + (size_t)(b*NPOS + np)*DD;
    float s = 0.f;
    #pragma unroll
    for (int u=0;u<8;u++) s = fmaf(kv[lane + 32*u], qv[lane + 32*u], s);
    #pragma unroll
    for (int o=16;o;o>>=1) s += __shfl_xor_sync(0xffffffffu, s, o);
    if (lane==0) logit[w] = s + rpb[n*9 + w];
    __syncthreads();
    if (t < 9) {
        float scale = expf(tau[0]);
        float m = -1e30f;
        #pragma unroll
        for (int u=0;u<9;u++) m = fmaxf(m, logit[u]*scale);
        ev[t] = expf(logit[t]*scale - m);
    }
    __syncthreads();
    if (t < 9) {
        float sum = 0.f;
        #pragma unroll
        for (int u=0;u<9;u++) sum += ev[u];
        attn[(size_t)blk*9 + t] = ev[t]/sum + 1e-6f;
    }
}

// ---------------- deterministic column scatter-sum ----------------
__device__ __forceinline__ int inv_list(int s, int* lst) {
    if (s == 0)       { lst[0]=0;  lst[1]=1;  return 2; }
    else if (s == 25) { lst[0]=26; lst[1]=27; return 2; }
    else              { lst[0]=s+1;           return 1; }
}

__global__ void col_sum_k(const float* __restrict__ attn, float* __restrict__ col) {
    int idx = blockIdx.x*blockDim.x + threadIdx.x;
    if (idx >= BB*NPOS) return;
    int t = idx % NPOS, b = idx / NPOS;
    int ti = t / WO, tj = t % WO;
    float acc = 0.f;
    for (int a=0;a<3;a++) {
        int sr = ti - a; if (sr < 0 || sr > 25) continue;
        int il[2]; int ic = inv_list(sr, il);
        for (int c=0;c<3;c++) {
            int sc = tj - c; if (sc < 0 || sc > 25) continue;
            int jl[2]; int jc = inv_list(sc, jl);
            for (int ii=0; ii<ic; ii++)
                for (int jj=0; jj<jc; jj++) {
                    int pp = il[ii]*WO + jl[jj];
                    #pragma unroll
                    for (int n=0;n<4;n++)
                        acc += attn[((size_t)(b*4+n)*NPOS + pp)*9 + a*3 + c];
                }
        }
    }
    col[idx] = acc;
}

// ---------------- group NA AV + in-place residual ----------------
__global__ void na3_av(const float* __restrict__ attn, const float* __restrict__ col,
                       const float* __restrict__ vg, float* __restrict__ xout) {
    int blk = blockIdx.x;                 // b*784 + p
    int p = blk % NPOS, b = blk / NPOS;
    int i = p / WO, j = p % WO;
    int t = threadIdx.x;
    __shared__ float wgt[4][9];
    __shared__ int npos[9];
    if (t < 9) {
        int a = t/3, c = t%3;
        int ni = min(max(i-1,0),25)+a, nj = min(max(j-1,0),25)+c;
        npos[t] = ni*WO + nj;
    }
    __syncthreads();
    if (t < 36) {
        int n = t/9, ac = t%9;
        float av = attn[((size_t)(b*4+n)*NPOS + p)*9 + ac];
        wgt[n][ac] = av / (col[b*NPOS + npos[ac]] + 1e-8f);
    }
    __syncthreads();
    float acc = xout[(size_t)blk*DD + t];
    #pragma unroll
    for (int n=0;n<4;n++) {
        const float* vb = vg + (size_t)(b*4+n)*NPOS*DD;
        #pragma unroll
        for (int ac=0;ac<9;ac++)
            acc = fmaf(wgt[n][ac], vb[(size_t)npos[ac]*DD + t], acc);
    }
    xout[(size_t)blk*DD + t] = acc;
}

// ---------------- RoPE table + apply ----------------
__global__ void rope_tab(float* __restrict__ cs, float* __restrict__ sn) {
    int idx = blockIdx.x*blockDim.x + threadIdx.x;
    if (idx >= NPOS*16) return;
    int pos = idx / 16, r = idx % 16;
    float f = expf(-((float)(2*r) / 32.f) * 9.210340371976184f); // ln(10000)
    float ang = (float)pos * f;
    cs[idx] = cosf(ang);
    sn[idx] = sinf(ang);
}

__global__ void rope_apply(float* __restrict__ qkv, const float* __restrict__ cs,
                           const float* __restrict__ sn) {
    int idx = blockIdx.x*blockDim.x + threadIdx.x;
    const int total = BB*NPOS*2*HEADS*16;
    if (idx >= total) return;
    int r = idx % 16; int rest = idx / 16;
    int h = rest % HEADS; rest /= HEADS;
    int part = rest % 2; rest /= 2;
    int pos = rest % NPOS; int b = rest / NPOS;
    size_t base = ((size_t)(b*NPOS + pos))*768 + part*256 + h*32 + 2*r;
    float c = cs[pos*16 + r], s = sn[pos*16 + r];
    float x0 = qkv[base], x1 = qkv[base+1];
    qkv[base]   = x0*c - x1*s;
    qkv[base+1] = x1*c + x0*s;
}

// ---------------- block NA (K=7, HD=32) full attention ----------------
__global__ void na7_k(const float* __restrict__ qkv, float* __restrict__ obuf) {
    int blk = blockIdx.x;                 // (b*8+h)*784 + p
    int p = blk % NPOS; int bh = blk / NPOS; int h = bh & 7; int b = bh >> 3;
    int i = p / WO, j = p % WO;
    int t = threadIdx.x; int w = t >> 5; int lane = t & 31;   // 8 warps
    __shared__ float qs[32];
    __shared__ float logit[49];
    __shared__ float prob[49];
    __shared__ int   kpos[49];
    __shared__ float part[8][32];
    __shared__ float red[2];
    size_t rowbase = (size_t)(b*NPOS + p)*768;
    if (t < 32) qs[t] = qkv[rowbase + h*32 + t];
    int si = min(max(i-3,0),21), sj = min(max(j-3,0),21);
    __syncthreads();
    for (int nb = w; nb < 49; nb += 8) {
        int a = nb / 7, c = nb % 7;
        int kp = (si+a)*WO + (sj+c);
        const float* kptr = qkv + (size_t)(b*NPOS + kp)*768 + 256 + h*32;
        float s = qs[lane] * kptr[lane];
        #pragma unroll
        for (int o=16;o;o>>=1) s += __shfl_xor_sync(0xffffffffu, s, o);
        if (lane==0) { logit[nb] = s * 0.17677669529663687f; kpos[nb] = kp; }
    }
    __syncthreads();
    if (t == 0) {
        float m = -1e30f;
        #pragma unroll
        for (int u=0;u<49;u++) m = fmaxf(m, logit[u]);
        red[0] = m;
    }
    __syncthreads();
    if (t < 49) prob[t] = expf(logit[t] - red[0]);
    __syncthreads();
    if (t == 0) {
        float s = 0.f;
        #pragma unroll
        for (int u=0;u<49;u++) s += prob[u];
        red[1] = s;
    }
    __syncthreads();
    float inv = 1.f / red[1];
    float acc = 0.f;
    for (int nb = w; nb < 49; nb += 8) {
        const float* vptr = qkv + (size_t)(b*NPOS + kpos[nb])*768 + 512 + h*32;
        acc = fmaf(prob[nb]*inv, vptr[lane], acc);
    }
    part[w][lane] = acc;
    __syncthreads();
    if (w == 0) {
        float s = 0.f;
        #pragma unroll
        for (int u=0;u<8;u++) s += part[u][lane];
        obuf[(size_t)(b*NPOS + p)*DD + h*32 + lane] = s;
    }
}

// ---------------- launch helpers ----------------
static inline void run_gemm(const float* A, const float* W, const float* bias,
                            const float* res, float* C, int M, int N, int K, int act) {
    dim3 grid(N/64, M/64);
    gemm_nt<<<grid, 128>>>(A, W, bias, res, C, M, N, K, act);
}

extern "C" void kernel_launch(void* const* d_in, const int* in_sizes, int n_in,
                              void* d_out, int out_size) {
    const float* x          = (const float*)d_in[0];
    const float* g_seed_w   = (const float*)d_in[1];
    const float* g_q_w      = (const float*)d_in[2];
    const float* g_k_w      = (const float*)d_in[3];
    const float* g_v_w      = (const float*)d_in[4];
    const float* g_mlp_w1   = (const float*)d_in[5];
    const float* g_mlp_b1   = (const float*)d_in[6];
    const float* g_mlp_w2   = (const float*)d_in[7];
    const float* g_mlp_b2   = (const float*)d_in[8];
    const float* g_ln_in_g  = (const float*)d_in[9];
    const float* g_ln_in_b  = (const float*)d_in[10];
    const float* g_ln_out_g = (const float*)d_in[11];
    const float* g_ln_out_b = (const float*)d_in[12];
    const float* g_tau      = (const float*)d_in[13];
    const float* g_rpb      = (const float*)d_in[14];
    const float* blk_ln1_g  = (const float*)d_in[15];
    const float* blk_ln1_b  = (const float*)d_in[16];
    const float* blk_qkv_w  = (const float*)d_in[17];
    const float* blk_proj_w = (const float*)d_in[18];
    const float* blk_proj_b = (const float*)d_in[19];
    const float* blk_ln2_g  = (const float*)d_in[20];
    const float* blk_ln2_b  = (const float*)d_in[21];
    const float* blk_mlp_w1 = (const float*)d_in[22];
    const float* blk_mlp_b1 = (const float*)d_in[23];
    const float* blk_mlp_w2 = (const float*)d_in[24];
    const float* blk_mlp_b2 = (const float*)d_in[25];
    float* out = (float*)d_out;

    float *lnx, *tmp0, *kg, *vg, *colim, *wseed, *xout, *buf1, *buf2, *attn, *colsum, *csb, *snb;
    cudaGetSymbolAddress((void**)&lnx,   g_lnx);
    cudaGetSymbolAddress((void**)&tmp0,  g_tmp0);
    cudaGetSymbolAddress((void**)&kg,    g_kg);
    cudaGetSymbolAddress((void**)&vg,    g_vg);
    cudaGetSymbolAddress((void**)&colim, g_colim);
    cudaGetSymbolAddress((void**)&wseed, g_wseed);
    cudaGetSymbolAddress((void**)&xout,  g_xout);
    cudaGetSymbolAddress((void**)&buf1,  g_buf1);
    cudaGetSymbolAddress((void**)&buf2,  g_buf2);
    cudaGetSymbolAddress((void**)&attn,  g_attn);
    cudaGetSymbolAddress((void**)&colsum,g_colsum);
    cudaGetSymbolAddress((void**)&csb,   g_cos);
    cudaGetSymbolAddress((void**)&snb,   g_sin);

    // ---- k, v group projections ----
    ln256<<<NTOKIN, 256>>>(x, g_ln_in_g, g_ln_in_b, nullptr, lnx);
    run_gemm(lnx, g_k_w, nullptr, nullptr, tmp0, NTOKIN, DD, DD, 0);
    to_groups_k<<<(BB*4*NPOS*DD + 255)/256, 256>>>(tmp0, kg);
    run_gemm(x, g_v_w, nullptr, nullptr, tmp0, NTOKIN, DD, DD, 0);
    to_groups_k<<<(BB*4*NPOS*DD + 255)/256, 256>>>(tmp0, vg);

    // ---- seed conv via im2col + GEMM ----
    wseed_tr<<<(DD*2304 + 255)/256, 256>>>(g_seed_w, wseed);
    im2col_k<<<(NTOK*2304 + 255)/256, 256>>>(x, colim);
    run_gemm(colim, wseed, nullptr, nullptr, tmp0, NTOK, DD, 2304, 0);
    ln256<<<NTOK, 256>>>(tmp0, g_ln_out_g, g_ln_out_b, nullptr, xout);

    // ---- RoPE tables ----
    rope_tab<<<(NPOS*16 + 255)/256, 256>>>(csb, snb);

    // ---- 3 grouped-NA seeding iterations ----
    for (int it = 0; it < 3; it++) {
        ln256<<<NTOK, 256>>>(xout, g_ln_out_g, g_ln_out_b, nullptr, buf1);
        run_gemm(buf1, g_q_w, nullptr, nullptr, buf2, NTOK, DD, DD, 0);
        na3_attn<<<BB*4*NPOS, 288>>>(kg, buf2, g_rpb, g_tau, attn);
        col_sum_k<<<(BB*NPOS + 255)/256, 256>>>(attn, colsum);
        na3_av<<<NTOK, 256>>>(attn, colsum, vg, xout);
        run_gemm(xout, g_mlp_w1, g_mlp_b1, nullptr, buf1, NTOK, 512, DD, 1);
        run_gemm(buf1, g_mlp_w2, g_mlp_b2, nullptr, buf2, NTOK, DD, 512, 0);
        ln256<<<NTOK, 256>>>(buf2, g_ln_out_g, g_ln_out_b, xout, xout);
    }

    // ---- 2 transformer blocks with 7x7 NA ----
    for (int l = 0; l < 2; l++) {
        const float* ln1g = blk_ln1_g + l*DD;
        const float* ln1b = blk_ln1_b + l*DD;
        const float* qkvw = blk_qkv_w + (size_t)l*768*DD;
        const float* pjw  = blk_proj_w + (size_t)l*DD*DD;
        const float* pjb  = blk_proj_b + l*DD;
        const float* ln2g = blk_ln2_g + l*DD;
        const float* ln2b = blk_ln2_b + l*DD;
        const float* mw1  = blk_mlp_w1 + (size_t)l*768*DD;
        const float* mb1  = blk_mlp_b1 + l*768;
        const float* mw2  = blk_mlp_w2 + (size_t)l*DD*768;
        const float* mb2  = blk_mlp_b2 + l*DD;

        ln256<<<NTOK, 256>>>(xout, ln1g, ln1b, nullptr, buf1);
        run_gemm(buf1, qkvw, nullptr, nullptr, buf2, NTOK, 768, DD, 0);
        rope_apply<<<(BB*NPOS*2*HEADS*16 + 255)/256, 256>>>(buf2, csb, snb);
        na7_k<<<BB*HEADS*NPOS, 256>>>(buf2, buf1);
        run_gemm(buf1, pjw, pjb, xout, xout, NTOK, DD, DD, 0);
        ln256<<<NTOK, 256>>>(xout, ln2g, ln2b, nullptr, buf1);
        run_gemm(buf1, mw1, mb1, nullptr, buf2, NTOK, 768, DD, 1);
        run_gemm(buf2, mw2, mb2, xout, (l == 1) ? out : xout, NTOK, DD, 768, 0);
    }
}

// round 3
// speedup vs baseline: 1.2582x; 1.0859x over previous
#include <cuda_runtime.h>
#include <cuda_bf16.h>
#include <math.h>

// ---------------- problem constants ----------------
#define BB 4
#define HI 56
#define WI 56
#define DD 256
#define HO 28
#define WO 28
#define NPOS 784
#define NTOK (BB*NPOS)     // 3136
#define NTOKIN (BB*HI*WI)  // 12544
#define HEADS 8
#define LN_EPS 1e-5f

// ---------------- scratch ----------------
__device__ float g_lnx   [NTOKIN*DD];
__device__ float g_tmp0  [NTOKIN*DD];
__device__ float g_kg    [BB*4*NPOS*DD];
__device__ float g_vg    [BB*4*NPOS*DD];
__device__ float g_colim [NTOK*2304];
__device__ float g_wseed [DD*2304];
__device__ float g_xout  [NTOK*DD];
__device__ float g_buf1  [NTOK*768];
__device__ float g_buf2  [NTOK*768];
__device__ float g_split [3*NTOK*DD];
__device__ float g_attn  [BB*4*NPOS*9];
__device__ float g_colsum[BB*NPOS];
__device__ float g_cos   [NPOS*16];
__device__ float g_sin   [NPOS*16];

__device__ __forceinline__ float gelu_exact(float x) {
    return 0.5f * x * (1.f + erff(x * 0.70710678118654752f));
}

// ---------------- LN over 256 (optionally + residual) ----------------
__global__ void ln256(const float* __restrict__ in, const float* __restrict__ gamma,
                      const float* __restrict__ beta, const float* __restrict__ res,
                      float* __restrict__ out) {
    int row = blockIdx.x, t = threadIdx.x;
    float x = in[row*DD + t];
    __shared__ float sm[8];
    float v = x;
    #pragma unroll
    for (int o=16;o;o>>=1) v += __shfl_xor_sync(0xffffffffu, v, o);
    if ((t&31)==0) sm[t>>5] = v;
    __syncthreads();
    float tot = 0.f;
    #pragma unroll
    for (int u=0;u<8;u++) tot += sm[u];
    float mean = tot * (1.f/256.f);
    __syncthreads();
    float d = x - mean;
    v = d*d;
    #pragma unroll
    for (int o=16;o;o>>=1) v += __shfl_xor_sync(0xffffffffu, v, o);
    if ((t&31)==0) sm[t>>5] = v;
    __syncthreads();
    tot = 0.f;
    #pragma unroll
    for (int u=0;u<8;u++) tot += sm[u];
    float var = tot * (1.f/256.f);
    float y = d * rsqrtf(var + LN_EPS) * gamma[t] + beta[t];
    if (res) y += res[row*DD + t];
    out[row*DD + t] = y;
}

// ---------------- SGEMM 64x128 tile, 128 thr, 8x8 microtile, double-buffered ----------------
// C[M,N] = A[M,K] @ W[N,K]^T. M%64==0, N%128==0, (K/ksplit)%16==0.
// ksplit>1: writes raw partials to C + z*M*N (combine_k applies epilogue).
// remap: k/v group row permutation fused into epilogue (requires N==256, ksplit==1).
__global__ __launch_bounds__(128)
void gemm128(const float* __restrict__ A, const float* __restrict__ W,
             const float* __restrict__ bias, const float* __restrict__ res,
             float* __restrict__ C, int M, int N, int K,
             int act, int remap, int ksplit) {
    __shared__ float As[2][16][64+4];
    __shared__ float Bs[2][16][128+4];
    int tid = threadIdx.x;
    int tm = tid >> 4, tn = tid & 15;
    int bm = blockIdx.y * 64, bn = blockIdx.x * 128;
    int kper = K / ksplit;
    const float* Abase = A + (size_t)bm*K + (size_t)blockIdx.z*kper;
    const float* Wbase = W + (size_t)bn*K + (size_t)blockIdx.z*kper;
    int arow = tid >> 1, ac0 = (tid & 1) * 8;
    const float* Aptr = Abase + (size_t)arow*K + ac0;
    const float* Bptr = Wbase + (size_t)tid*K;

    float4 a0,a1,b0,b1,b2,b3;
#define LDG_TILE(k0) \
    a0 = *(const float4*)(Aptr + (k0));      \
    a1 = *(const float4*)(Aptr + (k0) + 4);  \
    b0 = *(const float4*)(Bptr + (k0));      \
    b1 = *(const float4*)(Bptr + (k0) + 4);  \
    b2 = *(const float4*)(Bptr + (k0) + 8);  \
    b3 = *(const float4*)(Bptr + (k0) + 12);

#define STS_TILE(bf) \
    As[bf][ac0+0][arow]=a0.x; As[bf][ac0+1][arow]=a0.y; As[bf][ac0+2][arow]=a0.z; As[bf][ac0+3][arow]=a0.w; \
    As[bf][ac0+4][arow]=a1.x; As[bf][ac0+5][arow]=a1.y; As[bf][ac0+6][arow]=a1.z; As[bf][ac0+7][arow]=a1.w; \
    Bs[bf][0][tid]=b0.x;  Bs[bf][1][tid]=b0.y;  Bs[bf][2][tid]=b0.z;  Bs[bf][3][tid]=b0.w;  \
    Bs[bf][4][tid]=b1.x;  Bs[bf][5][tid]=b1.y;  Bs[bf][6][tid]=b1.z;  Bs[bf][7][tid]=b1.w;  \
    Bs[bf][8][tid]=b2.x;  Bs[bf][9][tid]=b2.y;  Bs[bf][10][tid]=b2.z; Bs[bf][11][tid]=b2.w; \
    Bs[bf][12][tid]=b3.x; Bs[bf][13][tid]=b3.y; Bs[bf][14][tid]=b3.z; Bs[bf][15][tid]=b3.w;

    float acc[8][8] = {};
    LDG_TILE(0)
    STS_TILE(0)
    __syncthreads();
    int buf = 0;
    for (int k0 = 0; k0 < kper; k0 += 16) {
        bool more = (k0 + 16) < kper;
        if (more) { LDG_TILE(k0+16) }
        #pragma unroll
        for (int kk = 0; kk < 16; kk++) {
            float af[8], bfr[8];
            *(float4*)&af[0]  = *(const float4*)&As[buf][kk][tm*8];
            *(float4*)&af[4]  = *(const float4*)&As[buf][kk][tm*8+4];
            *(float4*)&bfr[0] = *(const float4*)&Bs[buf][kk][tn*4];
            *(float4*)&bfr[4] = *(const float4*)&Bs[buf][kk][64+tn*4];
            #pragma unroll
            for (int i=0;i<8;i++)
                #pragma unroll
                for (int j=0;j<8;j++)
                    acc[i][j] = fmaf(af[i], bfr[j], acc[i][j]);
        }
        if (!more) break;
        buf ^= 1;
        STS_TILE(buf)
        __syncthreads();
    }
#undef LDG_TILE
#undef STS_TILE

    if (ksplit > 1) {
        float* Cp = C + (size_t)blockIdx.z * M * N;
        #pragma unroll
        for (int i=0;i<8;i++) {
            size_t r = bm + tm*8 + i;
            *(float4*)(Cp + r*N + bn + tn*4)      = *(float4*)&acc[i][0];
            *(float4*)(Cp + r*N + bn + 64 + tn*4) = *(float4*)&acc[i][4];
        }
        return;
    }

    float bv[8] = {0.f,0.f,0.f,0.f,0.f,0.f,0.f,0.f};
    if (bias) {
        *(float4*)&bv[0] = *(const float4*)(bias + bn + tn*4);
        *(float4*)&bv[4] = *(const float4*)(bias + bn + 64 + tn*4);
    }
    #pragma unroll
    for (int i=0;i<8;i++) {
        int r = bm + tm*8 + i;
        int orow = r;
        if (remap) {
            int b = r / (HI*WI); int rr = r % (HI*WI);
            int hi = rr / WI, wi = rr % WI;
            orow = ((b*4 + (hi&1)*2 + (wi&1))*NPOS + (hi>>1)*WO + (wi>>1));
        }
        float o[8];
        #pragma unroll
        for (int j=0;j<8;j++) {
            float v = acc[i][j] + bv[j];
            if (act) v = gelu_exact(v);
            o[j] = v;
        }
        if (res) {
            float4 r0 = *(const float4*)(res + (size_t)orow*N + bn + tn*4);
            float4 r1 = *(const float4*)(res + (size_t)orow*N + bn + 64 + tn*4);
            o[0]+=r0.x; o[1]+=r0.y; o[2]+=r0.z; o[3]+=r0.w;
            o[4]+=r1.x; o[5]+=r1.y; o[6]+=r1.z; o[7]+=r1.w;
        }
        *(float4*)(C + (size_t)orow*N + bn + tn*4)      = *(float4*)&o[0];
        *(float4*)(C + (size_t)orow*N + bn + 64 + tn*4) = *(float4*)&o[4];
    }
}

// ---------------- split-K combine with epilogue ----------------
__global__ void combine_k(const float* __restrict__ part, int s,
                          const float* __restrict__ bias, const float* __restrict__ res,
                          float* __restrict__ out, int M, int N, int act) {
    int i4 = blockIdx.x*blockDim.x + threadIdx.x;
    int tot = (M*N) >> 2;
    if (i4 >= tot) return;
    float4 v = ((const float4*)part)[i4];
    for (int z = 1; z < s; z++) {
        float4 w = ((const float4*)(part + (size_t)z*M*N))[i4];
        v.x+=w.x; v.y+=w.y; v.z+=w.z; v.w+=w.w;
    }
    int col = (i4*4) % N;
    if (bias) {
        float4 bvv = *(const float4*)(bias + col);
        v.x+=bvv.x; v.y+=bvv.y; v.z+=bvv.z; v.w+=bvv.w;
    }
    if (act) { v.x=gelu_exact(v.x); v.y=gelu_exact(v.y); v.z=gelu_exact(v.z); v.w=gelu_exact(v.w); }
    if (res) {
        float4 rr = ((const float4*)res)[i4];
        v.x+=rr.x; v.y+=rr.y; v.z+=rr.z; v.w+=rr.w;
    }
    ((float4*)out)[i4] = v;
}

// ---------------- im2col for seed conv (3x3 stride2 pad1) ----------------
__global__ void im2col_k(const float* __restrict__ x, float* __restrict__ out) {
    int idx = blockIdx.x*blockDim.x + threadIdx.x;
    const int total = NTOK*2304;
    if (idx >= total) return;
    int col = idx % 2304; int row = idx / 2304;
    int b = row / NPOS; int p = row % NPOS;
    int i = p / WO, j = p % WO;
    int kk = col >> 8; int ic = col & 255;
    int kh = kk / 3, kw = kk % 3;
    int hi = 2*i - 1 + kh, wi = 2*j - 1 + kw;
    float v = 0.f;
    if (hi >= 0 && hi < HI && wi >= 0 && wi < WI)
        v = x[((size_t)(b*(HI*WI) + hi*WI + wi))*DD + ic];
    out[idx] = v;
}

__global__ void wseed_tr(const float* __restrict__ w, float* __restrict__ w2) {
    int idx = blockIdx.x*blockDim.x + threadIdx.x;
    if (idx >= DD*2304) return;
    int oc = idx / 2304; int c = idx % 2304;
    int kk = c >> 8; int ic = c & 255;
    w2[idx] = w[(size_t)oc*2304 + ic*9 + kk];
}

// ---------------- group NA (K=3) logits + softmax ----------------
__global__ void na3_attn(const float* __restrict__ kg, const float* __restrict__ q,
                         const float* __restrict__ rpb, const float* __restrict__ tau,
                         float* __restrict__ attn) {
    int blk = blockIdx.x;
    int p = blk % NPOS; int bn = blk / NPOS; int n = bn & 3; int b = bn >> 2;
    int i = p / WO, j = p % WO;
    int t = threadIdx.x; int w = t >> 5; int lane = t & 31;
    __shared__ float logit[9];
    __shared__ float ev[9];
    int a = w / 3, c = w % 3;
    int si = min(max(i-1,0),25), sj = min(max(j-1,0),25);
    int np = (si+a)*WO + (sj+c);
    const float* kv = kg + (size_t)blk*DD;
    const float* qv = q + (size_t)(b*NPOS + np)*DD;
    float s = 0.f;
    #pragma unroll
    for (int u=0;u<8;u++) s = fmaf(kv[lane + 32*u], qv[lane + 32*u], s);
    #pragma unroll
    for (int o=16;o;o>>=1) s += __shfl_xor_sync(0xffffffffu, s, o);
    if (lane==0) logit[w] = s + rpb[n*9 + w];
    __syncthreads();
    if (t < 9) {
        float scale = expf(tau[0]);
        float m = -1e30f;
        #pragma unroll
        for (int u=0;u<9;u++) m = fmaxf(m, logit[u]*scale);
        ev[t] = expf(logit[t]*scale - m);
    }
    __syncthreads();
    if (t < 9) {
        float sum = 0.f;
        #pragma unroll
        for (int u=0;u<9;u++) sum += ev[u];
        attn[(size_t)blk*9 + t] = ev[t]/sum + 1e-6f;
    }
}

// ---------------- deterministic column scatter-sum ----------------
__device__ __forceinline__ int inv_list(int s, int* lst) {
    if (s == 0)       { lst[0]=0;  lst[1]=1;  return 2; }
    else if (s == 25) { lst[0]=26; lst[1]=27; return 2; }
    else              { lst[0]=s+1;           return 1; }
}

__global__ void col_sum_k(const float* __restrict__ attn, float* __restrict__ col) {
    int idx = blockIdx.x*blockDim.x + threadIdx.x;
    if (idx >= BB*NPOS) return;
    int t = idx % NPOS, b = idx / NPOS;
    int ti = t / WO, tj = t % WO;
    float acc = 0.f;
    for (int a=0;a<3;a++) {
        int sr = ti - a; if (sr < 0 || sr > 25) continue;
        int il[2]; int ic = inv_list(sr, il);
        for (int c=0;c<3;c++) {
            int sc = tj - c; if (sc < 0 || sc > 25) continue;
            int jl[2]; int jc = inv_list(sc, jl);
            for (int ii=0; ii<ic; ii++)
                for (int jj=0; jj<jc; jj++) {
                    int pp = il[ii]*WO + jl[jj];
                    #pragma unroll
                    for (int n=0;n<4;n++)
                        acc += attn[((size_t)(b*4+n)*NPOS + pp)*9 + a*3 + c];
                }
        }
    }
    col[idx] = acc;
}

// ---------------- group NA AV + in-place residual ----------------
__global__ void na3_av(const float* __restrict__ attn, const float* __restrict__ col,
                       const float* __restrict__ vg, float* __restrict__ xout) {
    int blk = blockIdx.x;
    int p = blk % NPOS, b = blk / NPOS;
    int i = p / WO, j = p % WO;
    int t = threadIdx.x;
    __shared__ float wgt[4][9];
    __shared__ int npos[9];
    if (t < 9) {
        int a = t/3, c = t%3;
        int ni = min(max(i-1,0),25)+a, nj = min(max(j-1,0),25)+c;
        npos[t] = ni*WO + nj;
    }
    __syncthreads();
    if (t < 36) {
        int n = t/9, ac = t%9;
        float av = attn[((size_t)(b*4+n)*NPOS + p)*9 + ac];
        wgt[n][ac] = av / (col[b*NPOS + npos[ac]] + 1e-8f);
    }
    __syncthreads();
    float acc = xout[(size_t)blk*DD + t];
    #pragma unroll
    for (int n=0;n<4;n++) {
        const float* vb = vg + (size_t)(b*4+n)*NPOS*DD;
        #pragma unroll
        for (int ac=0;ac<9;ac++)
            acc = fmaf(wgt[n][ac], vb[(size_t)npos[ac]*DD + t], acc);
    }
    xout[(size_t)blk*DD + t] = acc;
}

// ---------------- RoPE table + apply ----------------
__global__ void rope_tab(float* __restrict__ cs, float* __restrict__ sn) {
    int idx = blockIdx.x*blockDim.x + threadIdx.x;
    if (idx >= NPOS*16) return;
    int pos = idx / 16, r = idx % 16;
    float f = expf(-((float)(2*r) / 32.f) * 9.210340371976184f);
    float ang = (float)pos * f;
    cs[idx] = cosf(ang);
    sn[idx] = sinf(ang);
}

__global__ void rope_apply(float* __restrict__ qkv, const float* __restrict__ cs,
                           const float* __restrict__ sn) {
    int idx = blockIdx.x*blockDim.x + threadIdx.x;
    const int total = BB*NPOS*2*HEADS*16;
    if (idx >= total) return;
    int r = idx % 16; int rest = idx / 16;
    int h = rest % HEADS; rest /= HEADS;
    int part = rest % 2; rest /= 2;
    int pos = rest % NPOS; int b = rest / NPOS;
    size_t base = ((size_t)(b*NPOS + pos))*768 + part*256 + h*32 + 2*r;
    float c = cs[pos*16 + r], s = sn[pos*16 + r];
    float x0 = qkv[base], x1 = qkv[base+1];
    qkv[base]   = x0*c - x1*s;
    qkv[base+1] = x1*c + x0*s;
}

// ---------------- block NA (K=7, HD=32) ----------------
__global__ void na7_k(const float* __restrict__ qkv, float* __restrict__ obuf) {
    int blk = blockIdx.x;
    int p = blk % NPOS; int bh = blk / NPOS; int h = bh & 7; int b = bh >> 3;
    int i = p / WO, j = p % WO;
    int t = threadIdx.x; int w = t >> 5; int lane = t & 31;
    __shared__ float qs[32];
    __shared__ float logit[49];
    __shared__ float prob[49];
    __shared__ int   kpos[49];
    __shared__ float part[8][32];
    __shared__ float red[2];
    size_t rowbase = (size_t)(b*NPOS + p)*768;
    if (t < 32) qs[t] = qkv[rowbase + h*32 + t];
    int si = min(max(i-3,0),21), sj = min(max(j-3,0),21);
    __syncthreads();
    for (int nb = w; nb < 49; nb += 8) {
        int a = nb / 7, c = nb % 7;
        int kp = (si+a)*WO + (sj+c);
        const float* kptr = qkv + (size_t)(b*NPOS + kp)*768 + 256 + h*32;
        float s = qs[lane] * kptr[lane];
        #pragma unroll
        for (int o=16;o;o>>=1) s += __shfl_xor_sync(0xffffffffu, s, o);
        if (lane==0) { logit[nb] = s * 0.17677669529663687f; kpos[nb] = kp; }
    }
    __syncthreads();
    if (t == 0) {
        float m = -1e30f;
        #pragma unroll
        for (int u=0;u<49;u++) m = fmaxf(m, logit[u]);
        red[0] = m;
    }
    __syncthreads();
    if (t < 49) prob[t] = expf(logit[t] - red[0]);
    __syncthreads();
    if (t == 0) {
        float s = 0.f;
        #pragma unroll
        for (int u=0;u<49;u++) s += prob[u];
        red[1] = s;
    }
    __syncthreads();
    float inv = 1.f / red[1];
    float acc = 0.f;
    for (int nb = w; nb < 49; nb += 8) {
        const float* vptr = qkv + (size_t)(b*NPOS + kpos[nb])*768 + 512 + h*32;
        acc = fmaf(prob[nb]*inv, vptr[lane], acc);
    }
    part[w][lane] = acc;
    __syncthreads();
    if (w == 0) {
        float s = 0.f;
        #pragma unroll
        for (int u=0;u<8;u++) s += part[u][lane];
        obuf[(size_t)(b*NPOS + p)*DD + h*32 + lane] = s;
    }
}

// ---------------- launch helpers ----------------
static inline void run_g(const float* A, const float* W, const float* bias,
                         const float* res, float* C, int M, int N, int K,
                         int act, int remap, int s) {
    dim3 grid(N/128, M/64, s);
    gemm128<<<grid, 128>>>(A, W, bias, res, C, M, N, K, act, remap, s);
}
static inline void run_combine(const float* part, int s, const float* bias,
                               const float* res, float* out, int M, int N, int act) {
    int tot4 = (M*N) >> 2;
    combine_k<<<(tot4 + 255)/256, 256>>>(part, s, bias, res, out, M, N, act);
}

extern "C" void kernel_launch(void* const* d_in, const int* in_sizes, int n_in,
                              void* d_out, int out_size) {
    const float* x          = (const float*)d_in[0];
    const float* g_seed_w   = (const float*)d_in[1];
    const float* g_q_w      = (const float*)d_in[2];
    const float* g_k_w      = (const float*)d_in[3];
    const float* g_v_w      = (const float*)d_in[4];
    const float* g_mlp_w1   = (const float*)d_in[5];
    const float* g_mlp_b1   = (const float*)d_in[6];
    const float* g_mlp_w2   = (const float*)d_in[7];
    const float* g_mlp_b2   = (const float*)d_in[8];
    const float* g_ln_in_g  = (const float*)d_in[9];
    const float* g_ln_in_b  = (const float*)d_in[10];
    const float* g_ln_out_g = (const float*)d_in[11];
    const float* g_ln_out_b = (const float*)d_in[12];
    const float* g_tau      = (const float*)d_in[13];
    const float* g_rpb      = (const float*)d_in[14];
    const float* blk_ln1_g  = (const float*)d_in[15];
    const float* blk_ln1_b  = (const float*)d_in[16];
    const float* blk_qkv_w  = (const float*)d_in[17];
    const float* blk_proj_w = (const float*)d_in[18];
    const float* blk_proj_b = (const float*)d_in[19];
    const float* blk_ln2_g  = (const float*)d_in[20];
    const float* blk_ln2_b  = (const float*)d_in[21];
    const float* blk_mlp_w1 = (const float*)d_in[22];
    const float* blk_mlp_b1 = (const float*)d_in[23];
    const float* blk_mlp_w2 = (const float*)d_in[24];
    const float* blk_mlp_b2 = (const float*)d_in[25];
    float* out = (float*)d_out;

    float *lnx, *tmp0, *kg, *vg, *colim, *wseed, *xout, *buf1, *buf2, *split,
          *attn, *colsum, *csb, *snb;
    cudaGetSymbolAddress((void**)&lnx,   g_lnx);
    cudaGetSymbolAddress((void**)&tmp0,  g_tmp0);
    cudaGetSymbolAddress((void**)&kg,    g_kg);
    cudaGetSymbolAddress((void**)&vg,    g_vg);
    cudaGetSymbolAddress((void**)&colim, g_colim);
    cudaGetSymbolAddress((void**)&wseed, g_wseed);
    cudaGetSymbolAddress((void**)&xout,  g_xout);
    cudaGetSymbolAddress((void**)&buf1,  g_buf1);
    cudaGetSymbolAddress((void**)&buf2,  g_buf2);
    cudaGetSymbolAddress((void**)&split, g_split);
    cudaGetSymbolAddress((void**)&attn,  g_attn);
    cudaGetSymbolAddress((void**)&colsum,g_colsum);
    cudaGetSymbolAddress((void**)&csb,   g_cos);
    cudaGetSymbolAddress((void**)&snb,   g_sin);

    // ---- k, v group projections (permute fused into epilogue) ----
    ln256<<<NTOKIN, 256>>>(x, g_ln_in_g, g_ln_in_b, nullptr, lnx);
    run_g(lnx, g_k_w, nullptr, nullptr, kg, NTOKIN, DD, DD, 0, 1, 1);
    run_g(x,   g_v_w, nullptr, nullptr, vg, NTOKIN, DD, DD, 0, 1, 1);

    // ---- seed conv via im2col + split-K GEMM ----
    wseed_tr<<<(DD*2304 + 255)/256, 256>>>(g_seed_w, wseed);
    im2col_k<<<(NTOK*2304 + 255)/256, 256>>>(x, colim);
    run_g(colim, wseed, nullptr, nullptr, split, NTOK, DD, 2304, 0, 0, 3);
    run_combine(split, 3, nullptr, nullptr, tmp0, NTOK, DD, 0);
    ln256<<<NTOK, 256>>>(tmp0, g_ln_out_g, g_ln_out_b, nullptr, xout);

    rope_tab<<<(NPOS*16 + 255)/256, 256>>>(csb, snb);

    // ---- 3 grouped-NA seeding iterations ----
    for (int it = 0; it < 3; it++) {
        ln256<<<NTOK, 256>>>(xout, g_ln_out_g, g_ln_out_b, nullptr, buf1);
        run_g(buf1, g_q_w, nullptr, nullptr, split, NTOK, DD, DD, 0, 0, 2);
        run_combine(split, 2, nullptr, nullptr, buf2, NTOK, DD, 0);
        na3_attn<<<BB*4*NPOS, 288>>>(kg, buf2, g_rpb, g_tau, attn);
        col_sum_k<<<(BB*NPOS + 255)/256, 256>>>(attn, colsum);
        na3_av<<<NTOK, 256>>>(attn, colsum, vg, xout);
        run_g(xout, g_mlp_w1, g_mlp_b1, nullptr, buf1, NTOK, 512, DD, 1, 0, 1);
        run_g(buf1, g_mlp_w2, nullptr, nullptr, split, NTOK, DD, 512, 0, 0, 2);
        run_combine(split, 2, g_mlp_b2, nullptr, buf2, NTOK, DD, 0);
        ln256<<<NTOK, 256>>>(buf2, g_ln_out_g, g_ln_out_b, xout, xout);
    }

    // ---- 2 transformer blocks with 7x7 NA ----
    for (int l = 0; l < 2; l++) {
        const float* ln1g = blk_ln1_g + l*DD;
        const float* ln1b = blk_ln1_b + l*DD;
        const float* qkvw = blk_qkv_w + (size_t)l*768*DD;
        const float* pjw  = blk_proj_w + (size_t)l*DD*DD;
        const float* pjb  = blk_proj_b + l*DD;
        const float* ln2g = blk_ln2_g + l*DD;
        const float* ln2b = blk_ln2_b + l*DD;
        const float* mw1  = blk_mlp_w1 + (size_t)l*768*DD;
        const float* mb1  = blk_mlp_b1 + l*768;
        const float* mw2  = blk_mlp_w2 + (size_t)l*DD*768;
        const float* mb2  = blk_mlp_b2 + l*DD;

        ln256<<<NTOK, 256>>>(xout, ln1g, ln1b, nullptr, buf1);
        run_g(buf1, qkvw, nullptr, nullptr, buf2, NTOK, 768, DD, 0, 0, 1);
        rope_apply<<<(BB*NPOS*2*HEADS*16 + 255)/256, 256>>>(buf2, csb, snb);
        na7_k<<<BB*HEADS*NPOS, 256>>>(buf2, buf1);
        run_g(buf1, pjw, nullptr, nullptr, split, NTOK, DD, DD, 0, 0, 2);
        run_combine(split, 2, pjb, xout, xout, NTOK, DD, 0);
        ln256<<<NTOK, 256>>>(xout, ln2g, ln2b, nullptr, buf1);
        run_g(buf1, mw1, mb1, nullptr, buf2, NTOK, 768, DD, 1, 0, 1);
        run_g(buf2, mw2, nullptr, nullptr, split, NTOK, DD, 768, 0, 0, 2);
        run_combine(split, 2, mb2, xout, (l == 1) ? out : xout, NTOK, DD, 0);
    }
}

// round 5
// speedup vs baseline: 1.6726x; 1.3293x over previous
#include <cuda_runtime.h>
#include <cuda_bf16.h>
#include <math.h>
#include <stdint.h>

// ---------------- problem constants ----------------
#define BB 4
#define HI 56
#define WI 56
#define DD 256
#define HO 28
#define WO 28
#define NPOS 784
#define NTOK (BB*NPOS)     // 3136
#define NTOKP 3200         // padded to 128 multiple
#define NTOKIN (BB*HI*WI)  // 12544
#define HEADS 8
#define LN_EPS 1e-5f

typedef __nv_bfloat16 bf16;

// ---------------- scratch (device globals) ----------------
__device__ float g_tmp0  [NTOK*DD];
__device__ float g_xout  [NTOK*DD];
__device__ float g_buf1  [NTOK*768];
__device__ float g_buf2  [NTOK*768];
__device__ float g_kg    [BB*4*NPOS*DD];
__device__ float g_vg    [BB*4*NPOS*DD];
__device__ float g_split [3*NTOKP*DD];
__device__ float g_attn  [BB*4*NPOS*9];
__device__ float g_colsum[BB*NPOS];
__device__ float g_cos   [NPOS*16];
__device__ float g_sin   [NPOS*16];

// bf16 hi/lo operand buffers
__device__ bf16 g_xh[NTOKIN*DD],  g_xl[NTOKIN*DD];
__device__ bf16 g_lnxh[NTOKIN*DD],g_lnxl[NTOKIN*DD];
__device__ bf16 g_colh[NTOKP*2304], g_coll[NTOKP*2304];
__device__ bf16 g_a1h[NTOKP*768], g_a1l[NTOKP*768];
__device__ bf16 g_a2h[NTOKP*256], g_a2l[NTOKP*256];
// weights hi/lo
__device__ bf16 g_wsh[DD*2304], g_wsl[DD*2304];
__device__ bf16 g_wqh[DD*DD],   g_wql[DD*DD];
__device__ bf16 g_wkh[DD*DD],   g_wkl[DD*DD];
__device__ bf16 g_wvh[DD*DD],   g_wvl[DD*DD];
__device__ bf16 g_m1h[512*DD],  g_m1l[512*DD];
__device__ bf16 g_m2h[DD*512],  g_m2l[DD*512];
__device__ bf16 g_qkvh[2*768*DD], g_qkvl[2*768*DD];
__device__ bf16 g_pjh[2*DD*DD],   g_pjl[2*DD*DD];
__device__ bf16 g_bm1h[2*768*DD], g_bm1l[2*768*DD];
__device__ bf16 g_bm2h[2*DD*768], g_bm2l[2*DD*768];

// ---------------- helpers ----------------
__device__ __forceinline__ uint32_t smem_u32(const void* p) {
    uint32_t a;
    asm("{ .reg .u64 t; cvta.to.shared.u64 t, %1; cvt.u32.u64 %0, t; }" : "=r"(a) : "l"(p));
    return a;
}
__device__ __forceinline__ float gelu_exact(float x) {
    return 0.5f * x * (1.f + erff(x * 0.70710678118654752f));
}
__device__ __forceinline__ void cp16(uint32_t saddr, const void* gaddr) {
    asm volatile("cp.async.cg.shared.global [%0], [%1], 16;" :: "r"(saddr), "l"(gaddr));
}
#define CP_COMMIT() asm volatile("cp.async.commit_group;" ::: "memory")
#define CP_WAIT0()  asm volatile("cp.async.wait_group 0;" ::: "memory")

__device__ __forceinline__ void ldmx4(uint32_t addr, uint32_t* r) {
    asm volatile("ldmatrix.sync.aligned.m8n8.x4.shared.b16 {%0,%1,%2,%3}, [%4];"
        : "=r"(r[0]), "=r"(r[1]), "=r"(r[2]), "=r"(r[3]) : "r"(addr));
}
__device__ __forceinline__ void mma16816(float* d, const uint32_t* a, uint32_t b0, uint32_t b1) {
    asm volatile("mma.sync.aligned.m16n8k16.row.col.f32.bf16.bf16.f32 "
        "{%0,%1,%2,%3}, {%4,%5,%6,%7}, {%8,%9}, {%0,%1,%2,%3};"
        : "+f"(d[0]), "+f"(d[1]), "+f"(d[2]), "+f"(d[3])
        : "r"(a[0]), "r"(a[1]), "r"(a[2]), "r"(a[3]), "r"(b0), "r"(b1));
}

// ---------------- tensor-core GEMM (mma.sync bf16 hi/lo 3-pass) ----------------
// C[M,N] = A[M,K] @ W[N,K]^T, fp32 accum in registers.
// CTA tile 128x128, 8 warps (2x4), warp tile 64x32, K-chunk 64, cp.async double buffer.
#define TROW 144                       // smem row stride in bytes (64 bf16 + 8 pad)
#define TSZ  (128*TROW)                // 18432 bytes per tile
#define BUFSZ (4*TSZ)                  // Ah, Al, Bh, Bl
#define GTC_SMEM (2*BUFSZ)             // 147456

__global__ void __launch_bounds__(256, 1)
gemm_mma(const bf16* __restrict__ Ah, const bf16* __restrict__ Al,
         const bf16* __restrict__ Bh, const bf16* __restrict__ Bl,
         const float* __restrict__ bias, float* __restrict__ C,
         int Mreal, int Mpad, int N, int K, int act, int remap, int ksplit) {
    extern __shared__ char smraw[];
    uint32_t sb = smem_u32(smraw);
    int tid = threadIdx.x, wid = tid >> 5, lane = tid & 31;
    int wm = wid >> 2, wn = wid & 3;
    int bm = blockIdx.y * 128, bn = blockIdx.x * 128;
    int kper = K / ksplit;
    int kbase = blockIdx.z * kper;
    int nch = kper / 64;

    const bf16* srcs[4] = { Ah + (size_t)bm*K, Al + (size_t)bm*K,
                            Bh + (size_t)bn*K, Bl + (size_t)bn*K };
    int lrow = tid >> 1;              // rows: 2 threads per row, 4 rows per u-step? see below

    // load mapping: 1024 (row,seg) pairs per tile; idx = tid + u*256
    #define LOAD_CHUNK(c, b) {                                                  \
        int k0 = kbase + (c)*64;                                                \
        uint32_t dbase = sb + (b)*BUFSZ;                                        \
        _Pragma("unroll")                                                       \
        for (int s = 0; s < 4; s++) {                                           \
            const bf16* base = srcs[s];                                         \
            uint32_t dst = dbase + s*TSZ;                                       \
            _Pragma("unroll")                                                   \
            for (int u = 0; u < 4; u++) {                                       \
                int idx = tid + u*256;                                          \
                int row = idx >> 3, seg = idx & 7;                              \
                cp16(dst + row*TROW + seg*16, base + (size_t)row*K + k0 + seg*8); \
            }                                                                   \
        }                                                                       \
        CP_COMMIT();                                                            \
    }

    float acc[4][4][4];
    #pragma unroll
    for (int i=0;i<4;i++)
        #pragma unroll
        for (int j=0;j<4;j++)
            #pragma unroll
            for (int e=0;e<4;e++) acc[i][j][e] = 0.f;

    LOAD_CHUNK(0, 0)
    int buf = 0;
    int lr16 = lane & 15, lh = lane >> 4;    // ldmatrix addressing

    for (int c = 0; c < nch; c++) {
        CP_WAIT0();
        __syncthreads();
        if (c + 1 < nch) LOAD_CHUNK(c+1, buf^1)
        uint32_t aH = sb + buf*BUFSZ;
        uint32_t aL = aH + TSZ;
        uint32_t bH = aH + 2*TSZ;
        uint32_t bL = aH + 3*TSZ;
        #pragma unroll
        for (int kk = 0; kk < 4; kk++) {
            uint32_t ah[4][4], al[4][4], bh[2][4], bl[2][4];
            int kb = kk*32 + lh*16;
            #pragma unroll
            for (int mi = 0; mi < 4; mi++) {
                int row = wm*64 + mi*16 + lr16;
                ldmx4(aH + row*TROW + kb, ah[mi]);
                ldmx4(aL + row*TROW + kb, al[mi]);
            }
            #pragma unroll
            for (int n2 = 0; n2 < 2; n2++) {
                int row = wn*32 + n2*16 + lr16;
                ldmx4(bH + row*TROW + kb, bh[n2]);
                ldmx4(bL + row*TROW + kb, bl[n2]);
            }
            #pragma unroll
            for (int mi = 0; mi < 4; mi++) {
                #pragma unroll
                for (int nj = 0; nj < 4; nj++) {
                    int n2 = nj >> 1, sel = nj & 1;
                    mma16816(acc[mi][nj], ah[mi], bh[n2][sel], bh[n2][sel+2]);
                    mma16816(acc[mi][nj], ah[mi], bl[n2][sel], bl[n2][sel+2]);
                    mma16816(acc[mi][nj], al[mi], bh[n2][sel], bh[n2][sel+2]);
                }
            }
        }
        __syncthreads();
        buf ^= 1;
    }
    #undef LOAD_CHUNK

    // ---- epilogue ----
    int cbase = bn + wn*32 + (lane & 3)*2;
    int rbase = bm + wm*64 + (lane >> 2);
    if (ksplit > 1) {
        float* Cp = C + (size_t)blockIdx.z * Mpad * N;
        #pragma unroll
        for (int mi = 0; mi < 4; mi++) {
            #pragma unroll
            for (int half = 0; half < 2; half++) {
                int r = rbase + mi*16 + half*8;
                if (r >= Mreal) continue;
                #pragma unroll
                for (int nj = 0; nj < 4; nj++) {
                    float2 v = make_float2(acc[mi][nj][half*2], acc[mi][nj][half*2+1]);
                    *(float2*)(Cp + (size_t)r*N + cbase + nj*8) = v;
                }
            }
        }
        return;
    }
    #pragma unroll
    for (int mi = 0; mi < 4; mi++) {
        #pragma unroll
        for (int half = 0; half < 2; half++) {
            int r = rbase + mi*16 + half*8;
            if (r >= Mreal) continue;
            int orow = r;
            if (remap) {
                int b2 = r / (HI*WI); int rr = r % (HI*WI);
                int hi2 = rr / WI, wi2 = rr % WI;
                orow = (b2*4 + (hi2&1)*2 + (wi2&1))*NPOS + (hi2>>1)*WO + (wi2>>1);
            }
            #pragma unroll
            for (int nj = 0; nj < 4; nj++) {
                int col = cbase + nj*8;
                float v0 = acc[mi][nj][half*2], v1 = acc[mi][nj][half*2+1];
                if (bias) { v0 += bias[col]; v1 += bias[col+1]; }
                if (act)  { v0 = gelu_exact(v0); v1 = gelu_exact(v1); }
                *(float2*)(C + (size_t)orow*N + col) = make_float2(v0, v1);
            }
        }
    }
}

// ---------------- fp32 -> bf16 hi/lo converter ----------------
__global__ void cvt_hl(const float* __restrict__ in, bf16* __restrict__ hi,
                       bf16* __restrict__ lo, int n4) {
    int i = blockIdx.x*blockDim.x + threadIdx.x;
    if (i >= n4) return;
    float4 v = ((const float4*)in)[i];
    bf16 h0 = __float2bfloat16(v.x), h1 = __float2bfloat16(v.y);
    bf16 h2 = __float2bfloat16(v.z), h3 = __float2bfloat16(v.w);
    bf16 l0 = __float2bfloat16(v.x - __bfloat162float(h0));
    bf16 l1 = __float2bfloat16(v.y - __bfloat162float(h1));
    bf16 l2 = __float2bfloat16(v.z - __bfloat162float(h2));
    bf16 l3 = __float2bfloat16(v.w - __bfloat162float(h3));
    ((__nv_bfloat162*)hi)[2*i]   = __nv_bfloat162(h0, h1);
    ((__nv_bfloat162*)hi)[2*i+1] = __nv_bfloat162(h2, h3);
    ((__nv_bfloat162*)lo)[2*i]   = __nv_bfloat162(l0, l1);
    ((__nv_bfloat162*)lo)[2*i+1] = __nv_bfloat162(l2, l3);
}

// ---------------- LN over 256, optional residual, fp32 and/or hi/lo outputs ----------------
__global__ void ln256(const float* __restrict__ in, const float* __restrict__ gamma,
                      const float* __restrict__ beta, const float* __restrict__ res,
                      float* __restrict__ out, bf16* __restrict__ oh, bf16* __restrict__ ol) {
    int row = blockIdx.x, t = threadIdx.x;
    float x = in[row*DD + t];
    __shared__ float sm[8];
    float v = x;
    #pragma unroll
    for (int o=16;o;o>>=1) v += __shfl_xor_sync(0xffffffffu, v, o);
    if ((t&31)==0) sm[t>>5] = v;
    __syncthreads();
    float tot = 0.f;
    #pragma unroll
    for (int u=0;u<8;u++) tot += sm[u];
    float mean = tot * (1.f/256.f);
    __syncthreads();
    float d = x - mean;
    v = d*d;
    #pragma unroll
    for (int o=16;o;o>>=1) v += __shfl_xor_sync(0xffffffffu, v, o);
    if ((t&31)==0) sm[t>>5] = v;
    __syncthreads();
    tot = 0.f;
    #pragma unroll
    for (int u=0;u<8;u++) tot += sm[u];
    float var = tot * (1.f/256.f);
    float y = d * rsqrtf(var + LN_EPS) * gamma[t] + beta[t];
    if (res) y += res[row*DD + t];
    if (out) out[row*DD + t] = y;
    if (oh) {
        bf16 h = __float2bfloat16(y);
        oh[row*DD + t] = h;
        ol[row*DD + t] = __float2bfloat16(y - __bfloat162float(h));
    }
}

// ---------------- split-K combine with epilogue ----------------
__global__ void combine_k(const float* __restrict__ part, int s,
                          const float* __restrict__ bias, const float* __restrict__ res,
                          float* __restrict__ out, int Mreal, int Mpad, int N, int act) {
    int i4 = blockIdx.x*blockDim.x + threadIdx.x;
    int tot = (Mreal*N) >> 2;
    if (i4 >= tot) return;
    size_t zs = ((size_t)Mpad*N) >> 2;
    float4 v = ((const float4*)part)[i4];
    for (int z = 1; z < s; z++) {
        float4 w = ((const float4*)part)[i4 + z*zs];
        v.x+=w.x; v.y+=w.y; v.z+=w.z; v.w+=w.w;
    }
    int col = (i4*4) % N;
    if (bias) {
        float4 bvv = *(const float4*)(bias + col);
        v.x+=bvv.x; v.y+=bvv.y; v.z+=bvv.z; v.w+=bvv.w;
    }
    if (act) { v.x=gelu_exact(v.x); v.y=gelu_exact(v.y); v.z=gelu_exact(v.z); v.w=gelu_exact(v.w); }
    if (res) {
        float4 rr = ((const float4*)res)[i4];
        v.x+=rr.x; v.y+=rr.y; v.z+=rr.z; v.w+=rr.w;
    }
    ((float4*)out)[i4] = v;
}

// ---------------- im2col (3x3 stride2 pad1) directly to bf16 hi/lo ----------------
__global__ void im2col_hl(const float* __restrict__ x, bf16* __restrict__ oh, bf16* __restrict__ ol) {
    int idx = blockIdx.x*blockDim.x + threadIdx.x;
    const int total = NTOK*2304;
    if (idx >= total) return;
    int col = idx % 2304; int row = idx / 2304;
    int b = row / NPOS; int p = row % NPOS;
    int i = p / WO, j = p % WO;
    int kk = col >> 8; int ic = col & 255;
    int kh = kk / 3, kw = kk % 3;
    int hi = 2*i - 1 + kh, wi = 2*j - 1 + kw;
    float v = 0.f;
    if (hi >= 0 && hi < HI && wi >= 0 && wi < WI)
        v = x[((size_t)(b*(HI*WI) + hi*WI + wi))*DD + ic];
    bf16 h = __float2bfloat16(v);
    size_t o = (size_t)row*2304 + col;
    oh[o] = h;
    ol[o] = __float2bfloat16(v - __bfloat162float(h));
}

// seed weight (oc,ic,kh,kw) -> [oc][kk*256+ic] bf16 hi/lo
__global__ void wseed_tr_hl(const float* __restrict__ w, bf16* __restrict__ oh, bf16* __restrict__ ol) {
    int idx = blockIdx.x*blockDim.x + threadIdx.x;
    if (idx >= DD*2304) return;
    int oc = idx / 2304; int c = idx % 2304;
    int kk = c >> 8; int ic = c & 255;
    float v = w[(size_t)oc*2304 + ic*9 + kk];
    bf16 h = __float2bfloat16(v);
    oh[idx] = h;
    ol[idx] = __float2bfloat16(v - __bfloat162float(h));
}

// ---------------- group NA (K=3) logits + softmax ----------------
__global__ void na3_attn(const float* __restrict__ kg, const float* __restrict__ q,
                         const float* __restrict__ rpb, const float* __restrict__ tau,
                         float* __restrict__ attn) {
    int blk = blockIdx.x;
    int p = blk % NPOS; int bn = blk / NPOS; int n = bn & 3; int b = bn >> 2;
    int i = p / WO, j = p % WO;
    int t = threadIdx.x; int w = t >> 5; int lane = t & 31;
    __shared__ float logit[9];
    __shared__ float ev[9];
    int a = w / 3, c = w % 3;
    int si = min(max(i-1,0),25), sj = min(max(j-1,0),25);
    int np = (si+a)*WO + (sj+c);
    const float* kv = kg + (size_t)blk*DD;
    const float* qv = q + (size_t)(b*NPOS + np)*DD;
    float s = 0.f;
    #pragma unroll
    for (int u=0;u<8;u++) s = fmaf(kv[lane + 32*u], qv[lane + 32*u], s);
    #pragma unroll
    for (int o=16;o;o>>=1) s += __shfl_xor_sync(0xffffffffu, s, o);
    if (lane==0) logit[w] = s + rpb[n*9 + w];
    __syncthreads();
    if (t < 9) {
        float scale = expf(tau[0]);
        float m = -1e30f;
        #pragma unroll
        for (int u=0;u<9;u++) m = fmaxf(m, logit[u]*scale);
        ev[t] = expf(logit[t]*scale - m);
    }
    __syncthreads();
    if (t < 9) {
        float sum = 0.f;
        #pragma unroll
        for (int u=0;u<9;u++) sum += ev[u];
        attn[(size_t)blk*9 + t] = ev[t]/sum + 1e-6f;
    }
}

// ---------------- deterministic column scatter-sum ----------------
__device__ __forceinline__ int inv_list(int s, int* lst) {
    if (s == 0)       { lst[0]=0;  lst[1]=1;  return 2; }
    else if (s == 25) { lst[0]=26; lst[1]=27; return 2; }
    else              { lst[0]=s+1;           return 1; }
}

__global__ void col_sum_k(const float* __restrict__ attn, float* __restrict__ col) {
    int idx = blockIdx.x*blockDim.x + threadIdx.x;
    if (idx >= BB*NPOS) return;
    int t = idx % NPOS, b = idx / NPOS;
    int ti = t / WO, tj = t % WO;
    float acc = 0.f;
    for (int a=0;a<3;a++) {
        int sr = ti - a; if (sr < 0 || sr > 25) continue;
        int il[2]; int ic = inv_list(sr, il);
        for (int c=0;c<3;c++) {
            int sc = tj - c; if (sc < 0 || sc > 25) continue;
            int jl[2]; int jc = inv_list(sc, jl);
            for (int ii=0; ii<ic; ii++)
                for (int jj=0; jj<jc; jj++) {
                    int pp = il[ii]*WO + jl[jj];
                    #pragma unroll
                    for (int n=0;n<4;n++)
                        acc += attn[((size_t)(b*4+n)*NPOS + pp)*9 + a*3 + c];
                }
        }
    }
    col[idx] = acc;
}

// ---------------- group NA AV + in-place residual ----------------
__global__ void na3_av(const float* __restrict__ attn, const float* __restrict__ col,
                       const float* __restrict__ vg, float* __restrict__ xout) {
    int blk = blockIdx.x;
    int p = blk % NPOS, b = blk / NPOS;
    int i = p / WO, j = p % WO;
    int t = threadIdx.x;
    __shared__ float wgt[4][9];
    __shared__ int npos[9];
    if (t < 9) {
        int a = t/3, c = t%3;
        int ni = min(max(i-1,0),25)+a, nj = min(max(j-1,0),25)+c;
        npos[t] = ni*WO + nj;
    }
    __syncthreads();
    if (t < 36) {
        int n = t/9, ac = t%9;
        float av = attn[((size_t)(b*4+n)*NPOS + p)*9 + ac];
        wgt[n][ac] = av / (col[b*NPOS + npos[ac]] + 1e-8f);
    }
    __syncthreads();
    float acc = xout[(size_t)blk*DD + t];
    #pragma unroll
    for (int n=0;n<4;n++) {
        const float* vb = vg + (size_t)(b*4+n)*NPOS*DD;
        #pragma unroll
        for (int ac=0;ac<9;ac++)
            acc = fmaf(wgt[n][ac], vb[(size_t)npos[ac]*DD + t], acc);
    }
    xout[(size_t)blk*DD + t] = acc;
}

// ---------------- RoPE table + apply ----------------
__global__ void rope_tab(float* __restrict__ cs, float* __restrict__ sn) {
    int idx = blockIdx.x*blockDim.x + threadIdx.x;
    if (idx >= NPOS*16) return;
    int pos = idx / 16, r = idx % 16;
    float f = expf(-((float)(2*r) / 32.f) * 9.210340371976184f);
    float ang = (float)pos * f;
    cs[idx] = cosf(ang);
    sn[idx] = sinf(ang);
}

__global__ void rope_apply(float* __restrict__ qkv, const float* __restrict__ cs,
                           const float* __restrict__ sn) {
    int idx = blockIdx.x*blockDim.x + threadIdx.x;
    const int total = BB*NPOS*2*HEADS*16;
    if (idx >= total) return;
    int r = idx % 16; int rest = idx / 16;
    int h = rest % HEADS; rest /= HEADS;
    int part = rest % 2; rest /= 2;
    int pos = rest % NPOS; int b = rest / NPOS;
    size_t base = ((size_t)(b*NPOS + pos))*768 + part*256 + h*32 + 2*r;
    float c = cs[pos*16 + r], s = sn[pos*16 + r];
    float x0 = qkv[base], x1 = qkv[base+1];
    qkv[base]   = x0*c - x1*s;
    qkv[base+1] = x1*c + x0*s;
}

// ---------------- block NA (K=7, HD=32) ----------------
__global__ void na7_k(const float* __restrict__ qkv, float* __restrict__ obuf) {
    int blk = blockIdx.x;
    int p = blk % NPOS; int bh = blk / NPOS; int h = bh & 7; int b = bh >> 3;
    int i = p / WO, j = p % WO;
    int t = threadIdx.x; int w = t >> 5; int lane = t & 31;
    __shared__ float qs[32];
    __shared__ float logit[49];
    __shared__ float prob[49];
    __shared__ int   kpos[49];
    __shared__ float part[8][32];
    __shared__ float red[2];
    size_t rowbase = (size_t)(b*NPOS + p)*768;
    if (t < 32) qs[t] = qkv[rowbase + h*32 + t];
    int si = min(max(i-3,0),21), sj = min(max(j-3,0),21);
    __syncthreads();
    for (int nb = w; nb < 49; nb += 8) {
        int a = nb / 7, c = nb % 7;
        int kp = (si+a)*WO + (sj+c);
        const float* kptr = qkv + (size_t)(b*NPOS + kp)*768 + 256 + h*32;
        float s = qs[lane] * kptr[lane];
        #pragma unroll
        for (int o=16;o;o>>=1) s += __shfl_xor_sync(0xffffffffu, s, o);
        if (lane==0) { logit[nb] = s * 0.17677669529663687f; kpos[nb] = kp; }
    }
    __syncthreads();
    if (t == 0) {
        float m = -1e30f;
        #pragma unroll
        for (int u=0;u<49;u++) m = fmaxf(m, logit[u]);
        red[0] = m;
    }
    __syncthreads();
    if (t < 49) prob[t] = expf(logit[t] - red[0]);
    __syncthreads();
    if (t == 0) {
        float s = 0.f;
        #pragma unroll
        for (int u=0;u<49;u++) s += prob[u];
        red[1] = s;
    }
    __syncthreads();
    float inv = 1.f / red[1];
    float acc = 0.f;
    for (int nb = w; nb < 49; nb += 8) {
        const float* vptr = qkv + (size_t)(b*NPOS + kpos[nb])*768 + 512 + h*32;
        acc = fmaf(prob[nb]*inv, vptr[lane], acc);
    }
    part[w][lane] = acc;
    __syncthreads();
    if (w == 0) {
        float s = 0.f;
        #pragma unroll
        for (int u=0;u<8;u++) s += part[u][lane];
        obuf[(size_t)(b*NPOS + p)*DD + h*32 + lane] = s;
    }
}

// ---------------- host helpers ----------------
static inline void run_tc(const bf16* Ah, const bf16* Al, const bf16* Bh, const bf16* Bl,
                          const float* bias, float* C, int Mreal, int Mpad, int N, int K,
                          int act, int remap, int ks) {
    dim3 grid(N/128, Mpad/128, ks);
    gemm_mma<<<grid, 256, GTC_SMEM>>>(Ah, Al, Bh, Bl, bias, C, Mreal, Mpad, N, K, act, remap, ks);
}
static inline void run_cvt(const float* in, bf16* hi, bf16* lo, int n) {
    int n4 = n >> 2;
    cvt_hl<<<(n4 + 255)/256, 256>>>(in, hi, lo, n4);
}
static inline void run_combine(const float* part, int s, const float* bias,
                               const float* res, float* out, int Mreal, int Mpad, int N, int act) {
    int tot4 = (Mreal*N) >> 2;
    combine_k<<<(tot4 + 255)/256, 256>>>(part, s, bias, res, out, Mreal, Mpad, N, act);
}

extern "C" void kernel_launch(void* const* d_in, const int* in_sizes, int n_in,
                              void* d_out, int out_size) {
    const float* x          = (const float*)d_in[0];
    const float* g_seed_w   = (const float*)d_in[1];
    const float* g_q_w      = (const float*)d_in[2];
    const float* g_k_w      = (const float*)d_in[3];
    const float* g_v_w      = (const float*)d_in[4];
    const float* g_mlp_w1   = (const float*)d_in[5];
    const float* g_mlp_b1   = (const float*)d_in[6];
    const float* g_mlp_w2   = (const float*)d_in[7];
    const float* g_mlp_b2   = (const float*)d_in[8];
    const float* g_ln_in_g  = (const float*)d_in[9];
    const float* g_ln_in_b  = (const float*)d_in[10];
    const float* g_ln_out_g = (const float*)d_in[11];
    const float* g_ln_out_b = (const float*)d_in[12];
    const float* g_tau      = (const float*)d_in[13];
    const float* g_rpb      = (const float*)d_in[14];
    const float* blk_ln1_g  = (const float*)d_in[15];
    const float* blk_ln1_b  = (const float*)d_in[16];
    const float* blk_qkv_w  = (const float*)d_in[17];
    const float* blk_proj_w = (const float*)d_in[18];
    const float* blk_proj_b = (const float*)d_in[19];
    const float* blk_ln2_g  = (const float*)d_in[20];
    const float* blk_ln2_b  = (const float*)d_in[21];
    const float* blk_mlp_w1 = (const float*)d_in[22];
    const float* blk_mlp_b1 = (const float*)d_in[23];
    const float* blk_mlp_w2 = (const float*)d_in[24];
    const float* blk_mlp_b2 = (const float*)d_in[25];
    float* out = (float*)d_out;

    cudaFuncSetAttribute(gemm_mma, cudaFuncAttributeMaxDynamicSharedMemorySize, GTC_SMEM);

#define SYM(v, s) cudaGetSymbolAddress((void**)&v, s)
    float *tmp0, *xout, *buf1, *buf2, *kg, *vg, *split, *attn, *colsum, *csb, *snb;
    SYM(tmp0,g_tmp0); SYM(xout,g_xout); SYM(buf1,g_buf1); SYM(buf2,g_buf2);
    SYM(kg,g_kg); SYM(vg,g_vg); SYM(split,g_split); SYM(attn,g_attn);
    SYM(colsum,g_colsum); SYM(csb,g_cos); SYM(snb,g_sin);
    bf16 *xh,*xl,*lnxh,*lnxl,*colh,*coll,*a1h,*a1l,*a2h,*a2l;
    SYM(xh,g_xh); SYM(xl,g_xl); SYM(lnxh,g_lnxh); SYM(lnxl,g_lnxl);
    SYM(colh,g_colh); SYM(coll,g_coll); SYM(a1h,g_a1h); SYM(a1l,g_a1l);
    SYM(a2h,g_a2h); SYM(a2l,g_a2l);
    bf16 *wsh,*wsl,*wqh,*wql,*wkh,*wkl,*wvh,*wvl,*m1h,*m1l,*m2h,*m2l;
    SYM(wsh,g_wsh); SYM(wsl,g_wsl); SYM(wqh,g_wqh); SYM(wql,g_wql);
    SYM(wkh,g_wkh); SYM(wkl,g_wkl); SYM(wvh,g_wvh); SYM(wvl,g_wvl);
    SYM(m1h,g_m1h); SYM(m1l,g_m1l); SYM(m2h,g_m2h); SYM(m2l,g_m2l);
    bf16 *qkvh,*qkvl,*pjh,*pjl,*bm1h,*bm1l,*bm2h,*bm2l;
    SYM(qkvh,g_qkvh); SYM(qkvl,g_qkvl); SYM(pjh,g_pjh); SYM(pjl,g_pjl);
    SYM(bm1h,g_bm1h); SYM(bm1l,g_bm1l); SYM(bm2h,g_bm2h); SYM(bm2l,g_bm2l);
#undef SYM

    // ---- weight conversions ----
    wseed_tr_hl<<<(DD*2304 + 255)/256, 256>>>(g_seed_w, wsh, wsl);
    run_cvt(g_q_w, wqh, wql, DD*DD);
    run_cvt(g_k_w, wkh, wkl, DD*DD);
    run_cvt(g_v_w, wvh, wvl, DD*DD);
    run_cvt(g_mlp_w1, m1h, m1l, 512*DD);
    run_cvt(g_mlp_w2, m2h, m2l, DD*512);
    run_cvt(blk_qkv_w, qkvh, qkvl, 2*768*DD);
    run_cvt(blk_proj_w, pjh, pjl, 2*DD*DD);
    run_cvt(blk_mlp_w1, bm1h, bm1l, 2*768*DD);
    run_cvt(blk_mlp_w2, bm2h, bm2l, 2*DD*768);

    // ---- k, v group projections (permute fused into epilogue) ----
    ln256<<<NTOKIN, 256>>>(x, g_ln_in_g, g_ln_in_b, nullptr, nullptr, lnxh, lnxl);
    run_cvt(x, xh, xl, NTOKIN*DD);
    run_tc(lnxh, lnxl, wkh, wkl, nullptr, kg, NTOKIN, NTOKIN, DD, DD, 0, 1, 1);
    run_tc(xh,   xl,   wvh, wvl, nullptr, vg, NTOKIN, NTOKIN, DD, DD, 0, 1, 1);

    // ---- seed conv via im2col + split-K tensor GEMM ----
    im2col_hl<<<(NTOK*2304 + 255)/256, 256>>>(x, colh, coll);
    run_tc(colh, coll, wsh, wsl, nullptr, split, NTOK, NTOKP, DD, 2304, 0, 0, 3);
    run_combine(split, 3, nullptr, nullptr, tmp0, NTOK, NTOKP, DD, 0);
    ln256<<<NTOK, 256>>>(tmp0, g_ln_out_g, g_ln_out_b, nullptr, xout, nullptr, nullptr);

    rope_tab<<<(NPOS*16 + 255)/256, 256>>>(csb, snb);

    // ---- 3 grouped-NA seeding iterations ----
    for (int it = 0; it < 3; it++) {
        ln256<<<NTOK, 256>>>(xout, g_ln_out_g, g_ln_out_b, nullptr, nullptr, a1h, a1l);
        run_tc(a1h, a1l, wqh, wql, nullptr, split, NTOK, NTOKP, DD, DD, 0, 0, 2);
        run_combine(split, 2, nullptr, nullptr, buf2, NTOK, NTOKP, DD, 0);
        na3_attn<<<BB*4*NPOS, 288>>>(kg, buf2, g_rpb, g_tau, attn);
        col_sum_k<<<(BB*NPOS + 255)/256, 256>>>(attn, colsum);
        na3_av<<<NTOK, 256>>>(attn, colsum, vg, xout);
        run_cvt(xout, a2h, a2l, NTOK*DD);
        run_tc(a2h, a2l, m1h, m1l, g_mlp_b1, buf1, NTOK, NTOKP, 512, DD, 1, 0, 1);
        run_cvt(buf1, a1h, a1l, NTOK*512);
        run_tc(a1h, a1l, m2h, m2l, nullptr, split, NTOK, NTOKP, DD, 512, 0, 0, 2);
        run_combine(split, 2, g_mlp_b2, nullptr, buf2, NTOK, NTOKP, DD, 0);
        ln256<<<NTOK, 256>>>(buf2, g_ln_out_g, g_ln_out_b, xout, xout, nullptr, nullptr);
    }

    // ---- 2 transformer blocks with 7x7 NA ----
    for (int l = 0; l < 2; l++) {
        ln256<<<NTOK, 256>>>(xout, blk_ln1_g + l*DD, blk_ln1_b + l*DD, nullptr, nullptr, a1h, a1l);
        run_tc(a1h, a1l, qkvh + (size_t)l*768*DD, qkvl + (size_t)l*768*DD,
               nullptr, buf2, NTOK, NTOKP, 768, DD, 0, 0, 1);
        rope_apply<<<(BB*NPOS*2*HEADS*16 + 255)/256, 256>>>(buf2, csb, snb);
        na7_k<<<BB*HEADS*NPOS, 256>>>(buf2, buf1);
        run_cvt(buf1, a1h, a1l, NTOK*DD);
        run_tc(a1h, a1l, pjh + (size_t)l*DD*DD, pjl + (size_t)l*DD*DD,
               nullptr, split, NTOK, NTOKP, DD, DD, 0, 0, 2);
        run_combine(split, 2, blk_proj_b + l*DD, xout, xout, NTOK, NTOKP, DD, 0);
        ln256<<<NTOK, 256>>>(xout, blk_ln2_g + l*DD, blk_ln2_b + l*DD, nullptr, nullptr, a1h, a1l);
        run_tc(a1h, a1l, bm1h + (size_t)l*768*DD, bm1l + (size_t)l*768*DD,
               blk_mlp_b1 + l*768, buf2, NTOK, NTOKP, 768, DD, 1, 0, 1);
        run_cvt(buf2, a1h, a1l, NTOK*768);
        run_tc(a1h, a1l, bm2h + (size_t)l*DD*768, bm2l + (size_t)l*DD*768,
               nullptr, split, NTOK, NTOKP, DD, 768, 0, 0, 2);
        run_combine(split, 2, blk_mlp_b2 + l*DD, xout, (l == 1) ? out : xout, NTOK, NTOKP, DD, 0);
    }
}

// round 6
// speedup vs baseline: 1.8165x; 1.0861x over previous
#include <cuda_runtime.h>
#include <cuda_bf16.h>
#include <math.h>
#include <stdint.h>

// ---------------- problem constants ----------------
#define BB 4
#define HI 56
#define WI 56
#define DD 256
#define HO 28
#define WO 28
#define NPOS 784
#define NTOK (BB*NPOS)     // 3136
#define NTOKP 3200         // padded to 128 multiple
#define NTOKIN (BB*HI*WI)  // 12544
#define HEADS 8
#define LN_EPS 1e-5f

typedef __nv_bfloat16 bf16;

// ---------------- scratch (device globals) ----------------
__device__ float g_xout  [NTOK*DD];
__device__ float g_buf2  [NTOK*768];
__device__ float g_kg    [BB*4*NPOS*DD];
__device__ float g_vg    [BB*4*NPOS*DD];
__device__ float g_split [3*NTOKP*DD];
__device__ float g_attn  [BB*4*NPOS*9];
__device__ float g_colsum[BB*NPOS];
__device__ float g_cos   [NPOS*16];
__device__ float g_sin   [NPOS*16];

// bf16 hi/lo operand buffers
__device__ bf16 g_xh[NTOKIN*DD],  g_xl[NTOKIN*DD];
__device__ bf16 g_lnxh[NTOKIN*DD],g_lnxl[NTOKIN*DD];
__device__ bf16 g_colh[NTOKP*2304], g_coll[NTOKP*2304];
__device__ bf16 g_a1h[NTOKP*768], g_a1l[NTOKP*768];
__device__ bf16 g_a2h[NTOKP*256], g_a2l[NTOKP*256];
// weights hi/lo
__device__ bf16 g_wsh[DD*2304], g_wsl[DD*2304];
__device__ bf16 g_wqh[DD*DD],   g_wql[DD*DD];
__device__ bf16 g_wkh[DD*DD],   g_wkl[DD*DD];
__device__ bf16 g_wvh[DD*DD],   g_wvl[DD*DD];
__device__ bf16 g_m1h[512*DD],  g_m1l[512*DD];
__device__ bf16 g_m2h[DD*512],  g_m2l[DD*512];
__device__ bf16 g_qkvh[2*768*DD], g_qkvl[2*768*DD];
__device__ bf16 g_pjh[2*DD*DD],   g_pjl[2*DD*DD];
__device__ bf16 g_bm1h[2*768*DD], g_bm1l[2*768*DD];
__device__ bf16 g_bm2h[2*DD*768], g_bm2l[2*DD*768];

// ---------------- helpers ----------------
__device__ __forceinline__ uint32_t smem_u32(const void* p) {
    uint32_t a;
    asm("{ .reg .u64 t; cvta.to.shared.u64 t, %1; cvt.u32.u64 %0, t; }" : "=r"(a) : "l"(p));
    return a;
}
__device__ __forceinline__ float gelu_exact(float x) {
    return 0.5f * x * (1.f + erff(x * 0.70710678118654752f));
}
__device__ __forceinline__ void cp16(uint32_t saddr, const void* gaddr) {
    asm volatile("cp.async.cg.shared.global [%0], [%1], 16;" :: "r"(saddr), "l"(gaddr));
}
#define CP_COMMIT() asm volatile("cp.async.commit_group;" ::: "memory")
#define CP_WAIT0()  asm volatile("cp.async.wait_group 0;" ::: "memory")

__device__ __forceinline__ void ldmx4(uint32_t addr, uint32_t* r) {
    asm volatile("ldmatrix.sync.aligned.m8n8.x4.shared.b16 {%0,%1,%2,%3}, [%4];"
        : "=r"(r[0]), "=r"(r[1]), "=r"(r[2]), "=r"(r[3]) : "r"(addr));
}
__device__ __forceinline__ void mma16816(float* d, const uint32_t* a, uint32_t b0, uint32_t b1) {
    asm volatile("mma.sync.aligned.m16n8k16.row.col.f32.bf16.bf16.f32 "
        "{%0,%1,%2,%3}, {%4,%5,%6,%7}, {%8,%9}, {%0,%1,%2,%3};"
        : "+f"(d[0]), "+f"(d[1]), "+f"(d[2]), "+f"(d[3])
        : "r"(a[0]), "r"(a[1]), "r"(a[2]), "r"(a[3]), "r"(b0), "r"(b1));
}
__device__ __forceinline__ void split_hl(float v, bf16& h, bf16& l) {
    h = __float2bfloat16(v);
    l = __float2bfloat16(v - __bfloat162float(h));
}

// ---------------- tensor-core GEMM (mma.sync bf16 hi/lo 3-pass) ----------------
#define TROW 144
#define TSZ  (128*TROW)
#define BUFSZ (4*TSZ)
#define GTC_SMEM (2*BUFSZ)

__global__ void __launch_bounds__(256, 1)
gemm_mma(const bf16* __restrict__ Ah, const bf16* __restrict__ Al,
         const bf16* __restrict__ Bh, const bf16* __restrict__ Bl,
         const float* __restrict__ bias, float* __restrict__ C,
         bf16* __restrict__ Oh, bf16* __restrict__ Ol,
         const float* __restrict__ CS, const float* __restrict__ SN,
         int Mreal, int Mpad, int N, int K, int act, int remap, int ksplit) {
    extern __shared__ char smraw[];
    uint32_t sb = smem_u32(smraw);
    int tid = threadIdx.x, wid = tid >> 5, lane = tid & 31;
    int wm = wid >> 2, wn = wid & 3;
    int bm = blockIdx.y * 128, bn = blockIdx.x * 128;
    int kper = K / ksplit;
    int kbase = blockIdx.z * kper;
    int nch = kper / 64;

    const bf16* srcs[4] = { Ah + (size_t)bm*K, Al + (size_t)bm*K,
                            Bh + (size_t)bn*K, Bl + (size_t)bn*K };

    #define LOAD_CHUNK(c, b) {                                                  \
        int k0 = kbase + (c)*64;                                                \
        uint32_t dbase = sb + (b)*BUFSZ;                                        \
        _Pragma("unroll")                                                       \
        for (int s = 0; s < 4; s++) {                                           \
            const bf16* base = srcs[s];                                         \
            uint32_t dst = dbase + s*TSZ;                                       \
            _Pragma("unroll")                                                   \
            for (int u = 0; u < 4; u++) {                                       \
                int idx = tid + u*256;                                          \
                int row = idx >> 3, seg = idx & 7;                              \
                cp16(dst + row*TROW + seg*16, base + (size_t)row*K + k0 + seg*8); \
            }                                                                   \
        }                                                                       \
        CP_COMMIT();                                                            \
    }

    float acc[4][4][4];
    #pragma unroll
    for (int i=0;i<4;i++)
        #pragma unroll
        for (int j=0;j<4;j++)
            #pragma unroll
            for (int e=0;e<4;e++) acc[i][j][e] = 0.f;

    LOAD_CHUNK(0, 0)
    int buf = 0;
    int lr16 = lane & 15, lh = lane >> 4;

    for (int c = 0; c < nch; c++) {
        CP_WAIT0();
        __syncthreads();
        if (c + 1 < nch) LOAD_CHUNK(c+1, buf^1)
        uint32_t aH = sb + buf*BUFSZ;
        uint32_t aL = aH + TSZ;
        uint32_t bH = aH + 2*TSZ;
        uint32_t bL = aH + 3*TSZ;
        #pragma unroll
        for (int kk = 0; kk < 4; kk++) {
            uint32_t ah[4][4], al[4][4], bh[2][4], bl[2][4];
            int kb = kk*32 + lh*16;
            #pragma unroll
            for (int mi = 0; mi < 4; mi++) {
                int row = wm*64 + mi*16 + lr16;
                ldmx4(aH + row*TROW + kb, ah[mi]);
                ldmx4(aL + row*TROW + kb, al[mi]);
            }
            #pragma unroll
            for (int n2 = 0; n2 < 2; n2++) {
                int row = wn*32 + n2*16 + lr16;
                ldmx4(bH + row*TROW + kb, bh[n2]);
                ldmx4(bL + row*TROW + kb, bl[n2]);
            }
            #pragma unroll
            for (int mi = 0; mi < 4; mi++) {
                #pragma unroll
                for (int nj = 0; nj < 4; nj++) {
                    int n2 = nj >> 1, sel = nj & 1;
                    mma16816(acc[mi][nj], ah[mi], bh[n2][sel], bh[n2][sel+2]);
                    mma16816(acc[mi][nj], ah[mi], bl[n2][sel], bl[n2][sel+2]);
                    mma16816(acc[mi][nj], al[mi], bh[n2][sel], bh[n2][sel+2]);
                }
            }
        }
        __syncthreads();
        buf ^= 1;
    }
    #undef LOAD_CHUNK

    // ---- epilogue ----
    int cbase = bn + wn*32 + (lane & 3)*2;
    int rbase = bm + wm*64 + (lane >> 2);
    if (ksplit > 1) {
        float* Cp = C + (size_t)blockIdx.z * Mpad * N;
        #pragma unroll
        for (int mi = 0; mi < 4; mi++) {
            #pragma unroll
            for (int half = 0; half < 2; half++) {
                int r = rbase + mi*16 + half*8;
                if (r >= Mreal) continue;
                #pragma unroll
                for (int nj = 0; nj < 4; nj++) {
                    float2 v = make_float2(acc[mi][nj][half*2], acc[mi][nj][half*2+1]);
                    *(float2*)(Cp + (size_t)r*N + cbase + nj*8) = v;
                }
            }
        }
        return;
    }
    #pragma unroll
    for (int mi = 0; mi < 4; mi++) {
        #pragma unroll
        for (int half = 0; half < 2; half++) {
            int r = rbase + mi*16 + half*8;
            if (r >= Mreal) continue;
            int orow = r;
            if (remap) {
                int b2 = r / (HI*WI); int rr = r % (HI*WI);
                int hi2 = rr / WI, wi2 = rr % WI;
                orow = (b2*4 + (hi2&1)*2 + (wi2&1))*NPOS + (hi2>>1)*WO + (wi2>>1);
            }
            #pragma unroll
            for (int nj = 0; nj < 4; nj++) {
                int col = cbase + nj*8;
                float v0 = acc[mi][nj][half*2], v1 = acc[mi][nj][half*2+1];
                if (bias) { v0 += bias[col]; v1 += bias[col+1]; }
                if (act)  { v0 = gelu_exact(v0); v1 = gelu_exact(v1); }
                if (CS && col < 512) {   // fused RoPE (q,k halves)
                    int pos = orow % NPOS;
                    int rr2 = (col & 31) >> 1;
                    float c = CS[pos*16 + rr2], s = SN[pos*16 + rr2];
                    float t0 = v0*c - v1*s;
                    v1 = v1*c + v0*s;
                    v0 = t0;
                }
                if (Oh) {
                    __nv_bfloat162 hv, lv;
                    split_hl(v0, hv.x, lv.x);
                    split_hl(v1, hv.y, lv.y);
                    *(__nv_bfloat162*)(Oh + (size_t)orow*N + col) = hv;
                    *(__nv_bfloat162*)(Ol + (size_t)orow*N + col) = lv;
                } else {
                    *(float2*)(C + (size_t)orow*N + col) = make_float2(v0, v1);
                }
            }
        }
    }
}

// ---------------- fp32 -> bf16 hi/lo converter ----------------
__global__ void cvt_hl(const float* __restrict__ in, bf16* __restrict__ hi,
                       bf16* __restrict__ lo, int n4) {
    int i = blockIdx.x*blockDim.x + threadIdx.x;
    if (i >= n4) return;
    float4 v = ((const float4*)in)[i];
    __nv_bfloat162 h0, h1, l0, l1;
    split_hl(v.x, h0.x, l0.x); split_hl(v.y, h0.y, l0.y);
    split_hl(v.z, h1.x, l1.x); split_hl(v.w, h1.y, l1.y);
    ((__nv_bfloat162*)hi)[2*i]   = h0;
    ((__nv_bfloat162*)hi)[2*i+1] = h1;
    ((__nv_bfloat162*)lo)[2*i]   = l0;
    ((__nv_bfloat162*)lo)[2*i+1] = l1;
}

// ---------------- warp-per-row LN over 256 ----------------
__global__ void ln_warp(const float* __restrict__ in, const float* __restrict__ gamma,
                        const float* __restrict__ beta, const float* __restrict__ res,
                        float* __restrict__ out, bf16* __restrict__ oh, bf16* __restrict__ ol,
                        int nrows) {
    int gw = (blockIdx.x * blockDim.x + threadIdx.x) >> 5;
    int lane = threadIdx.x & 31;
    if (gw >= nrows) return;
    const float4* row = (const float4*)(in + (size_t)gw * DD);
    float4 v0 = row[lane], v1 = row[lane + 32];
    float s = v0.x+v0.y+v0.z+v0.w + v1.x+v1.y+v1.z+v1.w;
    #pragma unroll
    for (int o=16;o;o>>=1) s += __shfl_xor_sync(0xffffffffu, s, o);
    float mean = s * (1.f/256.f);
    float d[8] = {v0.x-mean, v0.y-mean, v0.z-mean, v0.w-mean,
                  v1.x-mean, v1.y-mean, v1.z-mean, v1.w-mean};
    float sq = 0.f;
    #pragma unroll
    for (int e=0;e<8;e++) sq += d[e]*d[e];
    #pragma unroll
    for (int o=16;o;o>>=1) sq += __shfl_xor_sync(0xffffffffu, sq, o);
    float inv = rsqrtf(sq * (1.f/256.f) + LN_EPS);
    float4 g0 = ((const float4*)gamma)[lane], g1 = ((const float4*)gamma)[lane+32];
    float4 b0 = ((const float4*)beta)[lane],  b1 = ((const float4*)beta)[lane+32];
    float y[8];
    y[0]=d[0]*inv*g0.x+b0.x; y[1]=d[1]*inv*g0.y+b0.y; y[2]=d[2]*inv*g0.z+b0.z; y[3]=d[3]*inv*g0.w+b0.w;
    y[4]=d[4]*inv*g1.x+b1.x; y[5]=d[5]*inv*g1.y+b1.y; y[6]=d[6]*inv*g1.z+b1.z; y[7]=d[7]*inv*g1.w+b1.w;
    if (res) {
        const float4* rr = (const float4*)(res + (size_t)gw * DD);
        float4 r0 = rr[lane], r1 = rr[lane+32];
        y[0]+=r0.x; y[1]+=r0.y; y[2]+=r0.z; y[3]+=r0.w;
        y[4]+=r1.x; y[5]+=r1.y; y[6]+=r1.z; y[7]+=r1.w;
    }
    if (out) {
        float4* op = (float4*)(out + (size_t)gw * DD);
        op[lane]    = make_float4(y[0],y[1],y[2],y[3]);
        op[lane+32] = make_float4(y[4],y[5],y[6],y[7]);
    }
    if (oh) {
        __nv_bfloat162* hp = (__nv_bfloat162*)(oh + (size_t)gw * DD);
        __nv_bfloat162* lp = (__nv_bfloat162*)(ol + (size_t)gw * DD);
        #pragma unroll
        for (int q = 0; q < 4; q++) {
            __nv_bfloat162 hv, lv;
            split_hl(y[q*2],   hv.x, lv.x);
            split_hl(y[q*2+1], hv.y, lv.y);
            int idx = (q < 2) ? (lane*2 + q) : (64 + lane*2 + (q-2));
            hp[idx] = hv;
            lp[idx] = lv;
        }
    }
}

// ---------------- fused split-K combine (+bias) -> LN -> (+res) -> out ----------------
__global__ void combine_ln(const float* __restrict__ part, int s,
                           const float* __restrict__ bias,
                           const float* __restrict__ gamma, const float* __restrict__ beta,
                           const float* __restrict__ res, float* __restrict__ out,
                           int Mpad, int nrows) {
    int gw = (blockIdx.x * blockDim.x + threadIdx.x) >> 5;
    int lane = threadIdx.x & 31;
    if (gw >= nrows) return;
    float y[8];
    {
        const float4* p0 = (const float4*)(part + (size_t)gw * DD);
        float4 v0 = p0[lane], v1 = p0[lane+32];
        y[0]=v0.x; y[1]=v0.y; y[2]=v0.z; y[3]=v0.w;
        y[4]=v1.x; y[5]=v1.y; y[6]=v1.z; y[7]=v1.w;
        for (int z = 1; z < s; z++) {
            const float4* pz = (const float4*)(part + (size_t)z*Mpad*DD + (size_t)gw * DD);
            float4 w0 = pz[lane], w1 = pz[lane+32];
            y[0]+=w0.x; y[1]+=w0.y; y[2]+=w0.z; y[3]+=w0.w;
            y[4]+=w1.x; y[5]+=w1.y; y[6]+=w1.z; y[7]+=w1.w;
        }
    }
    if (bias) {
        float4 c0 = ((const float4*)bias)[lane], c1 = ((const float4*)bias)[lane+32];
        y[0]+=c0.x; y[1]+=c0.y; y[2]+=c0.z; y[3]+=c0.w;
        y[4]+=c1.x; y[5]+=c1.y; y[6]+=c1.z; y[7]+=c1.w;
    }
    float sm = 0.f;
    #pragma unroll
    for (int e=0;e<8;e++) sm += y[e];
    #pragma unroll
    for (int o=16;o;o>>=1) sm += __shfl_xor_sync(0xffffffffu, sm, o);
    float mean = sm * (1.f/256.f);
    float sq = 0.f;
    #pragma unroll
    for (int e=0;e<8;e++) { y[e] -= mean; sq += y[e]*y[e]; }
    #pragma unroll
    for (int o=16;o;o>>=1) sq += __shfl_xor_sync(0xffffffffu, sq, o);
    float inv = rsqrtf(sq * (1.f/256.f) + LN_EPS);
    float4 g0 = ((const float4*)gamma)[lane], g1 = ((const float4*)gamma)[lane+32];
    float4 b0 = ((const float4*)beta)[lane],  b1 = ((const float4*)beta)[lane+32];
    y[0]=y[0]*inv*g0.x+b0.x; y[1]=y[1]*inv*g0.y+b0.y; y[2]=y[2]*inv*g0.z+b0.z; y[3]=y[3]*inv*g0.w+b0.w;
    y[4]=y[4]*inv*g1.x+b1.x; y[5]=y[5]*inv*g1.y+b1.y; y[6]=y[6]*inv*g1.z+b1.z; y[7]=y[7]*inv*g1.w+b1.w;
    if (res) {
        const float4* rr = (const float4*)(res + (size_t)gw * DD);
        float4 r0 = rr[lane], r1 = rr[lane+32];
        y[0]+=r0.x; y[1]+=r0.y; y[2]+=r0.z; y[3]+=r0.w;
        y[4]+=r1.x; y[5]+=r1.y; y[6]+=r1.z; y[7]+=r1.w;
    }
    float4* op = (float4*)(out + (size_t)gw * DD);
    op[lane]    = make_float4(y[0],y[1],y[2],y[3]);
    op[lane+32] = make_float4(y[4],y[5],y[6],y[7]);
}

// ---------------- plain split-K combine with epilogue ----------------
__global__ void combine_k(const float* __restrict__ part, int s,
                          const float* __restrict__ bias, const float* __restrict__ res,
                          float* __restrict__ out, int Mreal, int Mpad, int N, int act) {
    int i4 = blockIdx.x*blockDim.x + threadIdx.x;
    int tot = (Mreal*N) >> 2;
    if (i4 >= tot) return;
    size_t zs = ((size_t)Mpad*N) >> 2;
    float4 v = ((const float4*)part)[i4];
    for (int z = 1; z < s; z++) {
        float4 w = ((const float4*)part)[i4 + z*zs];
        v.x+=w.x; v.y+=w.y; v.z+=w.z; v.w+=w.w;
    }
    int col = (i4*4) % N;
    if (bias) {
        float4 bvv = *(const float4*)(bias + col);
        v.x+=bvv.x; v.y+=bvv.y; v.z+=bvv.z; v.w+=bvv.w;
    }
    if (act) { v.x=gelu_exact(v.x); v.y=gelu_exact(v.y); v.z=gelu_exact(v.z); v.w=gelu_exact(v.w); }
    if (res) {
        float4 rr = ((const float4*)res)[i4];
        v.x+=rr.x; v.y+=rr.y; v.z+=rr.z; v.w+=rr.w;
    }
    ((float4*)out)[i4] = v;
}

// ---------------- im2col (3x3 stride2 pad1), vectorized x4, bf16 hi/lo out ----------------
__global__ void im2col_hl(const float* __restrict__ x, bf16* __restrict__ oh, bf16* __restrict__ ol) {
    int idx = blockIdx.x*blockDim.x + threadIdx.x;
    const int total = NTOK*576;           // 4 cols per thread
    if (idx >= total) return;
    int c4 = idx % 576; int row = idx / 576;
    int b = row / NPOS; int p = row % NPOS;
    int i = p / WO, j = p % WO;
    int kk = c4 >> 6; int ic = (c4 & 63) * 4;
    int kh = kk / 3, kw = kk % 3;
    int hi = 2*i - 1 + kh, wi = 2*j - 1 + kw;
    float4 v = make_float4(0.f, 0.f, 0.f, 0.f);
    if (hi >= 0 && hi < HI && wi >= 0 && wi < WI)
        v = *(const float4*)(x + ((size_t)(b*(HI*WI) + hi*WI + wi))*DD + ic);
    __nv_bfloat162 h0, h1, l0, l1;
    split_hl(v.x, h0.x, l0.x); split_hl(v.y, h0.y, l0.y);
    split_hl(v.z, h1.x, l1.x); split_hl(v.w, h1.y, l1.y);
    size_t o = (size_t)row*2304 + kk*256 + ic;
    *(__nv_bfloat162*)(oh + o)     = h0;
    *(__nv_bfloat162*)(oh + o + 2) = h1;
    *(__nv_bfloat162*)(ol + o)     = l0;
    *(__nv_bfloat162*)(ol + o + 2) = l1;
}

// seed weight (oc,ic,kh,kw) -> [oc][kk*256+ic] bf16 hi/lo
__global__ void wseed_tr_hl(const float* __restrict__ w, bf16* __restrict__ oh, bf16* __restrict__ ol) {
    int idx = blockIdx.x*blockDim.x + threadIdx.x;
    if (idx >= DD*2304) return;
    int oc = idx / 2304; int c = idx % 2304;
    int kk = c >> 8; int ic = c & 255;
    float v = w[(size_t)oc*2304 + ic*9 + kk];
    split_hl(v, oh[idx], ol[idx]);
}

// ---------------- group NA (K=3) logits + softmax ----------------
__global__ void na3_attn(const float* __restrict__ kg, const float* __restrict__ q,
                         const float* __restrict__ rpb, const float* __restrict__ tau,
                         float* __restrict__ attn) {
    int blk = blockIdx.x;
    int p = blk % NPOS; int bn = blk / NPOS; int n = bn & 3; int b = bn >> 2;
    int i = p / WO, j = p % WO;
    int t = threadIdx.x; int w = t >> 5; int lane = t & 31;
    __shared__ float logit[9];
    __shared__ float ev[9];
    int a = w / 3, c = w % 3;
    int si = min(max(i-1,0),25), sj = min(max(j-1,0),25);
    int np = (si+a)*WO + (sj+c);
    const float* kv = kg + (size_t)blk*DD;
    const float* qv = q + (size_t)(b*NPOS + np)*DD;
    float s = 0.f;
    #pragma unroll
    for (int u=0;u<8;u++) s = fmaf(kv[lane + 32*u], qv[lane + 32*u], s);
    #pragma unroll
    for (int o=16;o;o>>=1) s += __shfl_xor_sync(0xffffffffu, s, o);
    if (lane==0) logit[w] = s + rpb[n*9 + w];
    __syncthreads();
    if (t < 9) {
        float scale = expf(tau[0]);
        float m = -1e30f;
        #pragma unroll
        for (int u=0;u<9;u++) m = fmaxf(m, logit[u]*scale);
        ev[t] = expf(logit[t]*scale - m);
    }
    __syncthreads();
    if (t < 9) {
        float sum = 0.f;
        #pragma unroll
        for (int u=0;u<9;u++) sum += ev[u];
        attn[(size_t)blk*9 + t] = ev[t]/sum + 1e-6f;
    }
}

// ---------------- deterministic column scatter-sum ----------------
__device__ __forceinline__ int inv_list(int s, int* lst) {
    if (s == 0)       { lst[0]=0;  lst[1]=1;  return 2; }
    else if (s == 25) { lst[0]=26; lst[1]=27; return 2; }
    else              { lst[0]=s+1;           return 1; }
}

__global__ void col_sum_k(const float* __restrict__ attn, float* __restrict__ col) {
    int idx = blockIdx.x*blockDim.x + threadIdx.x;
    if (idx >= BB*NPOS) return;
    int t = idx % NPOS, b = idx / NPOS;
    int ti = t / WO, tj = t % WO;
    float acc = 0.f;
    for (int a=0;a<3;a++) {
        int sr = ti - a; if (sr < 0 || sr > 25) continue;
        int il[2]; int ic = inv_list(sr, il);
        for (int c=0;c<3;c++) {
            int sc = tj - c; if (sc < 0 || sc > 25) continue;
            int jl[2]; int jc = inv_list(sc, jl);
            for (int ii=0; ii<ic; ii++)
                for (int jj=0; jj<jc; jj++) {
                    int pp = il[ii]*WO + jl[jj];
                    #pragma unroll
                    for (int n=0;n<4;n++)
                        acc += attn[((size_t)(b*4+n)*NPOS + pp)*9 + a*3 + c];
                }
        }
    }
    col[idx] = acc;
}

// ---------------- group NA AV + in-place residual + hi/lo out ----------------
__global__ void na3_av(const float* __restrict__ attn, const float* __restrict__ col,
                       const float* __restrict__ vg, float* __restrict__ xout,
                       bf16* __restrict__ oh, bf16* __restrict__ ol) {
    int blk = blockIdx.x;
    int p = blk % NPOS, b = blk / NPOS;
    int i = p / WO, j = p % WO;
    int t = threadIdx.x;
    __shared__ float wgt[4][9];
    __shared__ int npos[9];
    if (t < 9) {
        int a = t/3, c = t%3;
        int ni = min(max(i-1,0),25)+a, nj = min(max(j-1,0),25)+c;
        npos[t] = ni*WO + nj;
    }
    __syncthreads();
    if (t < 36) {
        int n = t/9, ac = t%9;
        float av = attn[((size_t)(b*4+n)*NPOS + p)*9 + ac];
        wgt[n][ac] = av / (col[b*NPOS + npos[ac]] + 1e-8f);
    }
    __syncthreads();
    float acc = xout[(size_t)blk*DD + t];
    #pragma unroll
    for (int n=0;n<4;n++) {
        const float* vb = vg + (size_t)(b*4+n)*NPOS*DD;
        #pragma unroll
        for (int ac=0;ac<9;ac++)
            acc = fmaf(wgt[n][ac], vb[(size_t)npos[ac]*DD + t], acc);
    }
    xout[(size_t)blk*DD + t] = acc;
    split_hl(acc, oh[(size_t)blk*DD + t], ol[(size_t)blk*DD + t]);
}

// ---------------- RoPE table ----------------
__global__ void rope_tab(float* __restrict__ cs, float* __restrict__ sn) {
    int idx = blockIdx.x*blockDim.x + threadIdx.x;
    if (idx >= NPOS*16) return;
    int pos = idx / 16, r = idx % 16;
    float f = expf(-((float)(2*r) / 32.f) * 9.210340371976184f);
    float ang = (float)pos * f;
    cs[idx] = cosf(ang);
    sn[idx] = sinf(ang);
}

// ---------------- block NA (K=7, HD=32), hi/lo out ----------------
__global__ void na7_k(const float* __restrict__ qkv, bf16* __restrict__ oh, bf16* __restrict__ ol) {
    int blk = blockIdx.x;
    int p = blk % NPOS; int bh = blk / NPOS; int h = bh & 7; int b = bh >> 3;
    int i = p / WO, j = p % WO;
    int t = threadIdx.x; int w = t >> 5; int lane = t & 31;
    __shared__ float qs[32];
    __shared__ float logit[49];
    __shared__ float prob[49];
    __shared__ int   kpos[49];
    __shared__ float part[8][32];
    __shared__ float red[2];
    size_t rowbase = (size_t)(b*NPOS + p)*768;
    if (t < 32) qs[t] = qkv[rowbase + h*32 + t];
    int si = min(max(i-3,0),21), sj = min(max(j-3,0),21);
    __syncthreads();
    for (int nb = w; nb < 49; nb += 8) {
        int a = nb / 7, c = nb % 7;
        int kp = (si+a)*WO + (sj+c);
        const float* kptr = qkv + (size_t)(b*NPOS + kp)*768 + 256 + h*32;
        float s = qs[lane] * kptr[lane];
        #pragma unroll
        for (int o=16;o;o>>=1) s += __shfl_xor_sync(0xffffffffu, s, o);
        if (lane==0) { logit[nb] = s * 0.17677669529663687f; kpos[nb] = kp; }
    }
    __syncthreads();
    if (t == 0) {
        float m = -1e30f;
        #pragma unroll
        for (int u=0;u<49;u++) m = fmaxf(m, logit[u]);
        red[0] = m;
    }
    __syncthreads();
    if (t < 49) prob[t] = expf(logit[t] - red[0]);
    __syncthreads();
    if (t == 0) {
        float s = 0.f;
        #pragma unroll
        for (int u=0;u<49;u++) s += prob[u];
        red[1] = s;
    }
    __syncthreads();
    float inv = 1.f / red[1];
    float acc = 0.f;
    for (int nb = w; nb < 49; nb += 8) {
        const float* vptr = qkv + (size_t)(b*NPOS + kpos[nb])*768 + 512 + h*32;
        acc = fmaf(prob[nb]*inv, vptr[lane], acc);
    }
    part[w][lane] = acc;
    __syncthreads();
    if (w == 0) {
        float s = 0.f;
        #pragma unroll
        for (int u=0;u<8;u++) s += part[u][lane];
        size_t o = (size_t)(b*NPOS + p)*DD + h*32 + lane;
        split_hl(s, oh[o], ol[o]);
    }
}

// ---------------- host helpers ----------------
static inline void run_tc(const bf16* Ah, const bf16* Al, const bf16* Bh, const bf16* Bl,
                          const float* bias, float* C, bf16* Oh, bf16* Ol,
                          const float* cs, const float* sn,
                          int Mreal, int Mpad, int N, int K, int act, int remap, int ks) {
    dim3 grid(N/128, Mpad/128, ks);
    gemm_mma<<<grid, 256, GTC_SMEM>>>(Ah, Al, Bh, Bl, bias, C, Oh, Ol, cs, sn,
                                      Mreal, Mpad, N, K, act, remap, ks);
}
static inline void run_cvt(const float* in, bf16* hi, bf16* lo, int n) {
    int n4 = n >> 2;
    cvt_hl<<<(n4 + 255)/256, 256>>>(in, hi, lo, n4);
}
static inline void run_ln(const float* in, const float* g, const float* b, const float* res,
                          float* out, bf16* oh, bf16* ol, int nrows) {
    ln_warp<<<(nrows + 7)/8, 256>>>(in, g, b, res, out, oh, ol, nrows);
}
static inline void run_combine(const float* part, int s, const float* bias,
                               const float* res, float* out, int Mreal, int Mpad, int N, int act) {
    int tot4 = (Mreal*N) >> 2;
    combine_k<<<(tot4 + 255)/256, 256>>>(part, s, bias, res, out, Mreal, Mpad, N, act);
}

extern "C" void kernel_launch(void* const* d_in, const int* in_sizes, int n_in,
                              void* d_out, int out_size) {
    const float* x          = (const float*)d_in[0];
    const float* g_seed_w   = (const float*)d_in[1];
    const float* g_q_w      = (const float*)d_in[2];
    const float* g_k_w      = (const float*)d_in[3];
    const float* g_v_w      = (const float*)d_in[4];
    const float* g_mlp_w1   = (const float*)d_in[5];
    const float* g_mlp_b1   = (const float*)d_in[6];
    const float* g_mlp_w2   = (const float*)d_in[7];
    const float* g_mlp_b2   = (const float*)d_in[8];
    const float* g_ln_in_g  = (const float*)d_in[9];
    const float* g_ln_in_b  = (const float*)d_in[10];
    const float* g_ln_out_g = (const float*)d_in[11];
    const float* g_ln_out_b = (const float*)d_in[12];
    const float* g_tau      = (const float*)d_in[13];
    const float* g_rpb      = (const float*)d_in[14];
    const float* blk_ln1_g  = (const float*)d_in[15];
    const float* blk_ln1_b  = (const float*)d_in[16];
    const float* blk_qkv_w  = (const float*)d_in[17];
    const float* blk_proj_w = (const float*)d_in[18];
    const float* blk_proj_b = (const float*)d_in[19];
    const float* blk_ln2_g  = (const float*)d_in[20];
    const float* blk_ln2_b  = (const float*)d_in[21];
    const float* blk_mlp_w1 = (const float*)d_in[22];
    const float* blk_mlp_b1 = (const float*)d_in[23];
    const float* blk_mlp_w2 = (const float*)d_in[24];
    const float* blk_mlp_b2 = (const float*)d_in[25];
    float* out = (float*)d_out;

    cudaFuncSetAttribute(gemm_mma, cudaFuncAttributeMaxDynamicSharedMemorySize, GTC_SMEM);

#define SYM(v, s) cudaGetSymbolAddress((void**)&v, s)
    float *xout, *buf2, *kg, *vg, *split, *attn, *colsum, *csb, *snb;
    SYM(xout,g_xout); SYM(buf2,g_buf2);
    SYM(kg,g_kg); SYM(vg,g_vg); SYM(split,g_split); SYM(attn,g_attn);
    SYM(colsum,g_colsum); SYM(csb,g_cos); SYM(snb,g_sin);
    bf16 *xh,*xl,*lnxh,*lnxl,*colh,*coll,*a1h,*a1l,*a2h,*a2l;
    SYM(xh,g_xh); SYM(xl,g_xl); SYM(lnxh,g_lnxh); SYM(lnxl,g_lnxl);
    SYM(colh,g_colh); SYM(coll,g_coll); SYM(a1h,g_a1h); SYM(a1l,g_a1l);
    SYM(a2h,g_a2h); SYM(a2l,g_a2l);
    bf16 *wsh,*wsl,*wqh,*wql,*wkh,*wkl,*wvh,*wvl,*m1h,*m1l,*m2h,*m2l;
    SYM(wsh,g_wsh); SYM(wsl,g_wsl); SYM(wqh,g_wqh); SYM(wql,g_wql);
    SYM(wkh,g_wkh); SYM(wkl,g_wkl); SYM(wvh,g_wvh); SYM(wvl,g_wvl);
    SYM(m1h,g_m1h); SYM(m1l,g_m1l); SYM(m2h,g_m2h); SYM(m2l,g_m2l);
    bf16 *qkvh,*qkvl,*pjh,*pjl,*bm1h,*bm1l,*bm2h,*bm2l;
    SYM(qkvh,g_qkvh); SYM(qkvl,g_qkvl); SYM(pjh,g_pjh); SYM(pjl,g_pjl);
    SYM(bm1h,g_bm1h); SYM(bm1l,g_bm1l); SYM(bm2h,g_bm2h); SYM(bm2l,g_bm2l);
#undef SYM

    // ---- weight conversions ----
    wseed_tr_hl<<<(DD*2304 + 255)/256, 256>>>(g_seed_w, wsh, wsl);
    run_cvt(g_q_w, wqh, wql, DD*DD);
    run_cvt(g_k_w, wkh, wkl, DD*DD);
    run_cvt(g_v_w, wvh, wvl, DD*DD);
    run_cvt(g_mlp_w1, m1h, m1l, 512*DD);
    run_cvt(g_mlp_w2, m2h, m2l, DD*512);
    run_cvt(blk_qkv_w, qkvh, qkvl, 2*768*DD);
    run_cvt(blk_proj_w, pjh, pjl, 2*DD*DD);
    run_cvt(blk_mlp_w1, bm1h, bm1l, 2*768*DD);
    run_cvt(blk_mlp_w2, bm2h, bm2l, 2*DD*768);

    // ---- k, v group projections (permute fused into epilogue) ----
    run_ln(x, g_ln_in_g, g_ln_in_b, nullptr, nullptr, lnxh, lnxl, NTOKIN);
    run_cvt(x, xh, xl, NTOKIN*DD);
    run_tc(lnxh, lnxl, wkh, wkl, nullptr, kg, nullptr, nullptr, nullptr, nullptr,
           NTOKIN, NTOKIN, DD, DD, 0, 1, 1);
    run_tc(xh,   xl,   wvh, wvl, nullptr, vg, nullptr, nullptr, nullptr, nullptr,
           NTOKIN, NTOKIN, DD, DD, 0, 1, 1);

    // ---- seed conv via im2col + split-K tensor GEMM + fused combine/LN ----
    im2col_hl<<<(NTOK*576 + 255)/256, 256>>>(x, colh, coll);
    run_tc(colh, coll, wsh, wsl, nullptr, split, nullptr, nullptr, nullptr, nullptr,
           NTOK, NTOKP, DD, 2304, 0, 0, 3);
    combine_ln<<<(NTOK + 7)/8, 256>>>(split, 3, nullptr, g_ln_out_g, g_ln_out_b,
                                      nullptr, xout, NTOKP, NTOK);

    rope_tab<<<(NPOS*16 + 255)/256, 256>>>(csb, snb);

    // ---- 3 grouped-NA seeding iterations ----
    for (int it = 0; it < 3; it++) {
        run_ln(xout, g_ln_out_g, g_ln_out_b, nullptr, nullptr, a2h, a2l, NTOK);
        run_tc(a2h, a2l, wqh, wql, nullptr, split, nullptr, nullptr, nullptr, nullptr,
               NTOK, NTOKP, DD, DD, 0, 0, 2);
        run_combine(split, 2, nullptr, nullptr, buf2, NTOK, NTOKP, DD, 0);
        na3_attn<<<BB*4*NPOS, 288>>>(kg, buf2, g_rpb, g_tau, attn);
        col_sum_k<<<(BB*NPOS + 255)/256, 256>>>(attn, colsum);
        na3_av<<<NTOK, 256>>>(attn, colsum, vg, xout, a2h, a2l);
        run_tc(a2h, a2l, m1h, m1l, g_mlp_b1, nullptr, a1h, a1l, nullptr, nullptr,
               NTOK, NTOKP, 512, DD, 1, 0, 1);
        run_tc(a1h, a1l, m2h, m2l, nullptr, split, nullptr, nullptr, nullptr, nullptr,
               NTOK, NTOKP, DD, 512, 0, 0, 2);
        combine_ln<<<(NTOK + 7)/8, 256>>>(split, 2, g_mlp_b2, g_ln_out_g, g_ln_out_b,
                                          xout, xout, NTOKP, NTOK);
    }

    // ---- 2 transformer blocks with 7x7 NA ----
    for (int l = 0; l < 2; l++) {
        run_ln(xout, blk_ln1_g + l*DD, blk_ln1_b + l*DD, nullptr, nullptr, a2h, a2l, NTOK);
        run_tc(a2h, a2l, qkvh + (size_t)l*768*DD, qkvl + (size_t)l*768*DD,
               nullptr, buf2, nullptr, nullptr, csb, snb,
               NTOK, NTOKP, 768, DD, 0, 0, 1);
        na7_k<<<BB*HEADS*NPOS, 256>>>(buf2, a2h, a2l);
        run_tc(a2h, a2l, pjh + (size_t)l*DD*DD, pjl + (size_t)l*DD*DD,
               nullptr, split, nullptr, nullptr, nullptr, nullptr,
               NTOK, NTOKP, DD, DD, 0, 0, 2);
        run_combine(split, 2, blk_proj_b + l*DD, xout, xout, NTOK, NTOKP, DD, 0);
        run_ln(xout, blk_ln2_g + l*DD, blk_ln2_b + l*DD, nullptr, nullptr, a2h, a2l, NTOK);
        run_tc(a2h, a2l, bm1h + (size_t)l*768*DD, bm1l + (size_t)l*768*DD,
               blk_mlp_b1 + l*768, nullptr, a1h, a1l, nullptr, nullptr,
               NTOK, NTOKP, 768, DD, 1, 0, 1);
        run_tc(a1h, a1l, bm2h + (size_t)l*DD*768, bm2l + (size_t)l*DD*768,
               nullptr, split, nullptr, nullptr, nullptr, nullptr,
               NTOK, NTOKP, DD, 768, 0, 0, 2);
        run_combine(split, 2, blk_mlp_b2 + l*DD, xout, (l == 1) ? out : xout, NTOK, NTOKP, DD, 0);
    }
}

// round 8
// speedup vs baseline: 1.9232x; 1.0588x over previous
#include <cuda_runtime.h>
#include <cuda_bf16.h>
#include <math.h>
#include <stdint.h>

// ---------------- problem constants ----------------
#define BB 4
#define HI 56
#define WI 56
#define DD 256
#define HO 28
#define WO 28
#define NPOS 784
#define NTOK (BB*NPOS)     // 3136
#define NTOKP 3200
#define NTOKIN (BB*HI*WI)  // 12544
#define HEADS 8
#define LN_EPS 1e-5f

typedef __nv_bfloat16 bf16;

// ---------------- scratch (device globals) ----------------
__device__ float g_xout  [NTOK*DD];
__device__ float g_buf2  [NTOK*768];
__device__ float g_kg    [BB*4*NPOS*DD];
__device__ float g_vg    [BB*4*NPOS*DD];
__device__ float g_split [3*NTOKP*DD];
__device__ float g_attn  [BB*4*NPOS*9];
__device__ float g_colsum[BB*NPOS];
__device__ float g_cos   [NPOS*16];
__device__ float g_sin   [NPOS*16];

__device__ bf16 g_xh[NTOKIN*DD],  g_xl[NTOKIN*DD];
__device__ bf16 g_lnxh[NTOKIN*DD],g_lnxl[NTOKIN*DD];
__device__ bf16 g_colh[NTOKP*2304], g_coll[NTOKP*2304];
__device__ bf16 g_a1h[NTOKP*768], g_a1l[NTOKP*768];
__device__ bf16 g_a2h[NTOKP*256], g_a2l[NTOKP*256];
__device__ bf16 g_wsh[DD*2304], g_wsl[DD*2304];
__device__ bf16 g_wqh[DD*DD],   g_wql[DD*DD];
__device__ bf16 g_wkh[DD*DD],   g_wkl[DD*DD];
__device__ bf16 g_wvh[DD*DD],   g_wvl[DD*DD];
__device__ bf16 g_m1h[512*DD],  g_m1l[512*DD];
__device__ bf16 g_m2h[DD*512],  g_m2l[DD*512];
__device__ bf16 g_qkvh[2*768*DD], g_qkvl[2*768*DD];
__device__ bf16 g_pjh[2*DD*DD],   g_pjl[2*DD*DD];
__device__ bf16 g_bm1h[2*768*DD], g_bm1l[2*768*DD];
__device__ bf16 g_bm2h[2*DD*768], g_bm2l[2*DD*768];

// ---------------- helpers ----------------
__device__ __forceinline__ uint32_t smem_u32(const void* p) {
    uint32_t a;
    asm("{ .reg .u64 t; cvta.to.shared.u64 t, %1; cvt.u32.u64 %0, t; }" : "=r"(a) : "l"(p));
    return a;
}
__device__ __forceinline__ float gelu_exact(float x) {
    return 0.5f * x * (1.f + erff(x * 0.70710678118654752f));
}
__device__ __forceinline__ void cp16(uint32_t saddr, const void* gaddr) {
    asm volatile("cp.async.cg.shared.global [%0], [%1], 16;" :: "r"(saddr), "l"(gaddr));
}
#define CP_COMMIT() asm volatile("cp.async.commit_group;" ::: "memory")
#define CP_WAIT0()  asm volatile("cp.async.wait_group 0;" ::: "memory")

__device__ __forceinline__ void ldmx4(uint32_t addr, uint32_t* r) {
    asm volatile("ldmatrix.sync.aligned.m8n8.x4.shared.b16 {%0,%1,%2,%3}, [%4];"
        : "=r"(r[0]), "=r"(r[1]), "=r"(r[2]), "=r"(r[3]) : "r"(addr));
}
__device__ __forceinline__ void mma16816(float* d, const uint32_t* a, uint32_t b0, uint32_t b1) {
    asm volatile("mma.sync.aligned.m16n8k16.row.col.f32.bf16.bf16.f32 "
        "{%0,%1,%2,%3}, {%4,%5,%6,%7}, {%8,%9}, {%0,%1,%2,%3};"
        : "+f"(d[0]), "+f"(d[1]), "+f"(d[2]), "+f"(d[3])
        : "r"(a[0]), "r"(a[1]), "r"(a[2]), "r"(a[3]), "r"(b0), "r"(b1));
}
__device__ __forceinline__ void split_hl(float v, bf16& h, bf16& l) {
    h = __float2bfloat16(v);
    l = __float2bfloat16(v - __bfloat162float(h));
}

// ---------------- tensor-core GEMM (mma.sync bf16 hi/lo 3-pass) ----------------
#define TROW 144
#define TSZ  (128*TROW)
#define BUFSZ (4*TSZ)
#define GTC_SMEM (2*BUFSZ)

__global__ void __launch_bounds__(256, 1)
gemm_mma(const bf16* __restrict__ Ah, const bf16* __restrict__ Al,
         const bf16* __restrict__ Bh, const bf16* __restrict__ Bl,
         const float* __restrict__ bias, float* __restrict__ C,
         bf16* __restrict__ Oh, bf16* __restrict__ Ol,
         const float* __restrict__ CS, const float* __restrict__ SN,
         int Mreal, int Mpad, int N, int K, int act, int remap, int ksplit) {
    extern __shared__ char smraw[];
    uint32_t sb = smem_u32(smraw);
    int tid = threadIdx.x, wid = tid >> 5, lane = tid & 31;
    int wm = wid >> 2, wn = wid & 3;
    int bm = blockIdx.y * 128, bn = blockIdx.x * 128;
    int kper = K / ksplit;
    int kbase = blockIdx.z * kper;
    int nch = kper / 64;

    const bf16* srcs[4] = { Ah + (size_t)bm*K, Al + (size_t)bm*K,
                            Bh + (size_t)bn*K, Bl + (size_t)bn*K };

    #define LOAD_CHUNK(c, b) {                                                  \
        int k0 = kbase + (c)*64;                                                \
        uint32_t dbase = sb + (b)*BUFSZ;                                        \
        _Pragma("unroll")                                                       \
        for (int s = 0; s < 4; s++) {                                           \
            const bf16* base = srcs[s];                                         \
            uint32_t dst = dbase + s*TSZ;                                       \
            _Pragma("unroll")                                                   \
            for (int u = 0; u < 4; u++) {                                       \
                int idx = tid + u*256;                                          \
                int row = idx >> 3, seg = idx & 7;                              \
                cp16(dst + row*TROW + seg*16, base + (size_t)row*K + k0 + seg*8); \
            }                                                                   \
        }                                                                       \
        CP_COMMIT();                                                            \
    }

    float acc[4][4][4];
    #pragma unroll
    for (int i=0;i<4;i++)
        #pragma unroll
        for (int j=0;j<4;j++)
            #pragma unroll
            for (int e=0;e<4;e++) acc[i][j][e] = 0.f;

    LOAD_CHUNK(0, 0)
    int buf = 0;
    int lr16 = lane & 15, lh = lane >> 4;

    for (int c = 0; c < nch; c++) {
        CP_WAIT0();
        __syncthreads();
        if (c + 1 < nch) LOAD_CHUNK(c+1, buf^1)
        uint32_t aH = sb + buf*BUFSZ;
        uint32_t aL = aH + TSZ;
        uint32_t bH = aH + 2*TSZ;
        uint32_t bL = aH + 3*TSZ;
        #pragma unroll
        for (int kk = 0; kk < 4; kk++) {
            uint32_t ah[4][4], al[4][4], bh[2][4], bl[2][4];
            int kb = kk*32 + lh*16;
            #pragma unroll
            for (int mi = 0; mi < 4; mi++) {
                int row = wm*64 + mi*16 + lr16;
                ldmx4(aH + row*TROW + kb, ah[mi]);
                ldmx4(aL + row*TROW + kb, al[mi]);
            }
            #pragma unroll
            for (int n2 = 0; n2 < 2; n2++) {
                int row = wn*32 + n2*16 + lr16;
                ldmx4(bH + row*TROW + kb, bh[n2]);
                ldmx4(bL + row*TROW + kb, bl[n2]);
            }
            #pragma unroll
            for (int mi = 0; mi < 4; mi++) {
                #pragma unroll
                for (int nj = 0; nj < 4; nj++) {
                    int n2 = nj >> 1, sel = nj & 1;
                    mma16816(acc[mi][nj], ah[mi], bh[n2][sel], bh[n2][sel+2]);
                    mma16816(acc[mi][nj], ah[mi], bl[n2][sel], bl[n2][sel+2]);
                    mma16816(acc[mi][nj], al[mi], bh[n2][sel], bh[n2][sel+2]);
                }
            }
        }
        __syncthreads();
        buf ^= 1;
    }
    #undef LOAD_CHUNK

    int cbase = bn + wn*32 + (lane & 3)*2;
    int rbase = bm + wm*64 + (lane >> 2);
    if (ksplit > 1) {
        float* Cp = C + (size_t)blockIdx.z * Mpad * N;
        #pragma unroll
        for (int mi = 0; mi < 4; mi++) {
            #pragma unroll
            for (int half = 0; half < 2; half++) {
                int r = rbase + mi*16 + half*8;
                if (r >= Mreal) continue;
                #pragma unroll
                for (int nj = 0; nj < 4; nj++) {
                    float2 v = make_float2(acc[mi][nj][half*2], acc[mi][nj][half*2+1]);
                    *(float2*)(Cp + (size_t)r*N + cbase + nj*8) = v;
                }
            }
        }
        return;
    }
    #pragma unroll
    for (int mi = 0; mi < 4; mi++) {
        #pragma unroll
        for (int half = 0; half < 2; half++) {
            int r = rbase + mi*16 + half*8;
            if (r >= Mreal) continue;
            int orow = r;
            if (remap) {
                int b2 = r / (HI*WI); int rr = r % (HI*WI);
                int hi2 = rr / WI, wi2 = rr % WI;
                orow = (b2*4 + (hi2&1)*2 + (wi2&1))*NPOS + (hi2>>1)*WO + (wi2>>1);
            }
            #pragma unroll
            for (int nj = 0; nj < 4; nj++) {
                int col = cbase + nj*8;
                float v0 = acc[mi][nj][half*2], v1 = acc[mi][nj][half*2+1];
                if (bias) { v0 += bias[col]; v1 += bias[col+1]; }
                if (act)  { v0 = gelu_exact(v0); v1 = gelu_exact(v1); }
                if (CS && col < 512) {
                    int pos = orow % NPOS;
                    int rr2 = (col & 31) >> 1;
                    float c = CS[pos*16 + rr2], s = SN[pos*16 + rr2];
                    float t0 = v0*c - v1*s;
                    v1 = v1*c + v0*s;
                    v0 = t0;
                }
                if (Oh) {
                    __nv_bfloat162 hv, lv;
                    split_hl(v0, hv.x, lv.x);
                    split_hl(v1, hv.y, lv.y);
                    *(__nv_bfloat162*)(Oh + (size_t)orow*N + col) = hv;
                    *(__nv_bfloat162*)(Ol + (size_t)orow*N + col) = lv;
                } else {
                    *(float2*)(C + (size_t)orow*N + col) = make_float2(v0, v1);
                }
            }
        }
    }
}

// ---------------- fp32 -> bf16 hi/lo converter ----------------
__global__ void cvt_hl(const float* __restrict__ in, bf16* __restrict__ hi,
                       bf16* __restrict__ lo, int n4) {
    int i = blockIdx.x*blockDim.x + threadIdx.x;
    if (i >= n4) return;
    float4 v = ((const float4*)in)[i];
    __nv_bfloat162 h0, h1, l0, l1;
    split_hl(v.x, h0.x, l0.x); split_hl(v.y, h0.y, l0.y);
    split_hl(v.z, h1.x, l1.x); split_hl(v.w, h1.y, l1.y);
    ((__nv_bfloat162*)hi)[2*i]   = h0;
    ((__nv_bfloat162*)hi)[2*i+1] = h1;
    ((__nv_bfloat162*)lo)[2*i]   = l0;
    ((__nv_bfloat162*)lo)[2*i+1] = l1;
}

// ---------------- warp-per-row LN over 256 ----------------
__global__ void ln_warp(const float* __restrict__ in, const float* __restrict__ gamma,
                        const float* __restrict__ beta, const float* __restrict__ res,
                        float* __restrict__ out, bf16* __restrict__ oh, bf16* __restrict__ ol,
                        int nrows) {
    int gw = (blockIdx.x * blockDim.x + threadIdx.x) >> 5;
    int lane = threadIdx.x & 31;
    if (gw >= nrows) return;
    const float4* row = (const float4*)(in + (size_t)gw * DD);
    float4 v0 = row[lane], v1 = row[lane + 32];
    float s = v0.x+v0.y+v0.z+v0.w + v1.x+v1.y+v1.z+v1.w;
    #pragma unroll
    for (int o=16;o;o>>=1) s += __shfl_xor_sync(0xffffffffu, s, o);
    float mean = s * (1.f/256.f);
    float d[8] = {v0.x-mean, v0.y-mean, v0.z-mean, v0.w-mean,
                  v1.x-mean, v1.y-mean, v1.z-mean, v1.w-mean};
    float sq = 0.f;
    #pragma unroll
    for (int e=0;e<8;e++) sq += d[e]*d[e];
    #pragma unroll
    for (int o=16;o;o>>=1) sq += __shfl_xor_sync(0xffffffffu, sq, o);
    float inv = rsqrtf(sq * (1.f/256.f) + LN_EPS);
    float4 g0 = ((const float4*)gamma)[lane], g1 = ((const float4*)gamma)[lane+32];
    float4 b0 = ((const float4*)beta)[lane],  b1 = ((const float4*)beta)[lane+32];
    float y[8];
    y[0]=d[0]*inv*g0.x+b0.x; y[1]=d[1]*inv*g0.y+b0.y; y[2]=d[2]*inv*g0.z+b0.z; y[3]=d[3]*inv*g0.w+b0.w;
    y[4]=d[4]*inv*g1.x+b1.x; y[5]=d[5]*inv*g1.y+b1.y; y[6]=d[6]*inv*g1.z+b1.z; y[7]=d[7]*inv*g1.w+b1.w;
    if (res) {
        const float4* rr = (const float4*)(res + (size_t)gw * DD);
        float4 r0 = rr[lane], r1 = rr[lane+32];
        y[0]+=r0.x; y[1]+=r0.y; y[2]+=r0.z; y[3]+=r0.w;
        y[4]+=r1.x; y[5]+=r1.y; y[6]+=r1.z; y[7]+=r1.w;
    }
    if (out) {
        float4* op = (float4*)(out + (size_t)gw * DD);
        op[lane]    = make_float4(y[0],y[1],y[2],y[3]);
        op[lane+32] = make_float4(y[4],y[5],y[6],y[7]);
    }
    if (oh) {
        __nv_bfloat162* hp = (__nv_bfloat162*)(oh + (size_t)gw * DD);
        __nv_bfloat162* lp = (__nv_bfloat162*)(ol + (size_t)gw * DD);
        #pragma unroll
        for (int q = 0; q < 4; q++) {
            __nv_bfloat162 hv, lv;
            split_hl(y[q*2],   hv.x, lv.x);
            split_hl(y[q*2+1], hv.y, lv.y);
            int idx = (q < 2) ? (lane*2 + q) : (64 + lane*2 + (q-2));
            hp[idx] = hv;
            lp[idx] = lv;
        }
    }
}

// ---------------- fused split-K combine (+bias) -> LN -> (+res) -> out ----------------
__global__ void combine_ln(const float* __restrict__ part, int s,
                           const float* __restrict__ bias,
                           const float* __restrict__ gamma, const float* __restrict__ beta,
                           const float* __restrict__ res, float* __restrict__ out,
                           int Mpad, int nrows) {
    int gw = (blockIdx.x * blockDim.x + threadIdx.x) >> 5;
    int lane = threadIdx.x & 31;
    if (gw >= nrows) return;
    float y[8];
    {
        const float4* p0 = (const float4*)(part + (size_t)gw * DD);
        float4 v0 = p0[lane], v1 = p0[lane+32];
        y[0]=v0.x; y[1]=v0.y; y[2]=v0.z; y[3]=v0.w;
        y[4]=v1.x; y[5]=v1.y; y[6]=v1.z; y[7]=v1.w;
        for (int z = 1; z < s; z++) {
            const float4* pz = (const float4*)(part + (size_t)z*Mpad*DD + (size_t)gw * DD);
            float4 w0 = pz[lane], w1 = pz[lane+32];
            y[0]+=w0.x; y[1]+=w0.y; y[2]+=w0.z; y[3]+=w0.w;
            y[4]+=w1.x; y[5]+=w1.y; y[6]+=w1.z; y[7]+=w1.w;
        }
    }
    if (bias) {
        float4 c0 = ((const float4*)bias)[lane], c1 = ((const float4*)bias)[lane+32];
        y[0]+=c0.x; y[1]+=c0.y; y[2]+=c0.z; y[3]+=c0.w;
        y[4]+=c1.x; y[5]+=c1.y; y[6]+=c1.z; y[7]+=c1.w;
    }
    float sm = 0.f;
    #pragma unroll
    for (int e=0;e<8;e++) sm += y[e];
    #pragma unroll
    for (int o=16;o;o>>=1) sm += __shfl_xor_sync(0xffffffffu, sm, o);
    float mean = sm * (1.f/256.f);
    float sq = 0.f;
    #pragma unroll
    for (int e=0;e<8;e++) { y[e] -= mean; sq += y[e]*y[e]; }
    #pragma unroll
    for (int o=16;o;o>>=1) sq += __shfl_xor_sync(0xffffffffu, sq, o);
    float inv = rsqrtf(sq * (1.f/256.f) + LN_EPS);
    float4 g0 = ((const float4*)gamma)[lane], g1 = ((const float4*)gamma)[lane+32];
    float4 b0 = ((const float4*)beta)[lane],  b1 = ((const float4*)beta)[lane+32];
    y[0]=y[0]*inv*g0.x+b0.x; y[1]=y[1]*inv*g0.y+b0.y; y[2]=y[2]*inv*g0.z+b0.z; y[3]=y[3]*inv*g0.w+b0.w;
    y[4]=y[4]*inv*g1.x+b1.x; y[5]=y[5]*inv*g1.y+b1.y; y[6]=y[6]*inv*g1.z+b1.z; y[7]=y[7]*inv*g1.w+b1.w;
    if (res) {
        const float4* rr = (const float4*)(res + (size_t)gw * DD);
        float4 r0 = rr[lane], r1 = rr[lane+32];
        y[0]+=r0.x; y[1]+=r0.y; y[2]+=r0.z; y[3]+=r0.w;
        y[4]+=r1.x; y[5]+=r1.y; y[6]+=r1.z; y[7]+=r1.w;
    }
    float4* op = (float4*)(out + (size_t)gw * DD);
    op[lane]    = make_float4(y[0],y[1],y[2],y[3]);
    op[lane+32] = make_float4(y[4],y[5],y[6],y[7]);
}

// ---------------- plain split-K combine with epilogue ----------------
__global__ void combine_k(const float* __restrict__ part, int s,
                          const float* __restrict__ bias, const float* __restrict__ res,
                          float* __restrict__ out, int Mreal, int Mpad, int N, int act) {
    int i4 = blockIdx.x*blockDim.x + threadIdx.x;
    int tot = (Mreal*N) >> 2;
    if (i4 >= tot) return;
    size_t zs = ((size_t)Mpad*N) >> 2;
    float4 v = ((const float4*)part)[i4];
    for (int z = 1; z < s; z++) {
        float4 w = ((const float4*)part)[i4 + z*zs];
        v.x+=w.x; v.y+=w.y; v.z+=w.z; v.w+=w.w;
    }
    int col = (i4*4) % N;
    if (bias) {
        float4 bvv = *(const float4*)(bias + col);
        v.x+=bvv.x; v.y+=bvv.y; v.z+=bvv.z; v.w+=bvv.w;
    }
    if (act) { v.x=gelu_exact(v.x); v.y=gelu_exact(v.y); v.z=gelu_exact(v.z); v.w=gelu_exact(v.w); }
    if (res) {
        float4 rr = ((const float4*)res)[i4];
        v.x+=rr.x; v.y+=rr.y; v.z+=rr.z; v.w+=rr.w;
    }
    ((float4*)out)[i4] = v;
}

// ---------------- im2col (3x3 stride2 pad1), vectorized x4, bf16 hi/lo out ----------------
__global__ void im2col_hl(const float* __restrict__ x, bf16* __restrict__ oh, bf16* __restrict__ ol) {
    int idx = blockIdx.x*blockDim.x + threadIdx.x;
    const int total = NTOK*576;
    if (idx >= total) return;
    int c4 = idx % 576; int row = idx / 576;
    int b = row / NPOS; int p = row % NPOS;
    int i = p / WO, j = p % WO;
    int kk = c4 >> 6; int ic = (c4 & 63) * 4;
    int kh = kk / 3, kw = kk % 3;
    int hi = 2*i - 1 + kh, wi = 2*j - 1 + kw;
    float4 v = make_float4(0.f, 0.f, 0.f, 0.f);
    if (hi >= 0 && hi < HI && wi >= 0 && wi < WI)
        v = *(const float4*)(x + ((size_t)(b*(HI*WI) + hi*WI + wi))*DD + ic);
    __nv_bfloat162 h0, h1, l0, l1;
    split_hl(v.x, h0.x, l0.x); split_hl(v.y, h0.y, l0.y);
    split_hl(v.z, h1.x, l1.x); split_hl(v.w, h1.y, l1.y);
    size_t o = (size_t)row*2304 + kk*256 + ic;
    *(__nv_bfloat162*)(oh + o)     = h0;
    *(__nv_bfloat162*)(oh + o + 2) = h1;
    *(__nv_bfloat162*)(ol + o)     = l0;
    *(__nv_bfloat162*)(ol + o + 2) = l1;
}

__global__ void wseed_tr_hl(const float* __restrict__ w, bf16* __restrict__ oh, bf16* __restrict__ ol) {
    int idx = blockIdx.x*blockDim.x + threadIdx.x;
    if (idx >= DD*2304) return;
    int oc = idx / 2304; int c = idx % 2304;
    int kk = c >> 8; int ic = c & 255;
    float v = w[(size_t)oc*2304 + ic*9 + kk];
    split_hl(v, oh[idx], ol[idx]);
}

// ---------------- group NA (K=3): 4 groups merged per block ----------------
__global__ void na3_attn4(const float* __restrict__ kg, const float* __restrict__ q,
                          const float* __restrict__ rpb, const float* __restrict__ tau,
                          float* __restrict__ attn) {
    int blk = blockIdx.x;                 // b*784 + p
    int p = blk % NPOS, b = blk / NPOS;
    int i = p / WO, j = p % WO;
    int t = threadIdx.x; int w = t >> 5; int lane = t & 31;   // 9 warps
    __shared__ float kgs[4][256];
    __shared__ float logit[4][9];
    __shared__ float ev[4][9];
    // stage the 4 kg rows for this (b,p): t<128, n in {0,1}, rows n and n+2
    if (t < 128) {
        int n = t >> 6, f = t & 63;
        ((float4*)kgs[n])[f]   = *(const float4*)(kg + ((size_t)(b*4+n)*NPOS + p)*DD + f*4);
        ((float4*)kgs[n+2])[f] = *(const float4*)(kg + ((size_t)(b*4+n+2)*NPOS + p)*DD + f*4);
    }
    int a = w / 3, c = w % 3;
    int si = min(max(i-1,0),25), sj = min(max(j-1,0),25);
    int np = (si+a)*WO + (sj+c);
    const float* qv = q + (size_t)(b*NPOS + np)*DD;
    float qr[8];
    #pragma unroll
    for (int u=0;u<8;u++) qr[u] = qv[lane + 32*u];
    __syncthreads();
    #pragma unroll
    for (int n = 0; n < 4; n++) {
        float s = 0.f;
        #pragma unroll
        for (int u=0;u<8;u++) s = fmaf(qr[u], kgs[n][lane + 32*u], s);
        #pragma unroll
        for (int o=16;o;o>>=1) s += __shfl_xor_sync(0xffffffffu, s, o);
        if (lane==0) logit[n][w] = s + rpb[n*9 + w];
    }
    __syncthreads();
    if (t < 36) {
        int n = t/9, ac = t%9;
        float scale = expf(tau[0]);
        float m = -1e30f;
        #pragma unroll
        for (int u=0;u<9;u++) m = fmaxf(m, logit[n][u]*scale);
        ev[n][ac] = expf(logit[n][ac]*scale - m);
    }
    __syncthreads();
    if (t < 36) {
        int n = t/9, ac = t%9;
        float sum = 0.f;
        #pragma unroll
        for (int u=0;u<9;u++) sum += ev[n][u];
        attn[((size_t)(b*4+n)*NPOS + p)*9 + ac] = ev[n][ac]/sum + 1e-6f;
    }
}

// ---------------- deterministic column scatter-sum ----------------
__device__ __forceinline__ int inv_list(int s, int* lst) {
    if (s == 0)       { lst[0]=0;  lst[1]=1;  return 2; }
    else if (s == 25) { lst[0]=26; lst[1]=27; return 2; }
    else              { lst[0]=s+1;           return 1; }
}

__global__ void col_sum_k(const float* __restrict__ attn, float* __restrict__ col) {
    int idx = blockIdx.x*blockDim.x + threadIdx.x;
    if (idx >= BB*NPOS) return;
    int t = idx % NPOS, b = idx / NPOS;
    int ti = t / WO, tj = t % WO;
    float acc = 0.f;
    for (int a=0;a<3;a++) {
        int sr = ti - a; if (sr < 0 || sr > 25) continue;
        int il[2]; int ic = inv_list(sr, il);
        for (int c=0;c<3;c++) {
            int sc = tj - c; if (sc < 0 || sc > 25) continue;
            int jl[2]; int jc = inv_list(sc, jl);
            for (int ii=0; ii<ic; ii++)
                for (int jj=0; jj<jc; jj++) {
                    int pp = il[ii]*WO + jl[jj];
                    #pragma unroll
                    for (int n=0;n<4;n++)
                        acc += attn[((size_t)(b*4+n)*NPOS + pp)*9 + a*3 + c];
                }
        }
    }
    col[idx] = acc;
}

// ---------------- group NA AV + in-place residual + hi/lo out ----------------
__global__ void na3_av(const float* __restrict__ attn, const float* __restrict__ col,
                       const float* __restrict__ vg, float* __restrict__ xout,
                       bf16* __restrict__ oh, bf16* __restrict__ ol) {
    int blk = blockIdx.x;
    int p = blk % NPOS, b = blk / NPOS;
    int i = p / WO, j = p % WO;
    int t = threadIdx.x;
    __shared__ float wgt[4][9];
    __shared__ int npos[9];
    if (t < 9) {
        int a = t/3, c = t%3;
        int ni = min(max(i-1,0),25)+a, nj = min(max(j-1,0),25)+c;
        npos[t] = ni*WO + nj;
    }
    __syncthreads();
    if (t < 36) {
        int n = t/9, ac = t%9;
        float av = attn[((size_t)(b*4+n)*NPOS + p)*9 + ac];
        wgt[n][ac] = av / (col[b*NPOS + npos[ac]] + 1e-8f);
    }
    __syncthreads();
    float acc = xout[(size_t)blk*DD + t];
    #pragma unroll
    for (int n=0;n<4;n++) {
        const float* vb = vg + (size_t)(b*4+n)*NPOS*DD;
        #pragma unroll
        for (int ac=0;ac<9;ac++)
            acc = fmaf(wgt[n][ac], vb[(size_t)npos[ac]*DD + t], acc);
    }
    xout[(size_t)blk*DD + t] = acc;
    split_hl(acc, oh[(size_t)blk*DD + t], ol[(size_t)blk*DD + t]);
}

// ---------------- RoPE table ----------------
__global__ void rope_tab(float* __restrict__ cs, float* __restrict__ sn) {
    int idx = blockIdx.x*blockDim.x + threadIdx.x;
    if (idx >= NPOS*16) return;
    int pos = idx / 16, r = idx % 16;
    float f = expf(-((float)(2*r) / 32.f) * 9.210340371976184f);
    float ang = (float)pos * f;
    cs[idx] = cosf(ang);
    sn[idx] = sinf(ang);
}

// ---------------- block NA (K=7): row-blocked, smem-staged k/v window ----------------
#define NA7_SMEM ((2*6272 + 8*64) * 4)
__global__ void __launch_bounds__(256)
na7_row(const float* __restrict__ qkv, bf16* __restrict__ oh, bf16* __restrict__ ol) {
    extern __shared__ float sm7[];
    float* ks = sm7;
    float* vs = sm7 + 6272;
    float* wb = sm7 + 12544;
    int blk = blockIdx.x;
    int i = blk % 28; int bh = blk / 28; int h = bh & 7; int b = bh >> 3;
    int t = threadIdx.x, w = t >> 5, lane = t & 31;
    int si = min(max(i-3,0),21);
    for (int idx = t; idx < 1568; idx += 256) {
        int pos = idx >> 3, f = (idx & 7) * 4;
        int a = pos / 28, c = pos % 28;
        size_t g = ((size_t)(b*NPOS + (si+a)*WO + c))*768 + h*32 + f;
        *(float4*)(ks + pos*32 + f) = *(const float4*)(qkv + g + 256);
        *(float4*)(vs + pos*32 + f) = *(const float4*)(qkv + g + 512);
    }
    __syncthreads();
    for (int j = w; j < 28; j += 8) {
        int sj = min(max(j-3,0),21);
        int p = i*WO + j;
        float qd = qkv[((size_t)(b*NPOS + p))*768 + h*32 + lane];
        for (int nb = 0; nb < 49; nb++) {
            int a = nb / 7, c = nb % 7;
            float s = qd * ks[(a*28 + sj + c)*32 + lane];
            #pragma unroll
            for (int o=16;o;o>>=1) s += __shfl_xor_sync(0xffffffffu, s, o);
            if (lane == 0) wb[w*64 + nb] = s * 0.17677669529663687f;
        }
        __syncwarp();
        float m = -1e30f;
        for (int nb = lane; nb < 49; nb += 32) m = fmaxf(m, wb[w*64 + nb]);
        #pragma unroll
        for (int o=16;o;o>>=1) m = fmaxf(m, __shfl_xor_sync(0xffffffffu, m, o));
        float sum = 0.f;
        for (int nb = lane; nb < 49; nb += 32) {
            float e = expf(wb[w*64 + nb] - m);
            wb[w*64 + nb] = e;
            sum += e;
        }
        #pragma unroll
        for (int o=16;o;o>>=1) sum += __shfl_xor_sync(0xffffffffu, sum, o);
        __syncwarp();
        float inv = 1.f / sum;
        float acc = 0.f;
        for (int nb = 0; nb < 49; nb++) {
            int a = nb / 7, c = nb % 7;
            acc = fmaf(wb[w*64 + nb] * inv, vs[(a*28 + sj + c)*32 + lane], acc);
        }
        size_t o = ((size_t)(b*NPOS + p))*DD + h*32 + lane;
        split_hl(acc, oh[o], ol[o]);
        __syncwarp();
    }
}

// ---------------- host helpers ----------------
static inline void run_tc(const bf16* Ah, const bf16* Al, const bf16* Bh, const bf16* Bl,
                          const float* bias, float* C, bf16* Oh, bf16* Ol,
                          const float* cs, const float* sn,
                          int Mreal, int Mpad, int N, int K, int act, int remap, int ks) {
    dim3 grid(N/128, Mpad/128, ks);
    gemm_mma<<<grid, 256, GTC_SMEM>>>(Ah, Al, Bh, Bl, bias, C, Oh, Ol, cs, sn,
                                      Mreal, Mpad, N, K, act, remap, ks);
}
static inline void run_cvt(const float* in, bf16* hi, bf16* lo, int n) {
    int n4 = n >> 2;
    cvt_hl<<<(n4 + 255)/256, 256>>>(in, hi, lo, n4);
}
static inline void run_ln(const float* in, const float* g, const float* b, const float* res,
                          float* out, bf16* oh, bf16* ol, int nrows) {
    ln_warp<<<(nrows + 7)/8, 256>>>(in, g, b, res, out, oh, ol, nrows);
}
static inline void run_combine(const float* part, int s, const float* bias,
                               const float* res, float* out, int Mreal, int Mpad, int N, int act) {
    int tot4 = (Mreal*N) >> 2;
    combine_k<<<(tot4 + 255)/256, 256>>>(part, s, bias, res, out, Mreal, Mpad, N, act);
}

extern "C" void kernel_launch(void* const* d_in, const int* in_sizes, int n_in,
                              void* d_out, int out_size) {
    const float* x          = (const float*)d_in[0];
    const float* g_seed_w   = (const float*)d_in[1];
    const float* g_q_w      = (const float*)d_in[2];
    const float* g_k_w      = (const float*)d_in[3];
    const float* g_v_w      = (const float*)d_in[4];
    const float* g_mlp_w1   = (const float*)d_in[5];
    const float* g_mlp_b1   = (const float*)d_in[6];
    const float* g_mlp_w2   = (const float*)d_in[7];
    const float* g_mlp_b2   = (const float*)d_in[8];
    const float* g_ln_in_g  = (const float*)d_in[9];
    const float* g_ln_in_b  = (const float*)d_in[10];
    const float* g_ln_out_g = (const float*)d_in[11];
    const float* g_ln_out_b = (const float*)d_in[12];
    const float* g_tau      = (const float*)d_in[13];
    const float* g_rpb      = (const float*)d_in[14];
    const float* blk_ln1_g  = (const float*)d_in[15];
    const float* blk_ln1_b  = (const float*)d_in[16];
    const float* blk_qkv_w  = (const float*)d_in[17];
    const float* blk_proj_w = (const float*)d_in[18];
    const float* blk_proj_b = (const float*)d_in[19];
    const float* blk_ln2_g  = (const float*)d_in[20];
    const float* blk_ln2_b  = (const float*)d_in[21];
    const float* blk_mlp_w1 = (const float*)d_in[22];
    const float* blk_mlp_b1 = (const float*)d_in[23];
    const float* blk_mlp_w2 = (const float*)d_in[24];
    const float* blk_mlp_b2 = (const float*)d_in[25];
    float* out = (float*)d_out;

    cudaFuncSetAttribute(gemm_mma, cudaFuncAttributeMaxDynamicSharedMemorySize, GTC_SMEM);
    cudaFuncSetAttribute(na7_row, cudaFuncAttributeMaxDynamicSharedMemorySize, NA7_SMEM);

#define SYM(v, s) cudaGetSymbolAddress((void**)&v, s)
    float *xout, *buf2, *kg, *vg, *split, *attn, *colsum, *csb, *snb;
    SYM(xout,g_xout); SYM(buf2,g_buf2);
    SYM(kg,g_kg); SYM(vg,g_vg); SYM(split,g_split); SYM(attn,g_attn);
    SYM(colsum,g_colsum); SYM(csb,g_cos); SYM(snb,g_sin);
    bf16 *xh,*xl,*lnxh,*lnxl,*colh,*coll,*a1h,*a1l,*a2h,*a2l;
    SYM(xh,g_xh); SYM(xl,g_xl); SYM(lnxh,g_lnxh); SYM(lnxl,g_lnxl);
    SYM(colh,g_colh); SYM(coll,g_coll); SYM(a1h,g_a1h); SYM(a1l,g_a1l);
    SYM(a2h,g_a2h); SYM(a2l,g_a2l);
    bf16 *wsh,*wsl,*wqh,*wql,*wkh,*wkl,*wvh,*wvl,*m1h,*m1l,*m2h,*m2l;
    SYM(wsh,g_wsh); SYM(wsl,g_wsl); SYM(wqh,g_wqh); SYM(wql,g_wql);
    SYM(wkh,g_wkh); SYM(wkl,g_wkl); SYM(wvh,g_wvh); SYM(wvl,g_wvl);
    SYM(m1h,g_m1h); SYM(m1l,g_m1l); SYM(m2h,g_m2h); SYM(m2l,g_m2l);
    bf16 *qkvh,*qkvl,*pjh,*pjl,*bm1h,*bm1l,*bm2h,*bm2l;
    SYM(qkvh,g_qkvh); SYM(qkvl,g_qkvl); SYM(pjh,g_pjh); SYM(pjl,g_pjl);
    SYM(bm1h,g_bm1h); SYM(bm1l,g_bm1l); SYM(bm2h,g_bm2h); SYM(bm2l,g_bm2l);
#undef SYM

    // ---- weight conversions ----
    wseed_tr_hl<<<(DD*2304 + 255)/256, 256>>>(g_seed_w, wsh, wsl);
    run_cvt(g_q_w, wqh, wql, DD*DD);
    run_cvt(g_k_w, wkh, wkl, DD*DD);
    run_cvt(g_v_w, wvh, wvl, DD*DD);
    run_cvt(g_mlp_w1, m1h, m1l, 512*DD);
    run_cvt(g_mlp_w2, m2h, m2l, DD*512);
    run_cvt(blk_qkv_w, qkvh, qkvl, 2*768*DD);
    run_cvt(blk_proj_w, pjh, pjl, 2*DD*DD);
    run_cvt(blk_mlp_w1, bm1h, bm1l, 2*768*DD);
    run_cvt(blk_mlp_w2, bm2h, bm2l, 2*DD*768);

    // ---- k, v group projections (permute fused into epilogue) ----
    run_ln(x, g_ln_in_g, g_ln_in_b, nullptr, nullptr, lnxh, lnxl, NTOKIN);
    run_cvt(x, xh, xl, NTOKIN*DD);
    run_tc(lnxh, lnxl, wkh, wkl, nullptr, kg, nullptr, nullptr, nullptr, nullptr,
           NTOKIN, NTOKIN, DD, DD, 0, 1, 1);
    run_tc(xh,   xl,   wvh, wvl, nullptr, vg, nullptr, nullptr, nullptr, nullptr,
           NTOKIN, NTOKIN, DD, DD, 0, 1, 1);

    // ---- seed conv via im2col + split-K tensor GEMM + fused combine/LN ----
    im2col_hl<<<(NTOK*576 + 255)/256, 256>>>(x, colh, coll);
    run_tc(colh, coll, wsh, wsl, nullptr, split, nullptr, nullptr, nullptr, nullptr,
           NTOK, NTOKP, DD, 2304, 0, 0, 3);
    combine_ln<<<(NTOK + 7)/8, 256>>>(split, 3, nullptr, g_ln_out_g, g_ln_out_b,
                                      nullptr, xout, NTOKP, NTOK);

    rope_tab<<<(NPOS*16 + 255)/256, 256>>>(csb, snb);

    // ---- 3 grouped-NA seeding iterations ----
    for (int it = 0; it < 3; it++) {
        run_ln(xout, g_ln_out_g, g_ln_out_b, nullptr, nullptr, a2h, a2l, NTOK);
        run_tc(a2h, a2l, wqh, wql, nullptr, split, nullptr, nullptr, nullptr, nullptr,
               NTOK, NTOKP, DD, DD, 0, 0, 2);
        run_combine(split, 2, nullptr, nullptr, buf2, NTOK, NTOKP, DD, 0);
        na3_attn4<<<NTOK, 288>>>(kg, buf2, g_rpb, g_tau, attn);
        col_sum_k<<<(BB*NPOS + 255)/256, 256>>>(attn, colsum);
        na3_av<<<NTOK, 256>>>(attn, colsum, vg, xout, a2h, a2l);
        run_tc(a2h, a2l, m1h, m1l, g_mlp_b1, nullptr, a1h, a1l, nullptr, nullptr,
               NTOK, NTOKP, 512, DD, 1, 0, 1);
        run_tc(a1h, a1l, m2h, m2l, nullptr, split, nullptr, nullptr, nullptr, nullptr,
               NTOK, NTOKP, DD, 512, 0, 0, 2);
        combine_ln<<<(NTOK + 7)/8, 256>>>(split, 2, g_mlp_b2, g_ln_out_g, g_ln_out_b,
                                          xout, xout, NTOKP, NTOK);
    }

    // ---- 2 transformer blocks with 7x7 NA ----
    for (int l = 0; l < 2; l++) {
        run_ln(xout, blk_ln1_g + l*DD, blk_ln1_b + l*DD, nullptr, nullptr, a2h, a2l, NTOK);
        run_tc(a2h, a2l, qkvh + (size_t)l*768*DD, qkvl + (size_t)l*768*DD,
               nullptr, buf2, nullptr, nullptr, csb, snb,
               NTOK, NTOKP, 768, DD, 0, 0, 1);
        na7_row<<<BB*HEADS*28, 256, NA7_SMEM>>>(buf2, a2h, a2l);
        run_tc(a2h, a2l, pjh + (size_t)l*DD*DD, pjl + (size_t)l*DD*DD,
               nullptr, split, nullptr, nullptr, nullptr, nullptr,
               NTOK, NTOKP, DD, DD, 0, 0, 2);
        run_combine(split, 2, blk_proj_b + l*DD, xout, xout, NTOK, NTOKP, DD, 0);
        run_ln(xout, blk_ln2_g + l*DD, blk_ln2_b + l*DD, nullptr, nullptr, a2h, a2l, NTOK);
        run_tc(a2h, a2l, bm1h + (size_t)l*768*DD, bm1l + (size_t)l*768*DD,
               blk_mlp_b1 + l*768, nullptr, a1h, a1l, nullptr, nullptr,
               NTOK, NTOKP, 768, DD, 1, 0, 1);
        run_tc(a1h, a1l, bm2h + (size_t)l*DD*768, bm2l + (size_t)l*DD*768,
               nullptr, split, nullptr, nullptr, nullptr, nullptr,
               NTOK, NTOKP, DD, 768, 0, 0, 2);
        run_combine(split, 2, blk_mlp_b2 + l*DD, xout, (l == 1) ? out : xout, NTOK, NTOKP, DD, 0);
    }
}

// round 9
// speedup vs baseline: 2.0330x; 1.0571x over previous
#include <cuda_runtime.h>
#include <cuda_bf16.h>
#include <math.h>
#include <stdint.h>

// ---------------- problem constants ----------------
#define BB 4
#define HI 56
#define WI 56
#define DD 256
#define HO 28
#define WO 28
#define NPOS 784
#define NTOK (BB*NPOS)     // 3136
#define NTOKP 3200
#define NTOKIN (BB*HI*WI)  // 12544
#define HEADS 8
#define LN_EPS 1e-5f

typedef __nv_bfloat16 bf16;

// ---------------- scratch (device globals) ----------------
__device__ float g_xout  [NTOK*DD];
__device__ float g_buf2  [NTOK*768];
__device__ float g_kg    [BB*4*NPOS*DD];
__device__ float g_vg    [BB*4*NPOS*DD];
__device__ float g_split [3*NTOKP*DD];
__device__ float g_attn  [BB*4*NPOS*9];
__device__ float g_colsum[BB*NPOS];
__device__ float g_cos   [NPOS*16];
__device__ float g_sin   [NPOS*16];

__device__ bf16 g_xh[NTOKIN*DD],  g_xl[NTOKIN*DD];
__device__ bf16 g_lnxh[NTOKIN*DD],g_lnxl[NTOKIN*DD];
__device__ bf16 g_colh[NTOKP*2304], g_coll[NTOKP*2304];
__device__ bf16 g_a1h[NTOKP*768], g_a1l[NTOKP*768];
__device__ bf16 g_a2h[NTOKP*256], g_a2l[NTOKP*256];
__device__ bf16 g_wsh[DD*2304], g_wsl[DD*2304];
__device__ bf16 g_wqh[DD*DD],   g_wql[DD*DD];
__device__ bf16 g_wkh[DD*DD],   g_wkl[DD*DD];
__device__ bf16 g_wvh[DD*DD],   g_wvl[DD*DD];
__device__ bf16 g_m1h[512*DD],  g_m1l[512*DD];
__device__ bf16 g_m2h[DD*512],  g_m2l[DD*512];
__device__ bf16 g_qkvh[2*768*DD], g_qkvl[2*768*DD];
__device__ bf16 g_pjh[2*DD*DD],   g_pjl[2*DD*DD];
__device__ bf16 g_bm1h[2*768*DD], g_bm1l[2*768*DD];
__device__ bf16 g_bm2h[2*DD*768], g_bm2l[2*DD*768];

// ---------------- helpers ----------------
__device__ __forceinline__ uint32_t smem_u32(const void* p) {
    uint32_t a;
    asm("{ .reg .u64 t; cvta.to.shared.u64 t, %1; cvt.u32.u64 %0, t; }" : "=r"(a) : "l"(p));
    return a;
}
__device__ __forceinline__ float gelu_exact(float x) {
    return 0.5f * x * (1.f + erff(x * 0.70710678118654752f));
}
__device__ __forceinline__ void cp16(uint32_t saddr, const void* gaddr) {
    asm volatile("cp.async.cg.shared.global [%0], [%1], 16;" :: "r"(saddr), "l"(gaddr));
}
#define CP_COMMIT() asm volatile("cp.async.commit_group;" ::: "memory")
#define CP_WAIT0()  asm volatile("cp.async.wait_group 0;" ::: "memory")

__device__ __forceinline__ void ldmx4(uint32_t addr, uint32_t* r) {
    asm volatile("ldmatrix.sync.aligned.m8n8.x4.shared.b16 {%0,%1,%2,%3}, [%4];"
        : "=r"(r[0]), "=r"(r[1]), "=r"(r[2]), "=r"(r[3]) : "r"(addr));
}
__device__ __forceinline__ void mma16816(float* d, const uint32_t* a, uint32_t b0, uint32_t b1) {
    asm volatile("mma.sync.aligned.m16n8k16.row.col.f32.bf16.bf16.f32 "
        "{%0,%1,%2,%3}, {%4,%5,%6,%7}, {%8,%9}, {%0,%1,%2,%3};"
        : "+f"(d[0]), "+f"(d[1]), "+f"(d[2]), "+f"(d[3])
        : "r"(a[0]), "r"(a[1]), "r"(a[2]), "r"(a[3]), "r"(b0), "r"(b1));
}
__device__ __forceinline__ void split_hl(float v, bf16& h, bf16& l) {
    h = __float2bfloat16(v);
    l = __float2bfloat16(v - __bfloat162float(h));
}

// ---------------- tensor-core GEMM (mma.sync bf16 hi/lo 3-pass) ----------------
#define TROW 144
#define TSZ  (128*TROW)
#define BUFSZ (4*TSZ)
#define GTC_SMEM (2*BUFSZ)

__global__ void __launch_bounds__(256, 1)
gemm_mma(const bf16* __restrict__ Ah, const bf16* __restrict__ Al,
         const bf16* __restrict__ Bh, const bf16* __restrict__ Bl,
         const float* __restrict__ bias, float* __restrict__ C,
         bf16* __restrict__ Oh, bf16* __restrict__ Ol,
         const float* __restrict__ CS, const float* __restrict__ SN,
         int Mreal, int Mpad, int N, int K, int act, int remap, int ksplit) {
    extern __shared__ char smraw[];
    uint32_t sb = smem_u32(smraw);
    int tid = threadIdx.x, wid = tid >> 5, lane = tid & 31;
    int wm = wid >> 2, wn = wid & 3;
    int bm = blockIdx.y * 128, bn = blockIdx.x * 128;
    int kper = K / ksplit;
    int kbase = blockIdx.z * kper;
    int nch = kper / 64;

    const bf16* srcs[4] = { Ah + (size_t)bm*K, Al + (size_t)bm*K,
                            Bh + (size_t)bn*K, Bl + (size_t)bn*K };

    #define LOAD_CHUNK(c, b) {                                                  \
        int k0 = kbase + (c)*64;                                                \
        uint32_t dbase = sb + (b)*BUFSZ;                                        \
        _Pragma("unroll")                                                       \
        for (int s = 0; s < 4; s++) {                                           \
            const bf16* base = srcs[s];                                         \
            uint32_t dst = dbase + s*TSZ;                                       \
            _Pragma("unroll")                                                   \
            for (int u = 0; u < 4; u++) {                                       \
                int idx = tid + u*256;                                          \
                int row = idx >> 3, seg = idx & 7;                              \
                cp16(dst + row*TROW + seg*16, base + (size_t)row*K + k0 + seg*8); \
            }                                                                   \
        }                                                                       \
        CP_COMMIT();                                                            \
    }

    float acc[4][4][4];
    #pragma unroll
    for (int i=0;i<4;i++)
        #pragma unroll
        for (int j=0;j<4;j++)
            #pragma unroll
            for (int e=0;e<4;e++) acc[i][j][e] = 0.f;

    LOAD_CHUNK(0, 0)
    int buf = 0;
    int lr16 = lane & 15, lh = lane >> 4;

    for (int c = 0; c < nch; c++) {
        CP_WAIT0();
        __syncthreads();
        if (c + 1 < nch) LOAD_CHUNK(c+1, buf^1)
        uint32_t aH = sb + buf*BUFSZ;
        uint32_t aL = aH + TSZ;
        uint32_t bH = aH + 2*TSZ;
        uint32_t bL = aH + 3*TSZ;
        #pragma unroll
        for (int kk = 0; kk < 4; kk++) {
            uint32_t ah[4][4], al[4][4], bh[2][4], bl[2][4];
            int kb = kk*32 + lh*16;
            #pragma unroll
            for (int mi = 0; mi < 4; mi++) {
                int row = wm*64 + mi*16 + lr16;
                ldmx4(aH + row*TROW + kb, ah[mi]);
                ldmx4(aL + row*TROW + kb, al[mi]);
            }
            #pragma unroll
            for (int n2 = 0; n2 < 2; n2++) {
                int row = wn*32 + n2*16 + lr16;
                ldmx4(bH + row*TROW + kb, bh[n2]);
                ldmx4(bL + row*TROW + kb, bl[n2]);
            }
            #pragma unroll
            for (int mi = 0; mi < 4; mi++) {
                #pragma unroll
                for (int nj = 0; nj < 4; nj++) {
                    int n2 = nj >> 1, sel = nj & 1;
                    mma16816(acc[mi][nj], ah[mi], bh[n2][sel], bh[n2][sel+2]);
                    mma16816(acc[mi][nj], ah[mi], bl[n2][sel], bl[n2][sel+2]);
                    mma16816(acc[mi][nj], al[mi], bh[n2][sel], bh[n2][sel+2]);
                }
            }
        }
        __syncthreads();
        buf ^= 1;
    }
    #undef LOAD_CHUNK

    int cbase = bn + wn*32 + (lane & 3)*2;
    int rbase = bm + wm*64 + (lane >> 2);
    if (ksplit > 1) {
        float* Cp = C + (size_t)blockIdx.z * Mpad * N;
        #pragma unroll
        for (int mi = 0; mi < 4; mi++) {
            #pragma unroll
            for (int half = 0; half < 2; half++) {
                int r = rbase + mi*16 + half*8;
                if (r >= Mreal) continue;
                #pragma unroll
                for (int nj = 0; nj < 4; nj++) {
                    float2 v = make_float2(acc[mi][nj][half*2], acc[mi][nj][half*2+1]);
                    *(float2*)(Cp + (size_t)r*N + cbase + nj*8) = v;
                }
            }
        }
        return;
    }
    #pragma unroll
    for (int mi = 0; mi < 4; mi++) {
        #pragma unroll
        for (int half = 0; half < 2; half++) {
            int r = rbase + mi*16 + half*8;
            if (r >= Mreal) continue;
            int orow = r;
            if (remap) {
                int b2 = r / (HI*WI); int rr = r % (HI*WI);
                int hi2 = rr / WI, wi2 = rr % WI;
                orow = (b2*4 + (hi2&1)*2 + (wi2&1))*NPOS + (hi2>>1)*WO + (wi2>>1);
            }
            #pragma unroll
            for (int nj = 0; nj < 4; nj++) {
                int col = cbase + nj*8;
                float v0 = acc[mi][nj][half*2], v1 = acc[mi][nj][half*2+1];
                if (bias) { v0 += bias[col]; v1 += bias[col+1]; }
                if (act)  { v0 = gelu_exact(v0); v1 = gelu_exact(v1); }
                if (CS && col < 512) {
                    int pos = orow % NPOS;
                    int rr2 = (col & 31) >> 1;
                    float c = CS[pos*16 + rr2], s = SN[pos*16 + rr2];
                    float t0 = v0*c - v1*s;
                    v1 = v1*c + v0*s;
                    v0 = t0;
                }
                if (Oh) {
                    __nv_bfloat162 hv, lv;
                    split_hl(v0, hv.x, lv.x);
                    split_hl(v1, hv.y, lv.y);
                    *(__nv_bfloat162*)(Oh + (size_t)orow*N + col) = hv;
                    *(__nv_bfloat162*)(Ol + (size_t)orow*N + col) = lv;
                } else {
                    *(float2*)(C + (size_t)orow*N + col) = make_float2(v0, v1);
                }
            }
        }
    }
}

// ---------------- merged weight converter (9 segments, compile-time offsets) ----------------
struct CvtSegs {
    const float* src[9];
    bf16* hi[9];
    bf16* lo[9];
};
// element counts /4 (float4 units)
#define S0 16384   // q 256*256
#define S1 16384   // k
#define S2 16384   // v
#define S3 32768   // m1 512*256
#define S4 32768   // m2
#define S5 98304   // qkv 2*768*256
#define S6 32768   // pj 2*256*256
#define S7 98304   // bm1
#define S8 98304   // bm2
#define CVT_TOT (S0+S1+S2+S3+S4+S5+S6+S7+S8)

__global__ void cvt_all(CvtSegs segs) {
    int i = blockIdx.x*blockDim.x + threadIdx.x;
    if (i >= CVT_TOT) return;
    int seg, off = i;
    if      (off < S0) seg = 0;
    else if ((off -= S0) < S1) seg = 1;
    else if ((off -= S1) < S2) seg = 2;
    else if ((off -= S2) < S3) seg = 3;
    else if ((off -= S3) < S4) seg = 4;
    else if ((off -= S4) < S5) seg = 5;
    else if ((off -= S5) < S6) seg = 6;
    else if ((off -= S6) < S7) seg = 7;
    else { off -= S7; seg = 8; }
    float4 v = ((const float4*)segs.src[seg])[off];
    __nv_bfloat162 h0, h1, l0, l1;
    split_hl(v.x, h0.x, l0.x); split_hl(v.y, h0.y, l0.y);
    split_hl(v.z, h1.x, l1.x); split_hl(v.w, h1.y, l1.y);
    ((__nv_bfloat162*)segs.hi[seg])[2*off]   = h0;
    ((__nv_bfloat162*)segs.hi[seg])[2*off+1] = h1;
    ((__nv_bfloat162*)segs.lo[seg])[2*off]   = l0;
    ((__nv_bfloat162*)segs.lo[seg])[2*off+1] = l1;
}

// ---------------- warp-per-row LN over 256 (+ optional raw hi/lo out) ----------------
__global__ void ln_warp(const float* __restrict__ in, const float* __restrict__ gamma,
                        const float* __restrict__ beta,
                        bf16* __restrict__ oh, bf16* __restrict__ ol,
                        bf16* __restrict__ rh, bf16* __restrict__ rl,
                        int nrows) {
    int gw = (blockIdx.x * blockDim.x + threadIdx.x) >> 5;
    int lane = threadIdx.x & 31;
    if (gw >= nrows) return;
    const float4* row = (const float4*)(in + (size_t)gw * DD);
    float4 v0 = row[lane], v1 = row[lane + 32];
    if (rh) {
        __nv_bfloat162* hp = (__nv_bfloat162*)(rh + (size_t)gw * DD);
        __nv_bfloat162* lp = (__nv_bfloat162*)(rl + (size_t)gw * DD);
        __nv_bfloat162 h0, l0, h1, l1;
        split_hl(v0.x, h0.x, l0.x); split_hl(v0.y, h0.y, l0.y);
        split_hl(v0.z, h1.x, l1.x); split_hl(v0.w, h1.y, l1.y);
        hp[lane*2] = h0; hp[lane*2+1] = h1;
        lp[lane*2] = l0; lp[lane*2+1] = l1;
        split_hl(v1.x, h0.x, l0.x); split_hl(v1.y, h0.y, l0.y);
        split_hl(v1.z, h1.x, l1.x); split_hl(v1.w, h1.y, l1.y);
        hp[64+lane*2] = h0; hp[64+lane*2+1] = h1;
        lp[64+lane*2] = l0; lp[64+lane*2+1] = l1;
    }
    float s = v0.x+v0.y+v0.z+v0.w + v1.x+v1.y+v1.z+v1.w;
    #pragma unroll
    for (int o=16;o;o>>=1) s += __shfl_xor_sync(0xffffffffu, s, o);
    float mean = s * (1.f/256.f);
    float d[8] = {v0.x-mean, v0.y-mean, v0.z-mean, v0.w-mean,
                  v1.x-mean, v1.y-mean, v1.z-mean, v1.w-mean};
    float sq = 0.f;
    #pragma unroll
    for (int e=0;e<8;e++) sq += d[e]*d[e];
    #pragma unroll
    for (int o=16;o;o>>=1) sq += __shfl_xor_sync(0xffffffffu, sq, o);
    float inv = rsqrtf(sq * (1.f/256.f) + LN_EPS);
    float4 g0 = ((const float4*)gamma)[lane], g1 = ((const float4*)gamma)[lane+32];
    float4 b0 = ((const float4*)beta)[lane],  b1 = ((const float4*)beta)[lane+32];
    float y[8];
    y[0]=d[0]*inv*g0.x+b0.x; y[1]=d[1]*inv*g0.y+b0.y; y[2]=d[2]*inv*g0.z+b0.z; y[3]=d[3]*inv*g0.w+b0.w;
    y[4]=d[4]*inv*g1.x+b1.x; y[5]=d[5]*inv*g1.y+b1.y; y[6]=d[6]*inv*g1.z+b1.z; y[7]=d[7]*inv*g1.w+b1.w;
    __nv_bfloat162* hp = (__nv_bfloat162*)(oh + (size_t)gw * DD);
    __nv_bfloat162* lp = (__nv_bfloat162*)(ol + (size_t)gw * DD);
    #pragma unroll
    for (int q = 0; q < 4; q++) {
        __nv_bfloat162 hv, lv;
        split_hl(y[q*2],   hv.x, lv.x);
        split_hl(y[q*2+1], hv.y, lv.y);
        int idx = (q < 2) ? (lane*2 + q) : (64 + lane*2 + (q-2));
        hp[idx] = hv;
        lp[idx] = lv;
    }
}

// warp-level LN of an 8-element-per-lane row fragment, then bf16 hi/lo store
__device__ __forceinline__ void ln_store_hl(float* y, const float* gamma, const float* beta,
                                            int lane, bf16* oh, bf16* ol, size_t rowoff) {
    float sm = 0.f;
    #pragma unroll
    for (int e=0;e<8;e++) sm += y[e];
    #pragma unroll
    for (int o=16;o;o>>=1) sm += __shfl_xor_sync(0xffffffffu, sm, o);
    float mean = sm * (1.f/256.f);
    float d[8], sq = 0.f;
    #pragma unroll
    for (int e=0;e<8;e++) { d[e] = y[e]-mean; sq += d[e]*d[e]; }
    #pragma unroll
    for (int o=16;o;o>>=1) sq += __shfl_xor_sync(0xffffffffu, sq, o);
    float inv = rsqrtf(sq * (1.f/256.f) + LN_EPS);
    float4 g0 = ((const float4*)gamma)[lane], g1 = ((const float4*)gamma)[lane+32];
    float4 b0 = ((const float4*)beta)[lane],  b1 = ((const float4*)beta)[lane+32];
    float z[8];
    z[0]=d[0]*inv*g0.x+b0.x; z[1]=d[1]*inv*g0.y+b0.y; z[2]=d[2]*inv*g0.z+b0.z; z[3]=d[3]*inv*g0.w+b0.w;
    z[4]=d[4]*inv*g1.x+b1.x; z[5]=d[5]*inv*g1.y+b1.y; z[6]=d[6]*inv*g1.z+b1.z; z[7]=d[7]*inv*g1.w+b1.w;
    __nv_bfloat162* hp = (__nv_bfloat162*)(oh + rowoff);
    __nv_bfloat162* lp = (__nv_bfloat162*)(ol + rowoff);
    #pragma unroll
    for (int q = 0; q < 4; q++) {
        __nv_bfloat162 hv, lv;
        split_hl(z[q*2],   hv.x, lv.x);
        split_hl(z[q*2+1], hv.y, lv.y);
        int idx = (q < 2) ? (lane*2 + q) : (64 + lane*2 + (q-2));
        hp[idx] = hv;
        lp[idx] = lv;
    }
}

// ---------------- combine(+bias) -> LN1 -> +res -> xout; then LN2 -> bf16 ----------------
__global__ void combine_ln2(const float* __restrict__ part, int s,
                            const float* __restrict__ bias,
                            const float* __restrict__ g1, const float* __restrict__ b1,
                            const float* __restrict__ res, float* __restrict__ outf,
                            const float* __restrict__ g2, const float* __restrict__ b2,
                            bf16* __restrict__ oh, bf16* __restrict__ ol,
                            int Mpad, int nrows) {
    int gw = (blockIdx.x * blockDim.x + threadIdx.x) >> 5;
    int lane = threadIdx.x & 31;
    if (gw >= nrows) return;
    float y[8];
    {
        const float4* p0 = (const float4*)(part + (size_t)gw * DD);
        float4 v0 = p0[lane], v1 = p0[lane+32];
        y[0]=v0.x; y[1]=v0.y; y[2]=v0.z; y[3]=v0.w;
        y[4]=v1.x; y[5]=v1.y; y[6]=v1.z; y[7]=v1.w;
        for (int z = 1; z < s; z++) {
            const float4* pz = (const float4*)(part + (size_t)z*Mpad*DD + (size_t)gw * DD);
            float4 w0 = pz[lane], w1 = pz[lane+32];
            y[0]+=w0.x; y[1]+=w0.y; y[2]+=w0.z; y[3]+=w0.w;
            y[4]+=w1.x; y[5]+=w1.y; y[6]+=w1.z; y[7]+=w1.w;
        }
    }
    if (bias) {
        float4 c0 = ((const float4*)bias)[lane], c1 = ((const float4*)bias)[lane+32];
        y[0]+=c0.x; y[1]+=c0.y; y[2]+=c0.z; y[3]+=c0.w;
        y[4]+=c1.x; y[5]+=c1.y; y[6]+=c1.z; y[7]+=c1.w;
    }
    // LN1
    float sm = 0.f;
    #pragma unroll
    for (int e=0;e<8;e++) sm += y[e];
    #pragma unroll
    for (int o=16;o;o>>=1) sm += __shfl_xor_sync(0xffffffffu, sm, o);
    float mean = sm * (1.f/256.f);
    float sq = 0.f;
    #pragma unroll
    for (int e=0;e<8;e++) { y[e] -= mean; sq += y[e]*y[e]; }
    #pragma unroll
    for (int o=16;o;o>>=1) sq += __shfl_xor_sync(0xffffffffu, sq, o);
    float inv = rsqrtf(sq * (1.f/256.f) + LN_EPS);
    float4 gg0 = ((const float4*)g1)[lane], gg1 = ((const float4*)g1)[lane+32];
    float4 bb0 = ((const float4*)b1)[lane], bb1 = ((const float4*)b1)[lane+32];
    y[0]=y[0]*inv*gg0.x+bb0.x; y[1]=y[1]*inv*gg0.y+bb0.y; y[2]=y[2]*inv*gg0.z+bb0.z; y[3]=y[3]*inv*gg0.w+bb0.w;
    y[4]=y[4]*inv*gg1.x+bb1.x; y[5]=y[5]*inv*gg1.y+bb1.y; y[6]=y[6]*inv*gg1.z+bb1.z; y[7]=y[7]*inv*gg1.w+bb1.w;
    if (res) {
        const float4* rr = (const float4*)(res + (size_t)gw * DD);
        float4 r0 = rr[lane], r1 = rr[lane+32];
        y[0]+=r0.x; y[1]+=r0.y; y[2]+=r0.z; y[3]+=r0.w;
        y[4]+=r1.x; y[5]+=r1.y; y[6]+=r1.z; y[7]+=r1.w;
    }
    float4* op = (float4*)(outf + (size_t)gw * DD);
    op[lane]    = make_float4(y[0],y[1],y[2],y[3]);
    op[lane+32] = make_float4(y[4],y[5],y[6],y[7]);
    ln_store_hl(y, g2, b2, lane, oh, ol, (size_t)gw * DD);
}

// ---------------- combine(+bias) -> +res -> xout; then LN -> bf16 ----------------
__global__ void combine_res_ln(const float* __restrict__ part, int s,
                               const float* __restrict__ bias, const float* __restrict__ res,
                               float* __restrict__ outf,
                               const float* __restrict__ g2, const float* __restrict__ b2,
                               bf16* __restrict__ oh, bf16* __restrict__ ol,
                               int Mpad, int nrows) {
    int gw = (blockIdx.x * blockDim.x + threadIdx.x) >> 5;
    int lane = threadIdx.x & 31;
    if (gw >= nrows) return;
    float y[8];
    {
        const float4* p0 = (const float4*)(part + (size_t)gw * DD);
        float4 v0 = p0[lane], v1 = p0[lane+32];
        y[0]=v0.x; y[1]=v0.y; y[2]=v0.z; y[3]=v0.w;
        y[4]=v1.x; y[5]=v1.y; y[6]=v1.z; y[7]=v1.w;
        for (int z = 1; z < s; z++) {
            const float4* pz = (const float4*)(part + (size_t)z*Mpad*DD + (size_t)gw * DD);
            float4 w0 = pz[lane], w1 = pz[lane+32];
            y[0]+=w0.x; y[1]+=w0.y; y[2]+=w0.z; y[3]+=w0.w;
            y[4]+=w1.x; y[5]+=w1.y; y[6]+=w1.z; y[7]+=w1.w;
        }
    }
    if (bias) {
        float4 c0 = ((const float4*)bias)[lane], c1 = ((const float4*)bias)[lane+32];
        y[0]+=c0.x; y[1]+=c0.y; y[2]+=c0.z; y[3]+=c0.w;
        y[4]+=c1.x; y[5]+=c1.y; y[6]+=c1.z; y[7]+=c1.w;
    }
    {
        const float4* rr = (const float4*)(res + (size_t)gw * DD);
        float4 r0 = rr[lane], r1 = rr[lane+32];
        y[0]+=r0.x; y[1]+=r0.y; y[2]+=r0.z; y[3]+=r0.w;
        y[4]+=r1.x; y[5]+=r1.y; y[6]+=r1.z; y[7]+=r1.w;
    }
    float4* op = (float4*)(outf + (size_t)gw * DD);
    op[lane]    = make_float4(y[0],y[1],y[2],y[3]);
    op[lane+32] = make_float4(y[4],y[5],y[6],y[7]);
    ln_store_hl(y, g2, b2, lane, oh, ol, (size_t)gw * DD);
}

// ---------------- plain split-K combine with epilogue ----------------
__global__ void combine_k(const float* __restrict__ part, int s,
                          const float* __restrict__ bias, const float* __restrict__ res,
                          float* __restrict__ out, int Mreal, int Mpad, int N, int act) {
    int i4 = blockIdx.x*blockDim.x + threadIdx.x;
    int tot = (Mreal*N) >> 2;
    if (i4 >= tot) return;
    size_t zs = ((size_t)Mpad*N) >> 2;
    float4 v = ((const float4*)part)[i4];
    for (int z = 1; z < s; z++) {
        float4 w = ((const float4*)part)[i4 + z*zs];
        v.x+=w.x; v.y+=w.y; v.z+=w.z; v.w+=w.w;
    }
    int col = (i4*4) % N;
    if (bias) {
        float4 bvv = *(const float4*)(bias + col);
        v.x+=bvv.x; v.y+=bvv.y; v.z+=bvv.z; v.w+=bvv.w;
    }
    if (act) { v.x=gelu_exact(v.x); v.y=gelu_exact(v.y); v.z=gelu_exact(v.z); v.w=gelu_exact(v.w); }
    if (res) {
        float4 rr = ((const float4*)res)[i4];
        v.x+=rr.x; v.y+=rr.y; v.z+=rr.z; v.w+=rr.w;
    }
    ((float4*)out)[i4] = v;
}

// ---------------- im2col (3x3 stride2 pad1), vectorized x4, bf16 hi/lo out ----------------
__global__ void im2col_hl(const float* __restrict__ x, bf16* __restrict__ oh, bf16* __restrict__ ol) {
    int idx = blockIdx.x*blockDim.x + threadIdx.x;
    const int total = NTOK*576;
    if (idx >= total) return;
    int c4 = idx % 576; int row = idx / 576;
    int b = row / NPOS; int p = row % NPOS;
    int i = p / WO, j = p % WO;
    int kk = c4 >> 6; int ic = (c4 & 63) * 4;
    int kh = kk / 3, kw = kk % 3;
    int hi = 2*i - 1 + kh, wi = 2*j - 1 + kw;
    float4 v = make_float4(0.f, 0.f, 0.f, 0.f);
    if (hi >= 0 && hi < HI && wi >= 0 && wi < WI)
        v = *(const float4*)(x + ((size_t)(b*(HI*WI) + hi*WI + wi))*DD + ic);
    __nv_bfloat162 h0, h1, l0, l1;
    split_hl(v.x, h0.x, l0.x); split_hl(v.y, h0.y, l0.y);
    split_hl(v.z, h1.x, l1.x); split_hl(v.w, h1.y, l1.y);
    size_t o = (size_t)row*2304 + kk*256 + ic;
    *(__nv_bfloat162*)(oh + o)     = h0;
    *(__nv_bfloat162*)(oh + o + 2) = h1;
    *(__nv_bfloat162*)(ol + o)     = l0;
    *(__nv_bfloat162*)(ol + o + 2) = l1;
}

__global__ void wseed_tr_hl(const float* __restrict__ w, bf16* __restrict__ oh, bf16* __restrict__ ol) {
    int idx = blockIdx.x*blockDim.x + threadIdx.x;
    if (idx >= DD*2304) return;
    int oc = idx / 2304; int c = idx % 2304;
    int kk = c >> 8; int ic = c & 255;
    float v = w[(size_t)oc*2304 + ic*9 + kk];
    split_hl(v, oh[idx], ol[idx]);
}

// ---------------- group NA (K=3): 4 groups merged, q read from split-K partials ----------------
__global__ void na3_attn4(const float* __restrict__ kg, const float* __restrict__ qsplit,
                          const float* __restrict__ rpb, const float* __restrict__ tau,
                          float* __restrict__ attn) {
    int blk = blockIdx.x;                 // b*784 + p
    int p = blk % NPOS, b = blk / NPOS;
    int i = p / WO, j = p % WO;
    int t = threadIdx.x; int w = t >> 5; int lane = t & 31;   // 9 warps
    __shared__ float kgs[4][256];
    __shared__ float logit[4][9];
    __shared__ float ev[4][9];
    if (t < 128) {
        int n = t >> 6, f = t & 63;
        ((float4*)kgs[n])[f]   = *(const float4*)(kg + ((size_t)(b*4+n)*NPOS + p)*DD + f*4);
        ((float4*)kgs[n+2])[f] = *(const float4*)(kg + ((size_t)(b*4+n+2)*NPOS + p)*DD + f*4);
    }
    int a = w / 3, c = w % 3;
    int si = min(max(i-1,0),25), sj = min(max(j-1,0),25);
    int np = (si+a)*WO + (sj+c);
    const float* q0 = qsplit + (size_t)(b*NPOS + np)*DD;
    const float* q1 = q0 + (size_t)NTOKP*DD;
    float qr[8];
    #pragma unroll
    for (int u=0;u<8;u++) qr[u] = q0[lane + 32*u] + q1[lane + 32*u];
    __syncthreads();
    #pragma unroll
    for (int n = 0; n < 4; n++) {
        float s = 0.f;
        #pragma unroll
        for (int u=0;u<8;u++) s = fmaf(qr[u], kgs[n][lane + 32*u], s);
        #pragma unroll
        for (int o=16;o;o>>=1) s += __shfl_xor_sync(0xffffffffu, s, o);
        if (lane==0) logit[n][w] = s + rpb[n*9 + w];
    }
    __syncthreads();
    if (t < 36) {
        int n = t/9, ac = t%9;
        float scale = expf(tau[0]);
        float m = -1e30f;
        #pragma unroll
        for (int u=0;u<9;u++) m = fmaxf(m, logit[n][u]*scale);
        ev[n][ac] = expf(logit[n][ac]*scale - m);
    }
    __syncthreads();
    if (t < 36) {
        int n = t/9, ac = t%9;
        float sum = 0.f;
        #pragma unroll
        for (int u=0;u<9;u++) sum += ev[n][u];
        attn[((size_t)(b*4+n)*NPOS + p)*9 + ac] = ev[n][ac]/sum + 1e-6f;
    }
}

// ---------------- deterministic column scatter-sum ----------------
__device__ __forceinline__ int inv_list(int s, int* lst) {
    if (s == 0)       { lst[0]=0;  lst[1]=1;  return 2; }
    else if (s == 25) { lst[0]=26; lst[1]=27; return 2; }
    else              { lst[0]=s+1;           return 1; }
}

__global__ void col_sum_k(const float* __restrict__ attn, float* __restrict__ col) {
    int idx = blockIdx.x*blockDim.x + threadIdx.x;
    if (idx >= BB*NPOS) return;
    int t = idx % NPOS, b = idx / NPOS;
    int ti = t / WO, tj = t % WO;
    float acc = 0.f;
    for (int a=0;a<3;a++) {
        int sr = ti - a; if (sr < 0 || sr > 25) continue;
        int il[2]; int ic = inv_list(sr, il);
        for (int c=0;c<3;c++) {
            int sc = tj - c; if (sc < 0 || sc > 25) continue;
            int jl[2]; int jc = inv_list(sc, jl);
            for (int ii=0; ii<ic; ii++)
                for (int jj=0; jj<jc; jj++) {
                    int pp = il[ii]*WO + jl[jj];
                    #pragma unroll
                    for (int n=0;n<4;n++)
                        acc += attn[((size_t)(b*4+n)*NPOS + pp)*9 + a*3 + c];
                }
        }
    }
    col[idx] = acc;
}

// ---------------- group NA AV + in-place residual + hi/lo out ----------------
__global__ void na3_av(const float* __restrict__ attn, const float* __restrict__ col,
                       const float* __restrict__ vg, float* __restrict__ xout,
                       bf16* __restrict__ oh, bf16* __restrict__ ol) {
    int blk = blockIdx.x;
    int p = blk % NPOS, b = blk / NPOS;
    int i = p / WO, j = p % WO;
    int t = threadIdx.x;
    __shared__ float wgt[4][9];
    __shared__ int npos[9];
    if (t < 9) {
        int a = t/3, c = t%3;
        int ni = min(max(i-1,0),25)+a, nj = min(max(j-1,0),25)+c;
        npos[t] = ni*WO + nj;
    }
    __syncthreads();
    if (t < 36) {
        int n = t/9, ac = t%9;
        float av = attn[((size_t)(b*4+n)*NPOS + p)*9 + ac];
        wgt[n][ac] = av / (col[b*NPOS + npos[ac]] + 1e-8f);
    }
    __syncthreads();
    float acc = xout[(size_t)blk*DD + t];
    #pragma unroll
    for (int n=0;n<4;n++) {
        const float* vb = vg + (size_t)(b*4+n)*NPOS*DD;
        #pragma unroll
        for (int ac=0;ac<9;ac++)
            acc = fmaf(wgt[n][ac], vb[(size_t)npos[ac]*DD + t], acc);
    }
    xout[(size_t)blk*DD + t] = acc;
    split_hl(acc, oh[(size_t)blk*DD + t], ol[(size_t)blk*DD + t]);
}

// ---------------- RoPE table ----------------
__global__ void rope_tab(float* __restrict__ cs, float* __restrict__ sn) {
    int idx = blockIdx.x*blockDim.x + threadIdx.x;
    if (idx >= NPOS*16) return;
    int pos = idx / 16, r = idx % 16;
    float f = expf(-((float)(2*r) / 32.f) * 9.210340371976184f);
    float ang = (float)pos * f;
    cs[idx] = cosf(ang);
    sn[idx] = sinf(ang);
}

// ---------------- block NA (K=7): row-blocked, smem-staged k/v window ----------------
#define NA7_SMEM ((2*6272 + 8*64) * 4)
__global__ void __launch_bounds__(256)
na7_row(const float* __restrict__ qkv, bf16* __restrict__ oh, bf16* __restrict__ ol) {
    extern __shared__ float sm7[];
    float* ks = sm7;
    float* vs = sm7 + 6272;
    float* wb = sm7 + 12544;
    int blk = blockIdx.x;
    int i = blk % 28; int bh = blk / 28; int h = bh & 7; int b = bh >> 3;
    int t = threadIdx.x, w = t >> 5, lane = t & 31;
    int si = min(max(i-3,0),21);
    for (int idx = t; idx < 1568; idx += 256) {
        int pos = idx >> 3, f = (idx & 7) * 4;
        int a = pos / 28, c = pos % 28;
        size_t g = ((size_t)(b*NPOS + (si+a)*WO + c))*768 + h*32 + f;
        *(float4*)(ks + pos*32 + f) = *(const float4*)(qkv + g + 256);
        *(float4*)(vs + pos*32 + f) = *(const float4*)(qkv + g + 512);
    }
    __syncthreads();
    for (int j = w; j < 28; j += 8) {
        int sj = min(max(j-3,0),21);
        int p = i*WO + j;
        float qd = qkv[((size_t)(b*NPOS + p))*768 + h*32 + lane];
        for (int nb = 0; nb < 49; nb++) {
            int a = nb / 7, c = nb % 7;
            float s = qd * ks[(a*28 + sj + c)*32 + lane];
            #pragma unroll
            for (int o=16;o;o>>=1) s += __shfl_xor_sync(0xffffffffu, s, o);
            if (lane == 0) wb[w*64 + nb] = s * 0.17677669529663687f;
        }
        __syncwarp();
        float m = -1e30f;
        for (int nb = lane; nb < 49; nb += 32) m = fmaxf(m, wb[w*64 + nb]);
        #pragma unroll
        for (int o=16;o;o>>=1) m = fmaxf(m, __shfl_xor_sync(0xffffffffu, m, o));
        float sum = 0.f;
        for (int nb = lane; nb < 49; nb += 32) {
            float e = expf(wb[w*64 + nb] - m);
            wb[w*64 + nb] = e;
            sum += e;
        }
        #pragma unroll
        for (int o=16;o;o>>=1) sum += __shfl_xor_sync(0xffffffffu, sum, o);
        __syncwarp();
        float inv = 1.f / sum;
        float acc = 0.f;
        for (int nb = 0; nb < 49; nb++) {
            int a = nb / 7, c = nb % 7;
            acc = fmaf(wb[w*64 + nb] * inv, vs[(a*28 + sj + c)*32 + lane], acc);
        }
        size_t o = ((size_t)(b*NPOS + p))*DD + h*32 + lane;
        split_hl(acc, oh[o], ol[o]);
        __syncwarp();
    }
}

// ---------------- host helpers ----------------
static inline void run_tc(const bf16* Ah, const bf16* Al, const bf16* Bh, const bf16* Bl,
                          const float* bias, float* C, bf16* Oh, bf16* Ol,
                          const float* cs, const float* sn,
                          int Mreal, int Mpad, int N, int K, int act, int remap, int ks) {
    dim3 grid(N/128, Mpad/128, ks);
    gemm_mma<<<grid, 256, GTC_SMEM>>>(Ah, Al, Bh, Bl, bias, C, Oh, Ol, cs, sn,
                                      Mreal, Mpad, N, K, act, remap, ks);
}

extern "C" void kernel_launch(void* const* d_in, const int* in_sizes, int n_in,
                              void* d_out, int out_size) {
    const float* x          = (const float*)d_in[0];
    const float* g_seed_w   = (const float*)d_in[1];
    const float* g_q_w      = (const float*)d_in[2];
    const float* g_k_w      = (const float*)d_in[3];
    const float* g_v_w      = (const float*)d_in[4];
    const float* g_mlp_w1   = (const float*)d_in[5];
    const float* g_mlp_b1   = (const float*)d_in[6];
    const float* g_mlp_w2   = (const float*)d_in[7];
    const float* g_mlp_b2   = (const float*)d_in[8];
    const float* g_ln_in_g  = (const float*)d_in[9];
    const float* g_ln_in_b  = (const float*)d_in[10];
    const float* g_ln_out_g = (const float*)d_in[11];
    const float* g_ln_out_b = (const float*)d_in[12];
    const float* g_tau      = (const float*)d_in[13];
    const float* g_rpb      = (const float*)d_in[14];
    const float* blk_ln1_g  = (const float*)d_in[15];
    const float* blk_ln1_b  = (const float*)d_in[16];
    const float* blk_qkv_w  = (const float*)d_in[17];
    const float* blk_proj_w = (const float*)d_in[18];
    const float* blk_proj_b = (const float*)d_in[19];
    const float* blk_ln2_g  = (const float*)d_in[20];
    const float* blk_ln2_b  = (const float*)d_in[21];
    const float* blk_mlp_w1 = (const float*)d_in[22];
    const float* blk_mlp_b1 = (const float*)d_in[23];
    const float* blk_mlp_w2 = (const float*)d_in[24];
    const float* blk_mlp_b2 = (const float*)d_in[25];
    float* out = (float*)d_out;

    cudaFuncSetAttribute(gemm_mma, cudaFuncAttributeMaxDynamicSharedMemorySize, GTC_SMEM);
    cudaFuncSetAttribute(na7_row, cudaFuncAttributeMaxDynamicSharedMemorySize, NA7_SMEM);

#define SYM(v, s) cudaGetSymbolAddress((void**)&v, s)
    float *xout, *buf2, *kg, *vg, *split, *attn, *colsum, *csb, *snb;
    SYM(xout,g_xout); SYM(buf2,g_buf2);
    SYM(kg,g_kg); SYM(vg,g_vg); SYM(split,g_split); SYM(attn,g_attn);
    SYM(colsum,g_colsum); SYM(csb,g_cos); SYM(snb,g_sin);
    bf16 *xh,*xl,*lnxh,*lnxl,*colh,*coll,*a1h,*a1l,*a2h,*a2l;
    SYM(xh,g_xh); SYM(xl,g_xl); SYM(lnxh,g_lnxh); SYM(lnxl,g_lnxl);
    SYM(colh,g_colh); SYM(coll,g_coll); SYM(a1h,g_a1h); SYM(a1l,g_a1l);
    SYM(a2h,g_a2h); SYM(a2l,g_a2l);
    bf16 *wsh,*wsl,*wqh,*wql,*wkh,*wkl,*wvh,*wvl,*m1h,*m1l,*m2h,*m2l;
    SYM(wsh,g_wsh); SYM(wsl,g_wsl); SYM(wqh,g_wqh); SYM(wql,g_wql);
    SYM(wkh,g_wkh); SYM(wkl,g_wkl); SYM(wvh,g_wvh); SYM(wvl,g_wvl);
    SYM(m1h,g_m1h); SYM(m1l,g_m1l); SYM(m2h,g_m2h); SYM(m2l,g_m2l);
    bf16 *qkvh,*qkvl,*pjh,*pjl,*bm1h,*bm1l,*bm2h,*bm2l;
    SYM(qkvh,g_qkvh); SYM(qkvl,g_qkvl); SYM(pjh,g_pjh); SYM(pjl,g_pjl);
    SYM(bm1h,g_bm1h); SYM(bm1l,g_bm1l); SYM(bm2h,g_bm2h); SYM(bm2l,g_bm2l);
#undef SYM

    // ---- weight conversions: seed transpose + single merged cvt ----
    wseed_tr_hl<<<(DD*2304 + 255)/256, 256>>>(g_seed_w, wsh, wsl);
    {
        CvtSegs cs;
        cs.src[0]=g_q_w;      cs.hi[0]=wqh;  cs.lo[0]=wql;
        cs.src[1]=g_k_w;      cs.hi[1]=wkh;  cs.lo[1]=wkl;
        cs.src[2]=g_v_w;      cs.hi[2]=wvh;  cs.lo[2]=wvl;
        cs.src[3]=g_mlp_w1;   cs.hi[3]=m1h;  cs.lo[3]=m1l;
        cs.src[4]=g_mlp_w2;   cs.hi[4]=m2h;  cs.lo[4]=m2l;
        cs.src[5]=blk_qkv_w;  cs.hi[5]=qkvh; cs.lo[5]=qkvl;
        cs.src[6]=blk_proj_w; cs.hi[6]=pjh;  cs.lo[6]=pjl;
        cs.src[7]=blk_mlp_w1; cs.hi[7]=bm1h; cs.lo[7]=bm1l;
        cs.src[8]=blk_mlp_w2; cs.hi[8]=bm2h; cs.lo[8]=bm2l;
        cvt_all<<<(CVT_TOT + 255)/256, 256>>>(cs);
    }

    // ---- LN_in(x) + raw x hi/lo in one pass ----
    ln_warp<<<(NTOKIN + 7)/8, 256>>>(x, g_ln_in_g, g_ln_in_b, lnxh, lnxl, xh, xl, NTOKIN);
    run_tc(lnxh, lnxl, wkh, wkl, nullptr, kg, nullptr, nullptr, nullptr, nullptr,
           NTOKIN, NTOKIN, DD, DD, 0, 1, 1);
    run_tc(xh,   xl,   wvh, wvl, nullptr, vg, nullptr, nullptr, nullptr, nullptr,
           NTOKIN, NTOKIN, DD, DD, 0, 1, 1);

    // ---- seed conv: im2col + split-K GEMM + fused combine/LN(out)/LN(out)->a2 ----
    im2col_hl<<<(NTOK*576 + 255)/256, 256>>>(x, colh, coll);
    run_tc(colh, coll, wsh, wsl, nullptr, split, nullptr, nullptr, nullptr, nullptr,
           NTOK, NTOKP, DD, 2304, 0, 0, 3);
    combine_ln2<<<(NTOK + 7)/8, 256>>>(split, 3, nullptr, g_ln_out_g, g_ln_out_b,
                                       nullptr, xout, g_ln_out_g, g_ln_out_b,
                                       a2h, a2l, NTOKP, NTOK);

    rope_tab<<<(NPOS*16 + 255)/256, 256>>>(csb, snb);

    // ---- 3 grouped-NA seeding iterations ----
    for (int it = 0; it < 3; it++) {
        // a2h/a2l already holds LN_out(xout)
        run_tc(a2h, a2l, wqh, wql, nullptr, split, nullptr, nullptr, nullptr, nullptr,
               NTOK, NTOKP, DD, DD, 0, 0, 2);
        na3_attn4<<<NTOK, 288>>>(kg, split, g_rpb, g_tau, attn);
        col_sum_k<<<(BB*NPOS + 255)/256, 256>>>(attn, colsum);
        na3_av<<<NTOK, 256>>>(attn, colsum, vg, xout, a2h, a2l);
        run_tc(a2h, a2l, m1h, m1l, g_mlp_b1, nullptr, a1h, a1l, nullptr, nullptr,
               NTOK, NTOKP, 512, DD, 1, 0, 1);
        run_tc(a1h, a1l, m2h, m2l, nullptr, split, nullptr, nullptr, nullptr, nullptr,
               NTOK, NTOKP, DD, 512, 0, 0, 2);
        // combine + LN_out(h) + res -> xout; second LN -> a2 for next consumer
        const float* g2 = (it < 2) ? g_ln_out_g : blk_ln1_g;
        const float* b2 = (it < 2) ? g_ln_out_b : blk_ln1_b;
        combine_ln2<<<(NTOK + 7)/8, 256>>>(split, 2, g_mlp_b2, g_ln_out_g, g_ln_out_b,
                                           xout, xout, g2, b2, a2h, a2l, NTOKP, NTOK);
    }

    // ---- 2 transformer blocks with 7x7 NA ----
    for (int l = 0; l < 2; l++) {
        // a2h/a2l holds LN1_l(xout)
        run_tc(a2h, a2l, qkvh + (size_t)l*768*DD, qkvl + (size_t)l*768*DD,
               nullptr, buf2, nullptr, nullptr, csb, snb,
               NTOK, NTOKP, 768, DD, 0, 0, 1);
        na7_row<<<BB*HEADS*28, 256, NA7_SMEM>>>(buf2, a2h, a2l);
        run_tc(a2h, a2l, pjh + (size_t)l*DD*DD, pjl + (size_t)l*DD*DD,
               nullptr, split, nullptr, nullptr, nullptr, nullptr,
               NTOK, NTOKP, DD, DD, 0, 0, 2);
        // combine + bias + res -> xout; LN2 -> a2 for mlp1
        combine_res_ln<<<(NTOK + 7)/8, 256>>>(split, 2, blk_proj_b + l*DD, xout, xout,
                                              blk_ln2_g + l*DD, blk_ln2_b + l*DD,
                                              a2h, a2l, NTOKP, NTOK);
        run_tc(a2h, a2l, bm1h + (size_t)l*768*DD, bm1l + (size_t)l*768*DD,
               blk_mlp_b1 + l*768, nullptr, a1h, a1l, nullptr, nullptr,
               NTOK, NTOKP, 768, DD, 1, 0, 1);
        run_tc(a1h, a1l, bm2h + (size_t)l*DD*768, bm2l + (size_t)l*DD*768,
               nullptr, split, nullptr, nullptr, nullptr, nullptr,
               NTOK, NTOKP, DD, 768, 0, 0, 2);
        if (l == 0) {
            // combine + bias + res -> xout; LN1 of layer 1 -> a2 for next qkv
            combine_res_ln<<<(NTOK + 7)/8, 256>>>(split, 2, blk_mlp_b2, xout, xout,
                                                  blk_ln1_g + DD, blk_ln1_b + DD,
                                                  a2h, a2l, NTOKP, NTOK);
        } else {
            int tot4 = (NTOK*DD) >> 2;
            combine_k<<<(tot4 + 255)/256, 256>>>(split, 2, blk_mlp_b2 + DD, xout, out,
                                                 NTOK, NTOKP, DD, 0);
        }
    }
}